// round 5
// baseline (speedup 1.0000x reference)
#include <cuda_runtime.h>
#include <cuda_bf16.h>
#include <math.h>

#define VOCAB 32000
#define HDIM  512
#define BATCH 128
#define ENCL  64
#define NSTEP 31
#define MROWS (BATCH * ENCL)   // 8192

// ---------------- scratch (static device globals; no allocation) ----------------
__device__ float g_P[MROWS * HDIM];        // enc @ W1a^T  (time-invariant)
__device__ float g_a2[MROWS * HDIM];
__device__ float g_epart[8 * MROWS];       // per-slice partial dots (a3 . v)
__device__ float g_hid[2][BATCH * HDIM];   // ping-pong hidden state
__device__ float g_qgh[BATCH * 2048];      // [q(512) | gh(1536)] per batch row
__device__ float g_ctx[BATCH * HDIM];
__device__ float g_gi[BATCH * 3 * HDIM];
__device__ float g_bqh[2048];              // [b1 | bhh]

// bf16 weight copies (converted once per replay)
__device__ __nv_bfloat16 g_Wp  [HDIM * HDIM];          // W1[:, :H]
__device__ __nv_bfloat16 g_Wqh [2048 * HDIM];          // [W1[:, H:] ; Whh]
__device__ __nv_bfloat16 g_W2  [HDIM * HDIM];
__device__ __nv_bfloat16 g_W3  [HDIM * HDIM];
__device__ __nv_bfloat16 g_Wih [3 * HDIM * 2 * HDIM];
__device__ __nv_bfloat16 g_Wo  [VOCAB * HDIM];

// ---------------- helpers ----------------
__device__ __forceinline__ unsigned bf2(float lo, float hi) {
    unsigned u;
    asm("cvt.rn.bf16x2.f32 %0, %1, %2;" : "=r"(u) : "f"(hi), "f"(lo));
    return u;
}
__device__ __forceinline__ float tanh_fast(float x) {
    float y;
    asm("tanh.approx.f32 %0, %1;" : "=f"(y) : "f"(x));
    return y;
}
__device__ __forceinline__ void mma_bf16(float c[4], const unsigned a[4], const unsigned b[2]) {
    asm volatile(
        "mma.sync.aligned.m16n8k16.row.col.f32.bf16.bf16.f32 "
        "{%0,%1,%2,%3}, {%4,%5,%6,%7}, {%8,%9}, {%0,%1,%2,%3};\n"
        : "+f"(c[0]), "+f"(c[1]), "+f"(c[2]), "+f"(c[3])
        : "r"(a[0]), "r"(a[1]), "r"(a[2]), "r"(a[3]), "r"(b[0]), "r"(b[1]));
}
__device__ __forceinline__ void ldsm4(unsigned& r0, unsigned& r1, unsigned& r2, unsigned& r3,
                                      unsigned addr) {
    asm volatile("ldmatrix.sync.aligned.m8n8.x4.shared.b16 {%0,%1,%2,%3}, [%4];"
                 : "=r"(r0), "=r"(r1), "=r"(r2), "=r"(r3) : "r"(addr));
}

// ---------------- weight conversion (fp32 -> bf16, strided source, float4) ----------------
__global__ void conv_kernel(__nv_bfloat16* __restrict__ dst, const float* __restrict__ src,
                            int rows, int cols, int sld, int soff) {
    const int i4 = (blockIdx.x * blockDim.x + threadIdx.x) * 4;
    if (i4 >= rows * cols) return;
    const int r = i4 / cols, c = i4 - r * cols;   // cols % 4 == 0 everywhere
    float4 v = *(const float4*)(src + (size_t)r * sld + soff + c);
    uint2 o;
    o.x = bf2(v.x, v.y);
    o.y = bf2(v.z, v.w);
    *(uint2*)(dst + i4) = o;
}

__global__ void init_misc_kernel(const float* __restrict__ ench,
                                 const float* __restrict__ b1,
                                 const float* __restrict__ bhh) {
    const int i = blockIdx.x * blockDim.x + threadIdx.x;
    if (i < BATCH * HDIM) g_hid[0][i] = ench[i];
    if (i < 2048) g_bqh[i] = (i < HDIM) ? b1[i] : bhh[i - HDIM];
}

// ---------------- GEMM:  act(A[M,K] * W[N,K]^T + bias),  W bf16, ldmatrix mainloop ----------
// CTA 128x128, warp 32x64 (4x2), K-tile 16. smem tiles row-major, 48B row stride
// (r*48 mod 128 covers all 16B slots -> LDSM conflict-free).
// AMODE 0: A fp32 direct      AMODE 1: tanh(P + Q[row>>6])      AMODE 2: [EMB[TGT] | Q] concat
// ACT 0: bias  ACT 1: bias+tanh  ACT 2: e-dot epilogue: C = e_part[8][M] slices, Q holds v.
// All launches: M,N multiples of tile -> no bounds checks.
template <int AMODE, int ACT>
__global__ __launch_bounds__(256) void gemm_kernel(
    const float* __restrict__ A, int lda,
    const __nv_bfloat16* __restrict__ W, int ldw,
    const float* __restrict__ bias,
    float* __restrict__ C, size_t ldc,
    int M, int N, int K,
    const float* __restrict__ Q, int qld,
    const float* __restrict__ EMB,
    const int* __restrict__ TGT)
{
    __shared__ __align__(16) unsigned char sm[2][2][128 * 48];  // [buf][A/W][row*48+chunk*16]

    const int tid    = threadIdx.x;
    const int warpid = tid >> 5, lane = tid & 31;
    const int wm = warpid >> 1, wn = warpid & 1;
    const int gid = lane >> 2, tidg = lane & 3;
    const int bm0 = blockIdx.y * 128, bn0 = blockIdx.x * 128;
    const int frow = tid >> 1;        // fetch row 0..127
    const int half = tid & 1;         // 16B chunk within k-tile

    const unsigned sbase = (unsigned)__cvta_generic_to_shared(&sm[0][0][0]);
    // per-lane ldmatrix offsets
    unsigned aoff[2], boff[4];
    #pragma unroll
    for (int mi = 0; mi < 2; mi++)
        aoff[mi] = (unsigned)((wm * 32 + mi * 16 + (lane & 15)) * 48 + (lane >> 4) * 16);
    #pragma unroll
    for (int p = 0; p < 4; p++)
        boff[p] = (unsigned)(6144 +
            (wn * 64 + p * 16 + ((lane >> 4) << 3) + (lane & 7)) * 48 + ((lane >> 3) & 1) * 16);

    float acc[2][8][4];
    #pragma unroll
    for (int mi = 0; mi < 2; mi++)
        #pragma unroll
        for (int ni = 0; ni < 8; ni++)
            #pragma unroll
            for (int qq = 0; qq < 4; qq++) acc[mi][ni][qq] = 0.f;

    const int nk = K >> 4;
    float4 pa0, pa1;
    uint4  pw;

    auto fetch = [&](int kt) {
        const int k0 = (kt << 4) + half * 8;
        const int arow = bm0 + frow;
        if (AMODE == 0) {
            pa0 = *(const float4*)(A + (size_t)arow * lda + k0);
            pa1 = *(const float4*)(A + (size_t)arow * lda + k0 + 4);
        } else if (AMODE == 1) {
            float4 p0 = *(const float4*)(A + (size_t)arow * lda + k0);
            float4 p1 = *(const float4*)(A + (size_t)arow * lda + k0 + 4);
            const float* qr = Q + (size_t)(arow >> 6) * qld + k0;
            pa0.x = tanh_fast(p0.x + qr[0]); pa0.y = tanh_fast(p0.y + qr[1]);
            pa0.z = tanh_fast(p0.z + qr[2]); pa0.w = tanh_fast(p0.w + qr[3]);
            pa1.x = tanh_fast(p1.x + qr[4]); pa1.y = tanh_fast(p1.y + qr[5]);
            pa1.z = tanh_fast(p1.z + qr[6]); pa1.w = tanh_fast(p1.w + qr[7]);
        } else {
            if (k0 < HDIM) {
                int tg = TGT[arow * 32];
                tg = max(0, min(tg, VOCAB - 1));
                pa0 = *(const float4*)(EMB + (size_t)tg * HDIM + k0);
                pa1 = *(const float4*)(EMB + (size_t)tg * HDIM + k0 + 4);
            } else {
                pa0 = *(const float4*)(Q + (size_t)arow * qld + (k0 - HDIM));
                pa1 = *(const float4*)(Q + (size_t)arow * qld + (k0 - HDIM) + 4);
            }
        }
        pw = *(const uint4*)(W + (size_t)(bn0 + frow) * ldw + (kt << 4) + half * 8);
    };
    auto store_smem = [&](int buf) {
        uint4 av;
        av.x = bf2(pa0.x, pa0.y); av.y = bf2(pa0.z, pa0.w);
        av.z = bf2(pa1.x, pa1.y); av.w = bf2(pa1.z, pa1.w);
        *(uint4*)&sm[buf][0][frow * 48 + half * 16] = av;
        *(uint4*)&sm[buf][1][frow * 48 + half * 16] = pw;
    };

    fetch(0);
    store_smem(0);
    __syncthreads();

    for (int kt = 0; kt < nk; kt++) {
        const int buf = kt & 1;
        const unsigned sb = sbase + buf * 12288;
        if (kt + 1 < nk) fetch(kt + 1);

        unsigned af[2][4], bfr[8][2];
        #pragma unroll
        for (int mi = 0; mi < 2; mi++)
            ldsm4(af[mi][0], af[mi][1], af[mi][2], af[mi][3], sb + aoff[mi]);
        #pragma unroll
        for (int p = 0; p < 4; p++) {
            unsigned r0, r1, r2, r3;
            ldsm4(r0, r1, r2, r3, sb + boff[p]);
            bfr[2 * p][0] = r0; bfr[2 * p][1] = r1;
            bfr[2 * p + 1][0] = r2; bfr[2 * p + 1][1] = r3;
        }
        #pragma unroll
        for (int mi = 0; mi < 2; mi++)
            #pragma unroll
            for (int ni = 0; ni < 8; ni++)
                mma_bf16(acc[mi][ni], af[mi], bfr[ni]);

        if (kt + 1 < nk) store_smem(buf ^ 1);
        __syncthreads();
    }

    if (ACT == 2) {
        // e-dot epilogue: per-row sum of tanh(acc + b3[col]) * v[col]; Q = v, C = e_part
        const float* v = Q;
        float es[2][2] = {{0.f, 0.f}, {0.f, 0.f}};
        #pragma unroll
        for (int mi = 0; mi < 2; mi++) {
            #pragma unroll
            for (int ni = 0; ni < 8; ni++) {
                const int col = bn0 + wn * 64 + ni * 8 + tidg * 2;
                const float v0 = v[col], v1 = v[col + 1];
                const float b0 = bias[col], b1 = bias[col + 1];
                es[mi][0] += tanh_fast(acc[mi][ni][0] + b0) * v0
                           + tanh_fast(acc[mi][ni][1] + b1) * v1;
                es[mi][1] += tanh_fast(acc[mi][ni][2] + b0) * v0
                           + tanh_fast(acc[mi][ni][3] + b1) * v1;
            }
        }
        const int slice = blockIdx.x * 2 + wn;   // 0..7
        #pragma unroll
        for (int mi = 0; mi < 2; mi++) {
            #pragma unroll
            for (int hh = 0; hh < 2; hh++) {
                float s = es[mi][hh];
                s += __shfl_xor_sync(0xffffffffu, s, 1);
                s += __shfl_xor_sync(0xffffffffu, s, 2);
                if (tidg == 0) {
                    const int row = bm0 + wm * 32 + mi * 16 + gid + hh * 8;
                    C[(size_t)slice * M + row] = s;
                }
            }
        }
        return;
    }

    // standard epilogue: bias (+ optional tanh)
    #pragma unroll
    for (int mi = 0; mi < 2; mi++) {
        #pragma unroll
        for (int ni = 0; ni < 8; ni++) {
            const int col = bn0 + wn * 64 + ni * 8 + tidg * 2;
            const float b0v = bias ? bias[col] : 0.f;
            const float b1v = bias ? bias[col + 1] : 0.f;
            const int row0 = bm0 + wm * 32 + mi * 16 + gid;
            float v0 = acc[mi][ni][0] + b0v, v1 = acc[mi][ni][1] + b1v;
            float v2 = acc[mi][ni][2] + b0v, v3 = acc[mi][ni][3] + b1v;
            if (ACT == 1) {
                v0 = tanh_fast(v0); v1 = tanh_fast(v1);
                v2 = tanh_fast(v2); v3 = tanh_fast(v3);
            }
            C[(size_t)row0 * ldc + col]           = v0;
            C[(size_t)row0 * ldc + col + 1]       = v1;
            C[(size_t)(row0 + 8) * ldc + col]     = v2;
            C[(size_t)(row0 + 8) * ldc + col + 1] = v3;
        }
    }
}

// ---------------- e from partials ; softmax over L ; ctx = alpha^T enc ----------------
__global__ __launch_bounds__(256) void softmax_ctx_kernel(
    const float* __restrict__ epart,
    const float* __restrict__ enc, float* __restrict__ ctx)
{
    __shared__ float e[ENCL];
    __shared__ float alpha[ENCL];
    const int b = blockIdx.x;
    const int tid = threadIdx.x;
    const int warp = tid >> 5, lane = tid & 31;

    if (tid < ENCL) {
        float s = 0.f;
        #pragma unroll
        for (int sl = 0; sl < 8; sl++) s += epart[sl * MROWS + b * ENCL + tid];
        e[tid] = s;
    }
    __syncthreads();
    if (warp == 0) {
        const float e0 = e[lane], e1 = e[lane + 32];
        float m = fmaxf(e0, e1);
        #pragma unroll
        for (int o = 16; o; o >>= 1) m = fmaxf(m, __shfl_xor_sync(0xffffffffu, m, o));
        const float x0 = expf(e0 - m), x1 = expf(e1 - m);
        float s = x0 + x1;
        #pragma unroll
        for (int o = 16; o; o >>= 1) s += __shfl_xor_sync(0xffffffffu, s, o);
        const float inv = 1.f / s;
        alpha[lane]      = x0 * inv;
        alpha[lane + 32] = x1 * inv;
    }
    __syncthreads();
    for (int j = tid; j < HDIM; j += 256) {
        float s = 0.f;
        #pragma unroll
        for (int l = 0; l < ENCL; l++)
            s += alpha[l] * enc[((size_t)b * ENCL + l) * HDIM + j];
        ctx[b * HDIM + j] = s;
    }
}

// ---------------- GRU gate combine (gh lives in qgh[:, 512:]) ----------------
__global__ void gru_kernel(const float* __restrict__ gi, const float* __restrict__ qgh,
                           const float* __restrict__ h, float* __restrict__ hn)
{
    const int b = blockIdx.x, j = threadIdx.x;
    const int o  = b * 3 * HDIM;
    const int og = b * 2048 + HDIM;
    const float r = 1.f / (1.f + expf(-(gi[o + j] + qgh[og + j])));
    const float z = 1.f / (1.f + expf(-(gi[o + HDIM + j] + qgh[og + HDIM + j])));
    const float n = tanhf(gi[o + 2 * HDIM + j] + r * qgh[og + 2 * HDIM + j]);
    const float hv = h[b * HDIM + j];
    hn[b * HDIM + j] = (1.f - z) * n + z * hv;
}

// ---------------- in-place log-softmax over one row of 32000 (single pass, regs) ----------------
__global__ __launch_bounds__(1024) void logsoftmax_kernel(float* __restrict__ out, int t) {
    const int b = blockIdx.x;
    float* row = out + ((size_t)b * NSTEP + t) * VOCAB;
    const int tid = threadIdx.x;
    __shared__ float sm[32];

    float r[32];
    float m = -1e30f;
    #pragma unroll
    for (int i = 0; i < 32; i++) {
        const int idx = tid + (i << 10);
        r[i] = (idx < VOCAB) ? row[idx] : -1e30f;
        m = fmaxf(m, r[i]);
    }
    #pragma unroll
    for (int o = 16; o; o >>= 1) m = fmaxf(m, __shfl_xor_sync(0xffffffffu, m, o));
    if ((tid & 31) == 0) sm[tid >> 5] = m;
    __syncthreads();
    if (tid == 0) {
        float v = sm[0];
        for (int i = 1; i < 32; i++) v = fmaxf(v, sm[i]);
        sm[0] = v;
    }
    __syncthreads();
    m = sm[0];

    float s = 0.f;
    #pragma unroll
    for (int i = 0; i < 32; i++) {
        const int idx = tid + (i << 10);
        if (idx < VOCAB) s += expf(r[i] - m);
    }
    #pragma unroll
    for (int o = 16; o; o >>= 1) s += __shfl_xor_sync(0xffffffffu, s, o);
    __syncthreads();
    if ((tid & 31) == 0) sm[tid >> 5] = s;
    __syncthreads();
    if (tid == 0) {
        float v = 0.f;
        for (int i = 0; i < 32; i++) v += sm[i];
        sm[0] = v;
    }
    __syncthreads();
    const float lse = m + logf(sm[0]);

    #pragma unroll
    for (int i = 0; i < 32; i++) {
        const int idx = tid + (i << 10);
        if (idx < VOCAB) row[idx] = r[i] - lse;
    }
}

// ---------------- launch ----------------
extern "C" void kernel_launch(void* const* d_in, const int* in_sizes, int n_in,
                              void* d_out, int out_size)
{
    const float* enc       = (const float*)d_in[0];
    const float* ench      = (const float*)d_in[1];
    const int* tgt         = (const int*)d_in[2];    // int32 (JAX x64 disabled)
    const float* emb       = (const float*)d_in[3];
    const float* W1        = (const float*)d_in[4];
    const float* b1        = (const float*)d_in[5];
    const float* W2        = (const float*)d_in[6];
    const float* b2        = (const float*)d_in[7];
    const float* W3        = (const float*)d_in[8];
    const float* b3        = (const float*)d_in[9];
    const float* av        = (const float*)d_in[10];
    const float* Wih       = (const float*)d_in[11];
    const float* Whh       = (const float*)d_in[12];
    const float* bih       = (const float*)d_in[13];
    const float* bhh       = (const float*)d_in[14];
    const float* oW        = (const float*)d_in[15];
    const float* ob        = (const float*)d_in[16];
    float* out = (float*)d_out;

    float *P, *a2, *epart, *hidb, *qgh, *ctx, *gi, *bqh;
    __nv_bfloat16 *Wp, *Wqh, *W2b, *W3b, *Wihb, *Wob;
    cudaGetSymbolAddress((void**)&P,     g_P);
    cudaGetSymbolAddress((void**)&a2,    g_a2);
    cudaGetSymbolAddress((void**)&epart, g_epart);
    cudaGetSymbolAddress((void**)&hidb,  g_hid);
    cudaGetSymbolAddress((void**)&qgh,   g_qgh);
    cudaGetSymbolAddress((void**)&ctx,   g_ctx);
    cudaGetSymbolAddress((void**)&gi,    g_gi);
    cudaGetSymbolAddress((void**)&bqh,   g_bqh);
    cudaGetSymbolAddress((void**)&Wp,    g_Wp);
    cudaGetSymbolAddress((void**)&Wqh,   g_Wqh);
    cudaGetSymbolAddress((void**)&W2b,   g_W2);
    cudaGetSymbolAddress((void**)&W3b,   g_W3);
    cudaGetSymbolAddress((void**)&Wihb,  g_Wih);
    cudaGetSymbolAddress((void**)&Wob,   g_Wo);

    init_misc_kernel<<<(BATCH * HDIM + 255) / 256, 256>>>(ench, b1, bhh);

    // weight conversions (fp32 -> bf16, 4 elems/thread)
    conv_kernel<<<(HDIM * HDIM / 4 + 255) / 256, 256>>>(Wp,  W1, HDIM, HDIM, 2 * HDIM, 0);
    conv_kernel<<<(HDIM * HDIM / 4 + 255) / 256, 256>>>(Wqh, W1, HDIM, HDIM, 2 * HDIM, HDIM);
    conv_kernel<<<(3 * HDIM * HDIM / 4 + 255) / 256, 256>>>(Wqh + HDIM * HDIM, Whh, 3 * HDIM, HDIM, HDIM, 0);
    conv_kernel<<<(HDIM * HDIM / 4 + 255) / 256, 256>>>(W2b, W2, HDIM, HDIM, HDIM, 0);
    conv_kernel<<<(HDIM * HDIM / 4 + 255) / 256, 256>>>(W3b, W3, HDIM, HDIM, HDIM, 0);
    conv_kernel<<<(3 * HDIM * 2 * HDIM / 4 + 255) / 256, 256>>>(Wihb, Wih, 3 * HDIM, 2 * HDIM, 2 * HDIM, 0);
    conv_kernel<<<(VOCAB * HDIM / 4 + 255) / 256, 256>>>(Wob, oW, VOCAB, HDIM, HDIM, 0);

    // P = enc @ W1[:, :H]^T   (time-invariant; no bias)
    gemm_kernel<0, 0><<<dim3(HDIM / 128, MROWS / 128), 256>>>(
        enc, HDIM, Wp, HDIM, nullptr, P, HDIM, MROWS, HDIM, HDIM,
        nullptr, 0, nullptr, nullptr);

    for (int t = 0; t < NSTEP; t++) {
        float* hi = hidb + (t & 1) * (BATCH * HDIM);
        float* ho = hidb + ((t + 1) & 1) * (BATCH * HDIM);

        // [q | gh] = hid @ [W1b ; Whh]^T + [b1 | bhh]
        gemm_kernel<0, 0><<<dim3(2048 / 128, 1), 256>>>(
            hi, HDIM, Wqh, HDIM, bqh, qgh, 2048, BATCH, 2048, HDIM,
            nullptr, 0, nullptr, nullptr);

        // a2 = tanh( tanh(P+q) @ W2^T + b2 )
        gemm_kernel<1, 1><<<dim3(HDIM / 128, MROWS / 128), 256>>>(
            P, HDIM, W2b, HDIM, b2, a2, HDIM, MROWS, HDIM, HDIM,
            qgh, 2048, nullptr, nullptr);

        // e_part = slicewise [ tanh(a2 @ W3^T + b3) . v ]    (a3 never materialized)
        gemm_kernel<0, 2><<<dim3(HDIM / 128, MROWS / 128), 256>>>(
            a2, HDIM, W3b, HDIM, b3, epart, 0, MROWS, HDIM, HDIM,
            av, 0, nullptr, nullptr);

        softmax_ctx_kernel<<<BATCH, 256>>>(epart, enc, ctx);

        // gi = [embed[tgt_t], ctx] @ Wih^T + bih
        gemm_kernel<2, 0><<<dim3(3 * HDIM / 128, 1), 256>>>(
            nullptr, 0, Wihb, 2 * HDIM, bih, gi, 3 * HDIM, BATCH, 3 * HDIM, 2 * HDIM,
            ctx, HDIM, emb, tgt + t);

        gru_kernel<<<BATCH, HDIM>>>(gi, qgh, hi, ho);

        // logits -> d_out (strided rows), then in-place log-softmax
        gemm_kernel<0, 0><<<dim3(VOCAB / 128, 1), 256>>>(
            ho, HDIM, Wob, HDIM, ob, out + (size_t)t * VOCAB, (size_t)NSTEP * VOCAB,
            BATCH, VOCAB, HDIM, nullptr, 0, nullptr, nullptr);

        logsoftmax_kernel<<<BATCH, 1024>>>(out, t);
    }
}

// round 6
// speedup vs baseline: 1.2973x; 1.2973x over previous
#include <cuda_runtime.h>
#include <cuda_bf16.h>
#include <math.h>

#define VOCAB 32000
#define HDIM  512
#define BATCH 128
#define ENCL  64
#define NSTEP 31
#define MROWS (BATCH * ENCL)   // 8192
#define STAGES 4

// ---------------- scratch (static device globals; no allocation) ----------------
__device__ float          g_P[MROWS * HDIM];        // enc @ W1a^T (fp32, time-invariant)
__device__ __nv_bfloat16  g_A1[MROWS * HDIM];       // tanh(P + q)  (per step)
__device__ __nv_bfloat16  g_a2[MROWS * HDIM];
__device__ float          g_epart[8 * MROWS];       // per-slice partial dots (a3 . v)
__device__ float          g_hid[2][BATCH * HDIM];   // fp32 recurrence (ping-pong)
__device__ __nv_bfloat16  g_hbf[BATCH * HDIM];      // bf16 mirror of current hidden
__device__ float          g_qgh[BATCH * 2048];      // [q(512) | gh(1536)]
__device__ __nv_bfloat16  g_xt[BATCH * 1024];       // [emb[tgt] | ctx]  bf16
__device__ float          g_gi[BATCH * 3 * HDIM];
__device__ float          g_bqh[2048];              // [b1 | bhh]

// bf16 operand copies (converted once per replay)
__device__ __nv_bfloat16 g_encb[MROWS * HDIM];
__device__ __nv_bfloat16 g_Wp  [HDIM * HDIM];
__device__ __nv_bfloat16 g_Wqh [2048 * HDIM];
__device__ __nv_bfloat16 g_W2  [HDIM * HDIM];
__device__ __nv_bfloat16 g_W3  [HDIM * HDIM];
__device__ __nv_bfloat16 g_Wih [1536 * 1024];
__device__ __nv_bfloat16 g_Wo  [VOCAB * HDIM];

// ---------------- helpers ----------------
__device__ __forceinline__ unsigned bf2(float lo, float hi) {
    unsigned u;
    asm("cvt.rn.bf16x2.f32 %0, %1, %2;" : "=r"(u) : "f"(hi), "f"(lo));
    return u;
}
__device__ __forceinline__ float tanh_fast(float x) {
    float y;
    asm("tanh.approx.f32 %0, %1;" : "=f"(y) : "f"(x));
    return y;
}
__device__ __forceinline__ void mma_bf16(float c[4], const unsigned a[4], const unsigned b[2]) {
    asm volatile(
        "mma.sync.aligned.m16n8k16.row.col.f32.bf16.bf16.f32 "
        "{%0,%1,%2,%3}, {%4,%5,%6,%7}, {%8,%9}, {%0,%1,%2,%3};\n"
        : "+f"(c[0]), "+f"(c[1]), "+f"(c[2]), "+f"(c[3])
        : "r"(a[0]), "r"(a[1]), "r"(a[2]), "r"(a[3]), "r"(b[0]), "r"(b[1]));
}
__device__ __forceinline__ void ldsm4(unsigned& r0, unsigned& r1, unsigned& r2, unsigned& r3,
                                      unsigned addr) {
    asm volatile("ldmatrix.sync.aligned.m8n8.x4.shared.b16 {%0,%1,%2,%3}, [%4];"
                 : "=r"(r0), "=r"(r1), "=r"(r2), "=r"(r3) : "r"(addr));
}
__device__ __forceinline__ void cpasync16(unsigned dst, const void* src) {
    asm volatile("cp.async.cg.shared.global [%0], [%1], 16;\n" :: "r"(dst), "l"(src));
}

// ---------------- unified weight/operand conversion (fp32 -> bf16) ----------------
// 4-elem units, segment table baked in.
#define N_ENC (MROWS * HDIM / 4)
#define N_SQ  (HDIM * HDIM / 4)           // 65536
#define N_WQ2 (1536 * HDIM / 4)           // 196608
#define N_WIH (1536 * 1024 / 4)           // 393216
#define N_WO  (VOCAB * HDIM / 4)          // 4096000
#define CB0 (N_ENC)
#define CB1 (CB0 + N_SQ)
#define CB2 (CB1 + N_SQ)
#define CB3 (CB2 + N_WQ2)
#define CB4 (CB3 + N_SQ)
#define CB5 (CB4 + N_SQ)
#define CB6 (CB5 + N_WIH)
#define CB7 (CB6 + N_WO)

__device__ __forceinline__ void copy4(__nv_bfloat16* dst, const float* src) {
    float4 v = *(const float4*)src;
    uint2 o;
    o.x = bf2(v.x, v.y);
    o.y = bf2(v.z, v.w);
    *(uint2*)dst = o;
}

__global__ void conv_all_kernel(const float* __restrict__ enc,
                                const float* __restrict__ W1,
                                const float* __restrict__ Whh,
                                const float* __restrict__ W2,
                                const float* __restrict__ W3,
                                const float* __restrict__ Wih,
                                const float* __restrict__ Wo) {
    const int i = blockIdx.x * blockDim.x + threadIdx.x;
    if (i >= CB7) return;
    if (i < CB0) {
        copy4(g_encb + i * 4, enc + i * 4);
    } else if (i < CB1) {                       // Wp = W1[:, :512]
        const int l = i - CB0, r = l >> 7, c = (l & 127) * 4;
        copy4(g_Wp + l * 4, W1 + (size_t)r * 1024 + c);
    } else if (i < CB2) {                       // Wqh[0:512] = W1[:, 512:]
        const int l = i - CB1, r = l >> 7, c = (l & 127) * 4;
        copy4(g_Wqh + l * 4, W1 + (size_t)r * 1024 + 512 + c);
    } else if (i < CB3) {                       // Wqh[512:2048] = Whh
        const int l = i - CB2;
        copy4(g_Wqh + HDIM * HDIM + l * 4, Whh + l * 4);
    } else if (i < CB4) {
        const int l = i - CB3;
        copy4(g_W2 + l * 4, W2 + l * 4);
    } else if (i < CB5) {
        const int l = i - CB4;
        copy4(g_W3 + l * 4, W3 + l * 4);
    } else if (i < CB6) {
        const int l = i - CB5;
        copy4(g_Wih + l * 4, Wih + l * 4);
    } else {
        const int l = i - CB6;
        copy4(g_Wo + l * 4, Wo + l * 4);
    }
}

__global__ void init_misc_kernel(const float* __restrict__ ench,
                                 const float* __restrict__ b1,
                                 const float* __restrict__ bhh) {
    const int i = blockIdx.x * blockDim.x + threadIdx.x;
    if (i < BATCH * HDIM) {
        const float h = ench[i];
        g_hid[0][i] = h;
        g_hbf[i] = __float2bfloat16(h);
    }
    if (i < 2048) g_bqh[i] = (i < HDIM) ? b1[i] : bhh[i - HDIM];
}

// ---------------- A1 = tanh(P + q)  (bf16) ----------------
__global__ __launch_bounds__(256) void a1prep_kernel(const float* __restrict__ P,
                                                     const float* __restrict__ qgh) {
    const int i4 = (blockIdx.x * blockDim.x + threadIdx.x) * 4;
    const int row = i4 >> 9, k = i4 & 511;
    float4 p = *(const float4*)(P + i4);
    const float* q = qgh + ((row >> 6) << 11) + k;
    uint2 o;
    o.x = bf2(tanh_fast(p.x + q[0]), tanh_fast(p.y + q[1]));
    o.y = bf2(tanh_fast(p.z + q[2]), tanh_fast(p.w + q[3]));
    *(uint2*)(g_A1 + i4) = o;
}

// ---------------- GEMM: cp.async 4-stage, A bf16, W bf16, ldmatrix + mma ----------------
// CTA 128x128, warp 32x64 (4x2 warps), K-tile 16.
// smem rows 48B stride (LDSM conflict-free); stage = A(6KB) + W(6KB).
// EPI 0: C fp32 = acc + bias
// EPI 1: C bf16 = tanh(acc + bias)
// EPI 2: e-dot: C = e_part[8][M] slices of sum(tanh(acc+bias[col]) * v[col])
template <int EPI>
__global__ __launch_bounds__(256) void gemm2(
    const __nv_bfloat16* __restrict__ A, int lda,
    const __nv_bfloat16* __restrict__ W, int ldw,
    const float* __restrict__ bias,
    void* __restrict__ Cv, size_t ldc,
    int M, int K,
    const float* __restrict__ v)
{
    __shared__ __align__(16) unsigned char sm[STAGES][2][128 * 48];

    const int tid    = threadIdx.x;
    const int warpid = tid >> 5, lane = tid & 31;
    const int wm = warpid >> 1, wn = warpid & 1;
    const int gid = lane >> 2, tidg = lane & 3;
    const int bm0 = blockIdx.y * 128, bn0 = blockIdx.x * 128;
    const int frow = tid >> 1;    // 0..127
    const int half = tid & 1;

    const unsigned sbase = (unsigned)__cvta_generic_to_shared(&sm[0][0][0]);
    unsigned aoff[2], boff[4];
    #pragma unroll
    for (int mi = 0; mi < 2; mi++)
        aoff[mi] = (unsigned)((wm * 32 + mi * 16 + (lane & 15)) * 48 + (lane >> 4) * 16);
    #pragma unroll
    for (int p = 0; p < 4; p++)
        boff[p] = (unsigned)(6144 +
            (wn * 64 + p * 16 + ((lane >> 4) << 3) + (lane & 7)) * 48 + ((lane >> 3) & 1) * 16);

    float acc[2][8][4];
    #pragma unroll
    for (int mi = 0; mi < 2; mi++)
        #pragma unroll
        for (int ni = 0; ni < 8; ni++)
            #pragma unroll
            for (int qq = 0; qq < 4; qq++) acc[mi][ni][qq] = 0.f;

    const int nk = K >> 4;
    const unsigned dstA = frow * 48 + half * 16;

    auto issue = [&](int kt) {
        const unsigned st = (unsigned)(kt & (STAGES - 1)) * 12288;
        cpasync16(sbase + st + dstA, A + (size_t)(bm0 + frow) * lda + (kt << 4) + half * 8);
        cpasync16(sbase + st + 6144 + dstA, W + (size_t)(bn0 + frow) * ldw + (kt << 4) + half * 8);
        asm volatile("cp.async.commit_group;\n");
    };

    #pragma unroll
    for (int s = 0; s < STAGES - 1; s++) issue(s);   // nk >= 32 > STAGES-1 always

    for (int kt = 0; kt < nk; kt++) {
        asm volatile("cp.async.wait_group %0;\n" :: "n"(STAGES - 2));
        __syncthreads();
        if (kt + STAGES - 1 < nk) issue(kt + STAGES - 1);
        else asm volatile("cp.async.commit_group;\n");

        const unsigned sb = sbase + (unsigned)(kt & (STAGES - 1)) * 12288;
        unsigned af[2][4], bfr[8][2];
        #pragma unroll
        for (int mi = 0; mi < 2; mi++)
            ldsm4(af[mi][0], af[mi][1], af[mi][2], af[mi][3], sb + aoff[mi]);
        #pragma unroll
        for (int p = 0; p < 4; p++) {
            unsigned r0, r1, r2, r3;
            ldsm4(r0, r1, r2, r3, sb + boff[p]);
            bfr[2 * p][0] = r0;     bfr[2 * p][1] = r1;
            bfr[2 * p + 1][0] = r2; bfr[2 * p + 1][1] = r3;
        }
        #pragma unroll
        for (int mi = 0; mi < 2; mi++)
            #pragma unroll
            for (int ni = 0; ni < 8; ni++)
                mma_bf16(acc[mi][ni], af[mi], bfr[ni]);
    }

    if (EPI == 2) {
        float* C = (float*)Cv;
        float es[2][2] = {{0.f, 0.f}, {0.f, 0.f}};
        #pragma unroll
        for (int mi = 0; mi < 2; mi++) {
            #pragma unroll
            for (int ni = 0; ni < 8; ni++) {
                const int col = bn0 + wn * 64 + ni * 8 + tidg * 2;
                const float v0 = v[col], v1 = v[col + 1];
                const float b0 = bias[col], b1 = bias[col + 1];
                es[mi][0] += tanh_fast(acc[mi][ni][0] + b0) * v0
                           + tanh_fast(acc[mi][ni][1] + b1) * v1;
                es[mi][1] += tanh_fast(acc[mi][ni][2] + b0) * v0
                           + tanh_fast(acc[mi][ni][3] + b1) * v1;
            }
        }
        const int slice = blockIdx.x * 2 + wn;   // 0..7
        #pragma unroll
        for (int mi = 0; mi < 2; mi++) {
            #pragma unroll
            for (int hh = 0; hh < 2; hh++) {
                float s = es[mi][hh];
                s += __shfl_xor_sync(0xffffffffu, s, 1);
                s += __shfl_xor_sync(0xffffffffu, s, 2);
                if (tidg == 0) {
                    const int row = bm0 + wm * 32 + mi * 16 + gid + hh * 8;
                    C[(size_t)slice * M + row] = s;
                }
            }
        }
        return;
    }

    #pragma unroll
    for (int mi = 0; mi < 2; mi++) {
        #pragma unroll
        for (int ni = 0; ni < 8; ni++) {
            const int col = bn0 + wn * 64 + ni * 8 + tidg * 2;
            const float b0v = bias ? bias[col] : 0.f;
            const float b1v = bias ? bias[col + 1] : 0.f;
            const int row0 = bm0 + wm * 32 + mi * 16 + gid;
            float v0 = acc[mi][ni][0] + b0v, v1 = acc[mi][ni][1] + b1v;
            float v2 = acc[mi][ni][2] + b0v, v3 = acc[mi][ni][3] + b1v;
            if (EPI == 1) {
                __nv_bfloat16* C = (__nv_bfloat16*)Cv;
                *(unsigned*)(C + (size_t)row0 * ldc + col) =
                    bf2(tanh_fast(v0), tanh_fast(v1));
                *(unsigned*)(C + (size_t)(row0 + 8) * ldc + col) =
                    bf2(tanh_fast(v2), tanh_fast(v3));
            } else {
                float* C = (float*)Cv;
                C[(size_t)row0 * ldc + col]           = v0;
                C[(size_t)row0 * ldc + col + 1]       = v1;
                C[(size_t)(row0 + 8) * ldc + col]     = v2;
                C[(size_t)(row0 + 8) * ldc + col + 1] = v3;
            }
        }
    }
}

// ---------------- e from partials ; softmax ; ctx ; build xt = [emb|ctx] bf16 ----------------
__global__ __launch_bounds__(256) void softmax_ctx_kernel(
    const float* __restrict__ epart,
    const float* __restrict__ enc,
    const int* __restrict__ tgt_t,
    const float* __restrict__ emb)
{
    __shared__ float e[ENCL];
    __shared__ float alpha[ENCL];
    const int b = blockIdx.x;
    const int tid = threadIdx.x;
    const int warp = tid >> 5, lane = tid & 31;

    if (tid < ENCL) {
        float s = 0.f;
        #pragma unroll
        for (int sl = 0; sl < 8; sl++) s += epart[sl * MROWS + b * ENCL + tid];
        e[tid] = s;
    }
    // gather embedding row -> xt[:, 0:512]
    {
        int tg = tgt_t[b * 32];
        tg = max(0, min(tg, VOCAB - 1));
        const float* er = emb + (size_t)tg * HDIM;
        for (int j = tid; j < HDIM; j += 256)
            g_xt[b * 1024 + j] = __float2bfloat16(er[j]);
    }
    __syncthreads();
    if (warp == 0) {
        const float e0 = e[lane], e1 = e[lane + 32];
        float m = fmaxf(e0, e1);
        #pragma unroll
        for (int o = 16; o; o >>= 1) m = fmaxf(m, __shfl_xor_sync(0xffffffffu, m, o));
        const float x0 = expf(e0 - m), x1 = expf(e1 - m);
        float s = x0 + x1;
        #pragma unroll
        for (int o = 16; o; o >>= 1) s += __shfl_xor_sync(0xffffffffu, s, o);
        const float inv = 1.f / s;
        alpha[lane]      = x0 * inv;
        alpha[lane + 32] = x1 * inv;
    }
    __syncthreads();
    for (int j = tid; j < HDIM; j += 256) {
        float s = 0.f;
        #pragma unroll
        for (int l = 0; l < ENCL; l++)
            s += alpha[l] * enc[((size_t)b * ENCL + l) * HDIM + j];
        g_xt[b * 1024 + 512 + j] = __float2bfloat16(s);
    }
}

// ---------------- GRU gate combine; writes fp32 state + bf16 mirror ----------------
__global__ void gru_kernel(const float* __restrict__ gi, const float* __restrict__ qgh,
                           const float* __restrict__ h, float* __restrict__ hn)
{
    const int b = blockIdx.x, j = threadIdx.x;
    const int o  = b * 3 * HDIM;
    const int og = b * 2048 + HDIM;
    const float r = 1.f / (1.f + expf(-(gi[o + j] + qgh[og + j])));
    const float z = 1.f / (1.f + expf(-(gi[o + HDIM + j] + qgh[og + HDIM + j])));
    const float n = tanhf(gi[o + 2 * HDIM + j] + r * qgh[og + 2 * HDIM + j]);
    const float hv = h[b * HDIM + j];
    const float out = (1.f - z) * n + z * hv;
    hn[b * HDIM + j] = out;
    g_hbf[b * HDIM + j] = __float2bfloat16(out);
}

// ---------------- in-place log-softmax over one row of 32000 ----------------
__global__ __launch_bounds__(1024) void logsoftmax_kernel(float* __restrict__ out, int t) {
    const int b = blockIdx.x;
    float* row = out + ((size_t)b * NSTEP + t) * VOCAB;
    const int tid = threadIdx.x;
    __shared__ float sm[32];

    float r[32];
    float m = -1e30f;
    #pragma unroll
    for (int i = 0; i < 32; i++) {
        const int idx = tid + (i << 10);
        r[i] = (idx < VOCAB) ? row[idx] : -1e30f;
        m = fmaxf(m, r[i]);
    }
    #pragma unroll
    for (int o = 16; o; o >>= 1) m = fmaxf(m, __shfl_xor_sync(0xffffffffu, m, o));
    if ((tid & 31) == 0) sm[tid >> 5] = m;
    __syncthreads();
    if (tid == 0) {
        float v = sm[0];
        for (int i = 1; i < 32; i++) v = fmaxf(v, sm[i]);
        sm[0] = v;
    }
    __syncthreads();
    m = sm[0];

    float s = 0.f;
    #pragma unroll
    for (int i = 0; i < 32; i++) {
        const int idx = tid + (i << 10);
        if (idx < VOCAB) s += expf(r[i] - m);
    }
    #pragma unroll
    for (int o = 16; o; o >>= 1) s += __shfl_xor_sync(0xffffffffu, s, o);
    __syncthreads();
    if ((tid & 31) == 0) sm[tid >> 5] = s;
    __syncthreads();
    if (tid == 0) {
        float v = 0.f;
        for (int i = 0; i < 32; i++) v += sm[i];
        sm[0] = v;
    }
    __syncthreads();
    const float lse = m + logf(sm[0]);

    #pragma unroll
    for (int i = 0; i < 32; i++) {
        const int idx = tid + (i << 10);
        if (idx < VOCAB) row[idx] = r[i] - lse;
    }
}

// ---------------- launch ----------------
extern "C" void kernel_launch(void* const* d_in, const int* in_sizes, int n_in,
                              void* d_out, int out_size)
{
    const float* enc       = (const float*)d_in[0];
    const float* ench      = (const float*)d_in[1];
    const int* tgt         = (const int*)d_in[2];    // int32 (JAX x64 disabled)
    const float* emb       = (const float*)d_in[3];
    const float* W1        = (const float*)d_in[4];
    const float* b1        = (const float*)d_in[5];
    const float* W2        = (const float*)d_in[6];
    const float* b2        = (const float*)d_in[7];
    const float* W3        = (const float*)d_in[8];
    const float* b3        = (const float*)d_in[9];
    const float* av        = (const float*)d_in[10];
    const float* Wih       = (const float*)d_in[11];
    const float* Whh       = (const float*)d_in[12];
    const float* bih       = (const float*)d_in[13];
    const float* bhh       = (const float*)d_in[14];
    const float* oW        = (const float*)d_in[15];
    const float* ob        = (const float*)d_in[16];
    float* out = (float*)d_out;

    float *P, *epart, *hidb, *qgh, *gi, *bqh;
    __nv_bfloat16 *A1, *a2b, *hbf, *xt, *encb, *Wp, *Wqh, *W2b, *W3b, *Wihb, *Wob;
    cudaGetSymbolAddress((void**)&P,     g_P);
    cudaGetSymbolAddress((void**)&A1,    g_A1);
    cudaGetSymbolAddress((void**)&a2b,   g_a2);
    cudaGetSymbolAddress((void**)&epart, g_epart);
    cudaGetSymbolAddress((void**)&hidb,  g_hid);
    cudaGetSymbolAddress((void**)&hbf,   g_hbf);
    cudaGetSymbolAddress((void**)&qgh,   g_qgh);
    cudaGetSymbolAddress((void**)&xt,    g_xt);
    cudaGetSymbolAddress((void**)&gi,    g_gi);
    cudaGetSymbolAddress((void**)&bqh,   g_bqh);
    cudaGetSymbolAddress((void**)&encb,  g_encb);
    cudaGetSymbolAddress((void**)&Wp,    g_Wp);
    cudaGetSymbolAddress((void**)&Wqh,   g_Wqh);
    cudaGetSymbolAddress((void**)&W2b,   g_W2);
    cudaGetSymbolAddress((void**)&W3b,   g_W3);
    cudaGetSymbolAddress((void**)&Wihb,  g_Wih);
    cudaGetSymbolAddress((void**)&Wob,   g_Wo);

    init_misc_kernel<<<(BATCH * HDIM + 255) / 256, 256>>>(ench, b1, bhh);
    conv_all_kernel<<<(CB7 + 255) / 256, 256>>>(enc, W1, Whh, W2, W3, Wih, oW);

    // P = enc @ W1[:, :H]^T  (fp32 out, no bias)
    gemm2<0><<<dim3(HDIM / 128, MROWS / 128), 256>>>(
        encb, HDIM, Wp, HDIM, nullptr, P, HDIM, MROWS, HDIM, nullptr);

    for (int t = 0; t < NSTEP; t++) {
        float* hi = hidb + (t & 1) * (BATCH * HDIM);
        float* ho = hidb + ((t + 1) & 1) * (BATCH * HDIM);

        // [q | gh] = hid @ [W1b ; Whh]^T + [b1 | bhh]
        gemm2<0><<<dim3(2048 / 128, 1), 256>>>(
            hbf, HDIM, Wqh, HDIM, bqh, qgh, 2048, BATCH, HDIM, nullptr);

        // A1 = tanh(P + q)  (bf16)
        a1prep_kernel<<<MROWS * HDIM / 4 / 256, 256>>>(P, qgh);

        // a2 = tanh(A1 @ W2^T + b2)  (bf16 out)
        gemm2<1><<<dim3(HDIM / 128, MROWS / 128), 256>>>(
            A1, HDIM, W2b, HDIM, b2, a2b, HDIM, MROWS, HDIM, nullptr);

        // e_part = slicewise [ tanh(a2 @ W3^T + b3) . v ]
        gemm2<2><<<dim3(HDIM / 128, MROWS / 128), 256>>>(
            a2b, HDIM, W3b, HDIM, b3, epart, 0, MROWS, HDIM, av);

        // softmax over L, ctx, build xt = [emb[tgt_t] | ctx] bf16
        softmax_ctx_kernel<<<BATCH, 256>>>(epart, enc, tgt + t, emb);

        // gi = xt @ Wih^T + bih
        gemm2<0><<<dim3(1536 / 128, 1), 256>>>(
            xt, 1024, Wihb, 1024, bih, gi, 1536, BATCH, 1024, nullptr);

        gru_kernel<<<BATCH, HDIM>>>(gi, qgh, hi, ho);

        // logits -> d_out (strided rows), then in-place log-softmax
        gemm2<0><<<dim3(VOCAB / 128, 1), 256>>>(
            hbf, HDIM, Wob, HDIM, ob, out + (size_t)t * VOCAB, (size_t)NSTEP * VOCAB,
            BATCH, HDIM, nullptr);

        logsoftmax_kernel<<<BATCH, 1024>>>(out, t);
    }
}

// round 7
// speedup vs baseline: 1.3200x; 1.0175x over previous
#include <cuda_runtime.h>
#include <cuda_bf16.h>
#include <math.h>

#define VOCAB 32000
#define HDIM  512
#define BATCH 128
#define ENCL  64
#define NSTEP 31
#define MROWS (BATCH * ENCL)   // 8192
#define STAGES 4

// ---------------- scratch (static device globals; no allocation) ----------------
__device__ float          g_P[MROWS * HDIM];        // enc @ W1a^T (fp32, time-invariant)
__device__ __nv_bfloat16  g_A1[MROWS * HDIM];       // tanh(P + q)  (per step)
__device__ __nv_bfloat16  g_a2[MROWS * HDIM];
__device__ float          g_epart[8 * MROWS];       // per-slice partial dots (a3 . v)
__device__ float          g_hid[2][BATCH * HDIM];   // fp32 recurrence (ping-pong)
__device__ __nv_bfloat16  g_hbf[BATCH * HDIM];      // bf16 mirror of current hidden
__device__ float          g_qgh[BATCH * 2048];      // [q(512) | gh(1536)]
__device__ __nv_bfloat16  g_xt[BATCH * 1024];       // [emb[tgt] | ctx]  bf16
__device__ float          g_gi[BATCH * 3 * HDIM];
__device__ float          g_bqh[2048];              // [b1 | bhh]

// bf16 operand copies (converted once per replay)
__device__ __nv_bfloat16 g_encb[MROWS * HDIM];
__device__ __nv_bfloat16 g_Wp  [HDIM * HDIM];
__device__ __nv_bfloat16 g_Wqh [2048 * HDIM];
__device__ __nv_bfloat16 g_W2  [HDIM * HDIM];
__device__ __nv_bfloat16 g_W3  [HDIM * HDIM];
__device__ __nv_bfloat16 g_Wih [1536 * 1024];
__device__ __nv_bfloat16 g_Wo  [VOCAB * HDIM];

// ---------------- helpers ----------------
__device__ __forceinline__ unsigned bf2(float lo, float hi) {
    unsigned u;
    asm("cvt.rn.bf16x2.f32 %0, %1, %2;" : "=r"(u) : "f"(hi), "f"(lo));
    return u;
}
__device__ __forceinline__ float tanh_fast(float x) {
    float y;
    asm("tanh.approx.f32 %0, %1;" : "=f"(y) : "f"(x));
    return y;
}
__device__ __forceinline__ void mma_bf16(float c[4], const unsigned a[4], const unsigned b[2]) {
    asm volatile(
        "mma.sync.aligned.m16n8k16.row.col.f32.bf16.bf16.f32 "
        "{%0,%1,%2,%3}, {%4,%5,%6,%7}, {%8,%9}, {%0,%1,%2,%3};\n"
        : "+f"(c[0]), "+f"(c[1]), "+f"(c[2]), "+f"(c[3])
        : "r"(a[0]), "r"(a[1]), "r"(a[2]), "r"(a[3]), "r"(b[0]), "r"(b[1]));
}
__device__ __forceinline__ void ldsm4(unsigned& r0, unsigned& r1, unsigned& r2, unsigned& r3,
                                      unsigned addr) {
    asm volatile("ldmatrix.sync.aligned.m8n8.x4.shared.b16 {%0,%1,%2,%3}, [%4];"
                 : "=r"(r0), "=r"(r1), "=r"(r2), "=r"(r3) : "r"(addr));
}
__device__ __forceinline__ void cpasync16(unsigned dst, const void* src) {
    asm volatile("cp.async.cg.shared.global [%0], [%1], 16;\n" :: "r"(dst), "l"(src));
}

// ---------------- unified weight/operand conversion (fp32 -> bf16) ----------------
// 4-elem units, segment table baked in.
#define N_ENC (MROWS * HDIM / 4)
#define N_SQ  (HDIM * HDIM / 4)           // 65536
#define N_WQ2 (1536 * HDIM / 4)           // 196608
#define N_WIH (1536 * 1024 / 4)           // 393216
#define N_WO  (VOCAB * HDIM / 4)          // 4096000
#define CB0 (N_ENC)
#define CB1 (CB0 + N_SQ)
#define CB2 (CB1 + N_SQ)
#define CB3 (CB2 + N_WQ2)
#define CB4 (CB3 + N_SQ)
#define CB5 (CB4 + N_SQ)
#define CB6 (CB5 + N_WIH)
#define CB7 (CB6 + N_WO)

__device__ __forceinline__ void copy4(__nv_bfloat16* dst, const float* src) {
    float4 v = *(const float4*)src;
    uint2 o;
    o.x = bf2(v.x, v.y);
    o.y = bf2(v.z, v.w);
    *(uint2*)dst = o;
}

__global__ void conv_all_kernel(const float* __restrict__ enc,
                                const float* __restrict__ W1,
                                const float* __restrict__ Whh,
                                const float* __restrict__ W2,
                                const float* __restrict__ W3,
                                const float* __restrict__ Wih,
                                const float* __restrict__ Wo) {
    const int i = blockIdx.x * blockDim.x + threadIdx.x;
    if (i >= CB7) return;
    if (i < CB0) {
        copy4(g_encb + i * 4, enc + i * 4);
    } else if (i < CB1) {                       // Wp = W1[:, :512]
        const int l = i - CB0, r = l >> 7, c = (l & 127) * 4;
        copy4(g_Wp + l * 4, W1 + (size_t)r * 1024 + c);
    } else if (i < CB2) {                       // Wqh[0:512] = W1[:, 512:]
        const int l = i - CB1, r = l >> 7, c = (l & 127) * 4;
        copy4(g_Wqh + l * 4, W1 + (size_t)r * 1024 + 512 + c);
    } else if (i < CB3) {                       // Wqh[512:2048] = Whh
        const int l = i - CB2;
        copy4(g_Wqh + HDIM * HDIM + l * 4, Whh + l * 4);
    } else if (i < CB4) {
        const int l = i - CB3;
        copy4(g_W2 + l * 4, W2 + l * 4);
    } else if (i < CB5) {
        const int l = i - CB4;
        copy4(g_W3 + l * 4, W3 + l * 4);
    } else if (i < CB6) {
        const int l = i - CB5;
        copy4(g_Wih + l * 4, Wih + l * 4);
    } else {
        const int l = i - CB6;
        copy4(g_Wo + l * 4, Wo + l * 4);
    }
}

__global__ void init_misc_kernel(const float* __restrict__ ench,
                                 const float* __restrict__ b1,
                                 const float* __restrict__ bhh) {
    const int i = blockIdx.x * blockDim.x + threadIdx.x;
    if (i < BATCH * HDIM) {
        const float h = ench[i];
        g_hid[0][i] = h;
        g_hbf[i] = __float2bfloat16(h);
    }
    if (i < 2048) g_bqh[i] = (i < HDIM) ? b1[i] : bhh[i - HDIM];
}

// ---------------- A1 = tanh(P + q)  (bf16) ----------------
__global__ __launch_bounds__(256) void a1prep_kernel(const float* __restrict__ P,
                                                     const float* __restrict__ qgh) {
    const int i4 = (blockIdx.x * blockDim.x + threadIdx.x) * 4;
    const int row = i4 >> 9, k = i4 & 511;
    float4 p = *(const float4*)(P + i4);
    const float* q = qgh + ((row >> 6) << 11) + k;
    uint2 o;
    o.x = bf2(tanh_fast(p.x + q[0]), tanh_fast(p.y + q[1]));
    o.y = bf2(tanh_fast(p.z + q[2]), tanh_fast(p.w + q[3]));
    *(uint2*)(g_A1 + i4) = o;
}

// ---------------- GEMM: cp.async 4-stage, A bf16, W bf16, ldmatrix + mma ----------------
// CTA 128x128, warp 32x64 (4x2 warps), K-tile 16.
// smem rows 48B stride (LDSM conflict-free); stage = A(6KB) + W(6KB).
// EPI 0: C fp32 = acc + bias
// EPI 1: C bf16 = tanh(acc + bias)
// EPI 2: e-dot: C = e_part[8][M] slices of sum(tanh(acc+bias[col]) * v[col])
template <int EPI>
__global__ __launch_bounds__(256) void gemm2(
    const __nv_bfloat16* __restrict__ A, int lda,
    const __nv_bfloat16* __restrict__ W, int ldw,
    const float* __restrict__ bias,
    void* __restrict__ Cv, size_t ldc,
    int M, int K,
    const float* __restrict__ v)
{
    __shared__ __align__(16) unsigned char sm[STAGES][2][128 * 48];

    const int tid    = threadIdx.x;
    const int warpid = tid >> 5, lane = tid & 31;
    const int wm = warpid >> 1, wn = warpid & 1;
    const int gid = lane >> 2, tidg = lane & 3;
    const int bm0 = blockIdx.y * 128, bn0 = blockIdx.x * 128;
    const int frow = tid >> 1;    // 0..127
    const int half = tid & 1;

    const unsigned sbase = (unsigned)__cvta_generic_to_shared(&sm[0][0][0]);
    unsigned aoff[2], boff[4];
    #pragma unroll
    for (int mi = 0; mi < 2; mi++)
        aoff[mi] = (unsigned)((wm * 32 + mi * 16 + (lane & 15)) * 48 + (lane >> 4) * 16);
    #pragma unroll
    for (int p = 0; p < 4; p++)
        boff[p] = (unsigned)(6144 +
            (wn * 64 + p * 16 + ((lane >> 4) << 3) + (lane & 7)) * 48 + ((lane >> 3) & 1) * 16);

    float acc[2][8][4];
    #pragma unroll
    for (int mi = 0; mi < 2; mi++)
        #pragma unroll
        for (int ni = 0; ni < 8; ni++)
            #pragma unroll
            for (int qq = 0; qq < 4; qq++) acc[mi][ni][qq] = 0.f;

    const int nk = K >> 4;
    const unsigned dstA = frow * 48 + half * 16;

    auto issue = [&](int kt) {
        const unsigned st = (unsigned)(kt & (STAGES - 1)) * 12288;
        cpasync16(sbase + st + dstA, A + (size_t)(bm0 + frow) * lda + (kt << 4) + half * 8);
        cpasync16(sbase + st + 6144 + dstA, W + (size_t)(bn0 + frow) * ldw + (kt << 4) + half * 8);
        asm volatile("cp.async.commit_group;\n");
    };

    #pragma unroll
    for (int s = 0; s < STAGES - 1; s++) issue(s);   // nk >= 32 > STAGES-1 always

    for (int kt = 0; kt < nk; kt++) {
        asm volatile("cp.async.wait_group %0;\n" :: "n"(STAGES - 2));
        __syncthreads();
        if (kt + STAGES - 1 < nk) issue(kt + STAGES - 1);
        else asm volatile("cp.async.commit_group;\n");

        const unsigned sb = sbase + (unsigned)(kt & (STAGES - 1)) * 12288;
        unsigned af[2][4], bfr[8][2];
        #pragma unroll
        for (int mi = 0; mi < 2; mi++)
            ldsm4(af[mi][0], af[mi][1], af[mi][2], af[mi][3], sb + aoff[mi]);
        #pragma unroll
        for (int p = 0; p < 4; p++) {
            unsigned r0, r1, r2, r3;
            ldsm4(r0, r1, r2, r3, sb + boff[p]);
            bfr[2 * p][0] = r0;     bfr[2 * p][1] = r1;
            bfr[2 * p + 1][0] = r2; bfr[2 * p + 1][1] = r3;
        }
        #pragma unroll
        for (int mi = 0; mi < 2; mi++)
            #pragma unroll
            for (int ni = 0; ni < 8; ni++)
                mma_bf16(acc[mi][ni], af[mi], bfr[ni]);
    }

    if (EPI == 2) {
        float* C = (float*)Cv;
        float es[2][2] = {{0.f, 0.f}, {0.f, 0.f}};
        #pragma unroll
        for (int mi = 0; mi < 2; mi++) {
            #pragma unroll
            for (int ni = 0; ni < 8; ni++) {
                const int col = bn0 + wn * 64 + ni * 8 + tidg * 2;
                const float v0 = v[col], v1 = v[col + 1];
                const float b0 = bias[col], b1 = bias[col + 1];
                es[mi][0] += tanh_fast(acc[mi][ni][0] + b0) * v0
                           + tanh_fast(acc[mi][ni][1] + b1) * v1;
                es[mi][1] += tanh_fast(acc[mi][ni][2] + b0) * v0
                           + tanh_fast(acc[mi][ni][3] + b1) * v1;
            }
        }
        const int slice = blockIdx.x * 2 + wn;   // 0..7
        #pragma unroll
        for (int mi = 0; mi < 2; mi++) {
            #pragma unroll
            for (int hh = 0; hh < 2; hh++) {
                float s = es[mi][hh];
                s += __shfl_xor_sync(0xffffffffu, s, 1);
                s += __shfl_xor_sync(0xffffffffu, s, 2);
                if (tidg == 0) {
                    const int row = bm0 + wm * 32 + mi * 16 + gid + hh * 8;
                    C[(size_t)slice * M + row] = s;
                }
            }
        }
        return;
    }

    #pragma unroll
    for (int mi = 0; mi < 2; mi++) {
        #pragma unroll
        for (int ni = 0; ni < 8; ni++) {
            const int col = bn0 + wn * 64 + ni * 8 + tidg * 2;
            const float b0v = bias ? bias[col] : 0.f;
            const float b1v = bias ? bias[col + 1] : 0.f;
            const int row0 = bm0 + wm * 32 + mi * 16 + gid;
            float v0 = acc[mi][ni][0] + b0v, v1 = acc[mi][ni][1] + b1v;
            float v2 = acc[mi][ni][2] + b0v, v3 = acc[mi][ni][3] + b1v;
            if (EPI == 1) {
                __nv_bfloat16* C = (__nv_bfloat16*)Cv;
                *(unsigned*)(C + (size_t)row0 * ldc + col) =
                    bf2(tanh_fast(v0), tanh_fast(v1));
                *(unsigned*)(C + (size_t)(row0 + 8) * ldc + col) =
                    bf2(tanh_fast(v2), tanh_fast(v3));
            } else {
                float* C = (float*)Cv;
                C[(size_t)row0 * ldc + col]           = v0;
                C[(size_t)row0 * ldc + col + 1]       = v1;
                C[(size_t)(row0 + 8) * ldc + col]     = v2;
                C[(size_t)(row0 + 8) * ldc + col + 1] = v3;
            }
        }
    }
}

// ---------------- e from partials ; softmax ; ctx ; build xt = [emb|ctx] bf16 ----------------
__global__ __launch_bounds__(256) void softmax_ctx_kernel(
    const float* __restrict__ epart,
    const float* __restrict__ enc,
    const int* __restrict__ tgt_t,
    const float* __restrict__ emb)
{
    __shared__ float e[ENCL];
    __shared__ float alpha[ENCL];
    const int b = blockIdx.x;
    const int tid = threadIdx.x;
    const int warp = tid >> 5, lane = tid & 31;

    if (tid < ENCL) {
        float s = 0.f;
        #pragma unroll
        for (int sl = 0; sl < 8; sl++) s += epart[sl * MROWS + b * ENCL + tid];
        e[tid] = s;
    }
    // gather embedding row -> xt[:, 0:512]
    {
        int tg = tgt_t[b * 32];
        tg = max(0, min(tg, VOCAB - 1));
        const float* er = emb + (size_t)tg * HDIM;
        for (int j = tid; j < HDIM; j += 256)
            g_xt[b * 1024 + j] = __float2bfloat16(er[j]);
    }
    __syncthreads();
    if (warp == 0) {
        const float e0 = e[lane], e1 = e[lane + 32];
        float m = fmaxf(e0, e1);
        #pragma unroll
        for (int o = 16; o; o >>= 1) m = fmaxf(m, __shfl_xor_sync(0xffffffffu, m, o));
        const float x0 = expf(e0 - m), x1 = expf(e1 - m);
        float s = x0 + x1;
        #pragma unroll
        for (int o = 16; o; o >>= 1) s += __shfl_xor_sync(0xffffffffu, s, o);
        const float inv = 1.f / s;
        alpha[lane]      = x0 * inv;
        alpha[lane + 32] = x1 * inv;
    }
    __syncthreads();
    for (int j = tid; j < HDIM; j += 256) {
        float s = 0.f;
        #pragma unroll
        for (int l = 0; l < ENCL; l++)
            s += alpha[l] * enc[((size_t)b * ENCL + l) * HDIM + j];
        g_xt[b * 1024 + 512 + j] = __float2bfloat16(s);
    }
}

// ---------------- GRU gate combine; writes fp32 state + bf16 mirror ----------------
__global__ void gru_kernel(const float* __restrict__ gi, const float* __restrict__ qgh,
                           const float* __restrict__ h, float* __restrict__ hn)
{
    const int b = blockIdx.x, j = threadIdx.x;
    const int o  = b * 3 * HDIM;
    const int og = b * 2048 + HDIM;
    const float r = 1.f / (1.f + expf(-(gi[o + j] + qgh[og + j])));
    const float z = 1.f / (1.f + expf(-(gi[o + HDIM + j] + qgh[og + HDIM + j])));
    const float n = tanhf(gi[o + 2 * HDIM + j] + r * qgh[og + 2 * HDIM + j]);
    const float hv = h[b * HDIM + j];
    const float out = (1.f - z) * n + z * hv;
    hn[b * HDIM + j] = out;
    g_hbf[b * HDIM + j] = __float2bfloat16(out);
}

// ---------------- in-place log-softmax over one row of 32000 ----------------
__global__ __launch_bounds__(1024) void logsoftmax_kernel(float* __restrict__ out, int t) {
    const int b = blockIdx.x;
    float* row = out + ((size_t)b * NSTEP + t) * VOCAB;
    const int tid = threadIdx.x;
    __shared__ float sm[32];

    float r[32];
    float m = -1e30f;
    #pragma unroll
    for (int i = 0; i < 32; i++) {
        const int idx = tid + (i << 10);
        r[i] = (idx < VOCAB) ? row[idx] : -1e30f;
        m = fmaxf(m, r[i]);
    }
    #pragma unroll
    for (int o = 16; o; o >>= 1) m = fmaxf(m, __shfl_xor_sync(0xffffffffu, m, o));
    if ((tid & 31) == 0) sm[tid >> 5] = m;
    __syncthreads();
    if (tid == 0) {
        float v = sm[0];
        for (int i = 1; i < 32; i++) v = fmaxf(v, sm[i]);
        sm[0] = v;
    }
    __syncthreads();
    m = sm[0];

    float s = 0.f;
    #pragma unroll
    for (int i = 0; i < 32; i++) {
        const int idx = tid + (i << 10);
        if (idx < VOCAB) s += expf(r[i] - m);
    }
    #pragma unroll
    for (int o = 16; o; o >>= 1) s += __shfl_xor_sync(0xffffffffu, s, o);
    __syncthreads();
    if ((tid & 31) == 0) sm[tid >> 5] = s;
    __syncthreads();
    if (tid == 0) {
        float v = 0.f;
        for (int i = 0; i < 32; i++) v += sm[i];
        sm[0] = v;
    }
    __syncthreads();
    const float lse = m + logf(sm[0]);

    #pragma unroll
    for (int i = 0; i < 32; i++) {
        const int idx = tid + (i << 10);
        if (idx < VOCAB) row[idx] = r[i] - lse;
    }
}

// ---------------- launch ----------------
extern "C" void kernel_launch(void* const* d_in, const int* in_sizes, int n_in,
                              void* d_out, int out_size)
{
    const float* enc       = (const float*)d_in[0];
    const float* ench      = (const float*)d_in[1];
    const int* tgt         = (const int*)d_in[2];    // int32 (JAX x64 disabled)
    const float* emb       = (const float*)d_in[3];
    const float* W1        = (const float*)d_in[4];
    const float* b1        = (const float*)d_in[5];
    const float* W2        = (const float*)d_in[6];
    const float* b2        = (const float*)d_in[7];
    const float* W3        = (const float*)d_in[8];
    const float* b3        = (const float*)d_in[9];
    const float* av        = (const float*)d_in[10];
    const float* Wih       = (const float*)d_in[11];
    const float* Whh       = (const float*)d_in[12];
    const float* bih       = (const float*)d_in[13];
    const float* bhh       = (const float*)d_in[14];
    const float* oW        = (const float*)d_in[15];
    const float* ob        = (const float*)d_in[16];
    float* out = (float*)d_out;

    float *P, *epart, *hidb, *qgh, *gi, *bqh;
    __nv_bfloat16 *A1, *a2b, *hbf, *xt, *encb, *Wp, *Wqh, *W2b, *W3b, *Wihb, *Wob;
    cudaGetSymbolAddress((void**)&P,     g_P);
    cudaGetSymbolAddress((void**)&A1,    g_A1);
    cudaGetSymbolAddress((void**)&a2b,   g_a2);
    cudaGetSymbolAddress((void**)&epart, g_epart);
    cudaGetSymbolAddress((void**)&hidb,  g_hid);
    cudaGetSymbolAddress((void**)&hbf,   g_hbf);
    cudaGetSymbolAddress((void**)&qgh,   g_qgh);
    cudaGetSymbolAddress((void**)&xt,    g_xt);
    cudaGetSymbolAddress((void**)&gi,    g_gi);
    cudaGetSymbolAddress((void**)&bqh,   g_bqh);
    cudaGetSymbolAddress((void**)&encb,  g_encb);
    cudaGetSymbolAddress((void**)&Wp,    g_Wp);
    cudaGetSymbolAddress((void**)&Wqh,   g_Wqh);
    cudaGetSymbolAddress((void**)&W2b,   g_W2);
    cudaGetSymbolAddress((void**)&W3b,   g_W3);
    cudaGetSymbolAddress((void**)&Wihb,  g_Wih);
    cudaGetSymbolAddress((void**)&Wob,   g_Wo);

    init_misc_kernel<<<(BATCH * HDIM + 255) / 256, 256>>>(ench, b1, bhh);
    conv_all_kernel<<<(CB7 + 255) / 256, 256>>>(enc, W1, Whh, W2, W3, Wih, oW);

    // P = enc @ W1[:, :H]^T  (fp32 out, no bias)
    gemm2<0><<<dim3(HDIM / 128, MROWS / 128), 256>>>(
        encb, HDIM, Wp, HDIM, nullptr, P, HDIM, MROWS, HDIM, nullptr);

    for (int t = 0; t < NSTEP; t++) {
        float* hi = hidb + (t & 1) * (BATCH * HDIM);
        float* ho = hidb + ((t + 1) & 1) * (BATCH * HDIM);

        // [q | gh] = hid @ [W1b ; Whh]^T + [b1 | bhh]
        gemm2<0><<<dim3(2048 / 128, 1), 256>>>(
            hbf, HDIM, Wqh, HDIM, bqh, qgh, 2048, BATCH, HDIM, nullptr);

        // A1 = tanh(P + q)  (bf16)
        a1prep_kernel<<<MROWS * HDIM / 4 / 256, 256>>>(P, qgh);

        // a2 = tanh(A1 @ W2^T + b2)  (bf16 out)
        gemm2<1><<<dim3(HDIM / 128, MROWS / 128), 256>>>(
            A1, HDIM, W2b, HDIM, b2, a2b, HDIM, MROWS, HDIM, nullptr);

        // e_part = slicewise [ tanh(a2 @ W3^T + b3) . v ]
        gemm2<2><<<dim3(HDIM / 128, MROWS / 128), 256>>>(
            a2b, HDIM, W3b, HDIM, b3, epart, 0, MROWS, HDIM, av);

        // softmax over L, ctx, build xt = [emb[tgt_t] | ctx] bf16
        softmax_ctx_kernel<<<BATCH, 256>>>(epart, enc, tgt + t, emb);

        // gi = xt @ Wih^T + bih
        gemm2<0><<<dim3(1536 / 128, 1), 256>>>(
            xt, 1024, Wihb, 1024, bih, gi, 1536, BATCH, 1024, nullptr);

        gru_kernel<<<BATCH, HDIM>>>(gi, qgh, hi, ho);

        // logits -> d_out (strided rows), then in-place log-softmax
        gemm2<0><<<dim3(VOCAB / 128, 1), 256>>>(
            hbf, HDIM, Wob, HDIM, ob, out + (size_t)t * VOCAB, (size_t)NSTEP * VOCAB,
            BATCH, HDIM, nullptr);

        logsoftmax_kernel<<<BATCH, 1024>>>(out, t);
    }
}

// round 10
// speedup vs baseline: 1.6365x; 1.2398x over previous
#include <cuda_runtime.h>
#include <cuda_bf16.h>
#include <math.h>

#define VOCAB 32000
#define HDIM  512
#define BATCH 128
#define ENCL  64
#define NSTEP 31
#define MROWS (BATCH * ENCL)   // 8192
#define STAGES 4

// ---------------- scratch (static device globals; no allocation) ----------------
__device__ float          g_P[MROWS * HDIM];        // enc @ W1a^T (fp32, time-invariant)
__device__ __nv_bfloat16  g_A1[MROWS * HDIM];       // tanh(P + q)
__device__ __nv_bfloat16  g_a2[MROWS * HDIM];
__device__ float          g_epart[8 * MROWS];       // per-slice partial dots (a3 . v)
__device__ float          g_hid[2][BATCH * HDIM];   // fp32 recurrence (ping-pong)
__device__ __nv_bfloat16  g_hbf[2][BATCH * HDIM];   // bf16 hidden (ping-pong, overlap-safe)
__device__ float          g_qgh[2 * BATCH * 2048];  // split-K parts of [q | gh]
__device__ __nv_bfloat16  g_xt[BATCH * 1024];       // [emb[tgt] | ctx]  bf16
__device__ float          g_gi[2 * BATCH * 1536];   // split-K parts of gi
__device__ float          g_bqh[2048];              // [b1 | bhh]

// bf16 operand copies (converted once per replay)
__device__ __nv_bfloat16 g_encb[MROWS * HDIM];
__device__ __nv_bfloat16 g_Wp  [HDIM * HDIM];
__device__ __nv_bfloat16 g_Wqh [2048 * HDIM];
__device__ __nv_bfloat16 g_W2  [HDIM * HDIM];
__device__ __nv_bfloat16 g_W3  [HDIM * HDIM];
__device__ __nv_bfloat16 g_Wih [1536 * 1024];
__device__ __nv_bfloat16 g_Wo  [VOCAB * HDIM];

// ---------------- helpers ----------------
__device__ __forceinline__ unsigned bf2(float lo, float hi) {
    unsigned u;
    asm("cvt.rn.bf16x2.f32 %0, %1, %2;" : "=r"(u) : "f"(hi), "f"(lo));
    return u;
}
__device__ __forceinline__ float tanh_fast(float x) {
    float y;
    asm("tanh.approx.f32 %0, %1;" : "=f"(y) : "f"(x));
    return y;
}
__device__ __forceinline__ void mma_bf16(float c[4], const unsigned a[4], const unsigned b[2]) {
    asm volatile(
        "mma.sync.aligned.m16n8k16.row.col.f32.bf16.bf16.f32 "
        "{%0,%1,%2,%3}, {%4,%5,%6,%7}, {%8,%9}, {%0,%1,%2,%3};\n"
        : "+f"(c[0]), "+f"(c[1]), "+f"(c[2]), "+f"(c[3])
        : "r"(a[0]), "r"(a[1]), "r"(a[2]), "r"(a[3]), "r"(b[0]), "r"(b[1]));
}
__device__ __forceinline__ void ldsm4(unsigned& r0, unsigned& r1, unsigned& r2, unsigned& r3,
                                      unsigned addr) {
    asm volatile("ldmatrix.sync.aligned.m8n8.x4.shared.b16 {%0,%1,%2,%3}, [%4];"
                 : "=r"(r0), "=r"(r1), "=r"(r2), "=r"(r3) : "r"(addr));
}
__device__ __forceinline__ void cpasync16(unsigned dst, const void* src) {
    asm volatile("cp.async.cg.shared.global [%0], [%1], 16;\n" :: "r"(dst), "l"(src));
}

// ---------------- unified weight/operand conversion (fp32 -> bf16) ----------------
#define N_ENC (MROWS * HDIM / 4)
#define N_SQ  (HDIM * HDIM / 4)
#define N_WQ2 (1536 * HDIM / 4)
#define N_WIH (1536 * 1024 / 4)
#define N_WO  (VOCAB * HDIM / 4)
#define CB0 (N_ENC)
#define CB1 (CB0 + N_SQ)
#define CB2 (CB1 + N_SQ)
#define CB3 (CB2 + N_WQ2)
#define CB4 (CB3 + N_SQ)
#define CB5 (CB4 + N_SQ)
#define CB6 (CB5 + N_WIH)
#define CB7 (CB6 + N_WO)

__device__ __forceinline__ void copy4(__nv_bfloat16* dst, const float* src) {
    float4 v = *(const float4*)src;
    uint2 o;
    o.x = bf2(v.x, v.y);
    o.y = bf2(v.z, v.w);
    *(uint2*)dst = o;
}

__global__ void conv_all_kernel(const float* __restrict__ enc,
                                const float* __restrict__ W1,
                                const float* __restrict__ Whh,
                                const float* __restrict__ W2,
                                const float* __restrict__ W3,
                                const float* __restrict__ Wih,
                                const float* __restrict__ Wo) {
    const int i = blockIdx.x * blockDim.x + threadIdx.x;
    if (i >= CB7) return;
    if (i < CB0) {
        copy4(g_encb + i * 4, enc + i * 4);
    } else if (i < CB1) {
        const int l = i - CB0, r = l >> 7, c = (l & 127) * 4;
        copy4(g_Wp + l * 4, W1 + (size_t)r * 1024 + c);
    } else if (i < CB2) {
        const int l = i - CB1, r = l >> 7, c = (l & 127) * 4;
        copy4(g_Wqh + l * 4, W1 + (size_t)r * 1024 + 512 + c);
    } else if (i < CB3) {
        const int l = i - CB2;
        copy4(g_Wqh + HDIM * HDIM + l * 4, Whh + l * 4);
    } else if (i < CB4) {
        const int l = i - CB3;
        copy4(g_W2 + l * 4, W2 + l * 4);
    } else if (i < CB5) {
        const int l = i - CB4;
        copy4(g_W3 + l * 4, W3 + l * 4);
    } else if (i < CB6) {
        const int l = i - CB5;
        copy4(g_Wih + l * 4, Wih + l * 4);
    } else {
        const int l = i - CB6;
        copy4(g_Wo + l * 4, Wo + l * 4);
    }
}

__global__ void init_misc_kernel(const float* __restrict__ ench,
                                 const float* __restrict__ b1,
                                 const float* __restrict__ bhh) {
    const int i = blockIdx.x * blockDim.x + threadIdx.x;
    if (i < BATCH * HDIM) {
        const float h = ench[i];
        g_hid[0][i] = h;
        g_hbf[0][i] = __float2bfloat16(h);
    }
    if (i < 2048) g_bqh[i] = (i < HDIM) ? b1[i] : bhh[i - HDIM];
}

// ---------------- A1 = tanh(P + q0 + q1)  (bf16; sums split-K q parts) ----------------
__global__ __launch_bounds__(256) void a1prep_kernel(const float* __restrict__ P,
                                                     const float* __restrict__ qgh) {
    const int i4 = (blockIdx.x * blockDim.x + threadIdx.x) * 4;
    const int row = i4 >> 9, k = i4 & 511;
    float4 p = *(const float4*)(P + i4);
    const float* q0 = qgh + ((row >> 6) << 11) + k;
    const float* q1 = q0 + BATCH * 2048;
    uint2 o;
    o.x = bf2(tanh_fast(p.x + q0[0] + q1[0]), tanh_fast(p.y + q0[1] + q1[1]));
    o.y = bf2(tanh_fast(p.z + q0[2] + q1[2]), tanh_fast(p.w + q0[3] + q1[3]));
    *(uint2*)(g_A1 + i4) = o;
}

// ---------------- GEMM: cp.async 4-stage, bf16 in, ldmatrix + mma, optional split-K ------
// CTA 128x128, warp 32x64 (4x2 warps), K-tile 16; blockIdx.z = split-K part.
// EPI 0: C fp32 = acc (+bias if z==0), written at C + z*partStride
// EPI 1: C bf16 = tanh(acc + bias)
// EPI 2: e-dot: C = e_part[8][M] slices of sum(tanh(acc+bias[col]) * v[col])
template <int EPI, int SPLIT>
__global__ __launch_bounds__(256) void gemm2(
    const __nv_bfloat16* __restrict__ A, int lda,
    const __nv_bfloat16* __restrict__ W, int ldw,
    const float* __restrict__ bias,
    void* __restrict__ Cv, size_t ldc, size_t partStride,
    int M, int K,
    const float* __restrict__ v)
{
    __shared__ __align__(16) unsigned char sm[STAGES][2][128 * 48];

    const int tid    = threadIdx.x;
    const int warpid = tid >> 5, lane = tid & 31;
    const int wm = warpid >> 1, wn = warpid & 1;
    const int gid = lane >> 2, tidg = lane & 3;
    const int bm0 = blockIdx.y * 128, bn0 = blockIdx.x * 128;
    const int z   = (SPLIT > 1) ? blockIdx.z : 0;
    const int kbase = z * (K / SPLIT);
    const int frow = tid >> 1;
    const int half = tid & 1;

    const unsigned sbase = (unsigned)__cvta_generic_to_shared(&sm[0][0][0]);
    unsigned aoff[2], boff[4];
    #pragma unroll
    for (int mi = 0; mi < 2; mi++)
        aoff[mi] = (unsigned)((wm * 32 + mi * 16 + (lane & 15)) * 48 + (lane >> 4) * 16);
    #pragma unroll
    for (int p = 0; p < 4; p++)
        boff[p] = (unsigned)(6144 +
            (wn * 64 + p * 16 + ((lane >> 4) << 3) + (lane & 7)) * 48 + ((lane >> 3) & 1) * 16);

    float acc[2][8][4];
    #pragma unroll
    for (int mi = 0; mi < 2; mi++)
        #pragma unroll
        for (int ni = 0; ni < 8; ni++)
            #pragma unroll
            for (int qq = 0; qq < 4; qq++) acc[mi][ni][qq] = 0.f;

    const int nk = (K / SPLIT) >> 4;
    const unsigned dstA = frow * 48 + half * 16;

    auto issue = [&](int kt) {
        const unsigned st = (unsigned)(kt & (STAGES - 1)) * 12288;
        cpasync16(sbase + st + dstA,
                  A + (size_t)(bm0 + frow) * lda + kbase + (kt << 4) + half * 8);
        cpasync16(sbase + st + 6144 + dstA,
                  W + (size_t)(bn0 + frow) * ldw + kbase + (kt << 4) + half * 8);
        asm volatile("cp.async.commit_group;\n");
    };

    #pragma unroll
    for (int s = 0; s < STAGES - 1; s++) issue(s);   // nk >= 16 > STAGES-1 always

    for (int kt = 0; kt < nk; kt++) {
        asm volatile("cp.async.wait_group %0;\n" :: "n"(STAGES - 2));
        __syncthreads();
        if (kt + STAGES - 1 < nk) issue(kt + STAGES - 1);
        else asm volatile("cp.async.commit_group;\n");

        const unsigned sb = sbase + (unsigned)(kt & (STAGES - 1)) * 12288;
        unsigned af[2][4], bfr[8][2];
        #pragma unroll
        for (int mi = 0; mi < 2; mi++)
            ldsm4(af[mi][0], af[mi][1], af[mi][2], af[mi][3], sb + aoff[mi]);
        #pragma unroll
        for (int p = 0; p < 4; p++) {
            unsigned r0, r1, r2, r3;
            ldsm4(r0, r1, r2, r3, sb + boff[p]);
            bfr[2 * p][0] = r0;     bfr[2 * p][1] = r1;
            bfr[2 * p + 1][0] = r2; bfr[2 * p + 1][1] = r3;
        }
        #pragma unroll
        for (int mi = 0; mi < 2; mi++)
            #pragma unroll
            for (int ni = 0; ni < 8; ni++)
                mma_bf16(acc[mi][ni], af[mi], bfr[ni]);
    }

    if (EPI == 2) {
        float* C = (float*)Cv;
        float es[2][2] = {{0.f, 0.f}, {0.f, 0.f}};
        #pragma unroll
        for (int mi = 0; mi < 2; mi++) {
            #pragma unroll
            for (int ni = 0; ni < 8; ni++) {
                const int col = bn0 + wn * 64 + ni * 8 + tidg * 2;
                const float v0 = v[col], v1 = v[col + 1];
                const float b0 = bias[col], b1 = bias[col + 1];
                es[mi][0] += tanh_fast(acc[mi][ni][0] + b0) * v0
                           + tanh_fast(acc[mi][ni][1] + b1) * v1;
                es[mi][1] += tanh_fast(acc[mi][ni][2] + b0) * v0
                           + tanh_fast(acc[mi][ni][3] + b1) * v1;
            }
        }
        const int slice = blockIdx.x * 2 + wn;
        #pragma unroll
        for (int mi = 0; mi < 2; mi++) {
            #pragma unroll
            for (int hh = 0; hh < 2; hh++) {
                float s = es[mi][hh];
                s += __shfl_xor_sync(0xffffffffu, s, 1);
                s += __shfl_xor_sync(0xffffffffu, s, 2);
                if (tidg == 0) {
                    const int row = bm0 + wm * 32 + mi * 16 + gid + hh * 8;
                    C[(size_t)slice * M + row] = s;
                }
            }
        }
        return;
    }

    const bool addBias = (bias != nullptr) && (z == 0);
    #pragma unroll
    for (int mi = 0; mi < 2; mi++) {
        #pragma unroll
        for (int ni = 0; ni < 8; ni++) {
            const int col = bn0 + wn * 64 + ni * 8 + tidg * 2;
            const float b0v = addBias ? bias[col] : 0.f;
            const float b1v = addBias ? bias[col + 1] : 0.f;
            const int row0 = bm0 + wm * 32 + mi * 16 + gid;
            float v0 = acc[mi][ni][0] + b0v, v1 = acc[mi][ni][1] + b1v;
            float v2 = acc[mi][ni][2] + b0v, v3 = acc[mi][ni][3] + b1v;
            if (EPI == 1) {
                __nv_bfloat16* C = (__nv_bfloat16*)Cv;
                *(unsigned*)(C + (size_t)row0 * ldc + col) =
                    bf2(tanh_fast(v0), tanh_fast(v1));
                *(unsigned*)(C + (size_t)(row0 + 8) * ldc + col) =
                    bf2(tanh_fast(v2), tanh_fast(v3));
            } else {
                float* C = (float*)Cv + (size_t)z * partStride;
                C[(size_t)row0 * ldc + col]           = v0;
                C[(size_t)row0 * ldc + col + 1]       = v1;
                C[(size_t)(row0 + 8) * ldc + col]     = v2;
                C[(size_t)(row0 + 8) * ldc + col + 1] = v3;
            }
        }
    }
}

// ---------------- e from partials ; softmax ; ctx ; build xt = [emb|ctx] bf16 ----------------
__global__ __launch_bounds__(256) void softmax_ctx_kernel(
    const float* __restrict__ epart,
    const float* __restrict__ enc,
    const int* __restrict__ tgt_t,
    const float* __restrict__ emb)
{
    __shared__ float e[ENCL];
    __shared__ float alpha[ENCL];
    const int b = blockIdx.x;
    const int tid = threadIdx.x;
    const int warp = tid >> 5, lane = tid & 31;

    if (tid < ENCL) {
        float s = 0.f;
        #pragma unroll
        for (int sl = 0; sl < 8; sl++) s += epart[sl * MROWS + b * ENCL + tid];
        e[tid] = s;
    }
    {
        int tg = tgt_t[b * 32];
        tg = max(0, min(tg, VOCAB - 1));
        const float* er = emb + (size_t)tg * HDIM;
        for (int j = tid; j < HDIM; j += 256)
            g_xt[b * 1024 + j] = __float2bfloat16(er[j]);
    }
    __syncthreads();
    if (warp == 0) {
        const float e0 = e[lane], e1 = e[lane + 32];
        float m = fmaxf(e0, e1);
        #pragma unroll
        for (int o = 16; o; o >>= 1) m = fmaxf(m, __shfl_xor_sync(0xffffffffu, m, o));
        const float x0 = expf(e0 - m), x1 = expf(e1 - m);
        float s = x0 + x1;
        #pragma unroll
        for (int o = 16; o; o >>= 1) s += __shfl_xor_sync(0xffffffffu, s, o);
        const float inv = 1.f / s;
        alpha[lane]      = x0 * inv;
        alpha[lane + 32] = x1 * inv;
    }
    __syncthreads();
    for (int j = tid; j < HDIM; j += 256) {
        float s = 0.f;
        #pragma unroll
        for (int l = 0; l < ENCL; l++)
            s += alpha[l] * enc[((size_t)b * ENCL + l) * HDIM + j];
        g_xt[b * 1024 + 512 + j] = __float2bfloat16(s);
    }
}

// ---------------- GRU gate combine; sums split-K parts; fp32 state + bf16 mirror ----------
__global__ void gru_kernel(const float* __restrict__ gi, const float* __restrict__ qgh,
                           const float* __restrict__ h, float* __restrict__ hn,
                           __nv_bfloat16* __restrict__ hbf_out)
{
    const int b = blockIdx.x, j = threadIdx.x;
    const int o  = b * 1536;
    const int og = b * 2048 + HDIM;
    const int GS = BATCH * 1536, QS = BATCH * 2048;
    const float gir = gi[o + j]              + gi[GS + o + j];
    const float giz = gi[o + HDIM + j]       + gi[GS + o + HDIM + j];
    const float gin = gi[o + 2 * HDIM + j]   + gi[GS + o + 2 * HDIM + j];
    const float ghr = qgh[og + j]            + qgh[QS + og + j];
    const float ghz = qgh[og + HDIM + j]     + qgh[QS + og + HDIM + j];
    const float ghn = qgh[og + 2 * HDIM + j] + qgh[QS + og + 2 * HDIM + j];
    const float r = 1.f / (1.f + expf(-(gir + ghr)));
    const float z = 1.f / (1.f + expf(-(giz + ghz)));
    const float n = tanhf(gin + r * ghn);
    const float hv = h[b * HDIM + j];
    const float out = (1.f - z) * n + z * hv;
    hn[b * HDIM + j] = out;
    hbf_out[b * HDIM + j] = __float2bfloat16(out);
}

// ---------------- in-place log-softmax over one row of 32000 ----------------
__global__ __launch_bounds__(1024) void logsoftmax_kernel(float* __restrict__ out, int t) {
    const int b = blockIdx.x;
    float* row = out + ((size_t)b * NSTEP + t) * VOCAB;
    const int tid = threadIdx.x;
    __shared__ float sm[32];

    float r[32];
    float m = -1e30f;
    #pragma unroll
    for (int i = 0; i < 32; i++) {
        const int idx = tid + (i << 10);
        r[i] = (idx < VOCAB) ? row[idx] : -1e30f;
        m = fmaxf(m, r[i]);
    }
    #pragma unroll
    for (int o = 16; o; o >>= 1) m = fmaxf(m, __shfl_xor_sync(0xffffffffu, m, o));
    if ((tid & 31) == 0) sm[tid >> 5] = m;
    __syncthreads();
    if (tid == 0) {
        float v = sm[0];
        for (int i = 1; i < 32; i++) v = fmaxf(v, sm[i]);
        sm[0] = v;
    }
    __syncthreads();
    m = sm[0];

    float s = 0.f;
    #pragma unroll
    for (int i = 0; i < 32; i++) {
        const int idx = tid + (i << 10);
        if (idx < VOCAB) s += expf(r[i] - m);
    }
    #pragma unroll
    for (int o = 16; o; o >>= 1) s += __shfl_xor_sync(0xffffffffu, s, o);
    __syncthreads();
    if ((tid & 31) == 0) sm[tid >> 5] = s;
    __syncthreads();
    if (tid == 0) {
        float v = 0.f;
        for (int i = 0; i < 32; i++) v += sm[i];
        sm[0] = v;
    }
    __syncthreads();
    const float lse = m + logf(sm[0]);

    #pragma unroll
    for (int i = 0; i < 32; i++) {
        const int idx = tid + (i << 10);
        if (idx < VOCAB) row[idx] = r[i] - lse;
    }
}

// ---------------- launch ----------------
extern "C" void kernel_launch(void* const* d_in, const int* in_sizes, int n_in,
                              void* d_out, int out_size)
{
    const float* enc       = (const float*)d_in[0];
    const float* ench      = (const float*)d_in[1];
    const int* tgt         = (const int*)d_in[2];
    const float* emb       = (const float*)d_in[3];
    const float* W1        = (const float*)d_in[4];
    const float* b1        = (const float*)d_in[5];
    const float* W2        = (const float*)d_in[6];
    const float* b2        = (const float*)d_in[7];
    const float* W3        = (const float*)d_in[8];
    const float* b3        = (const float*)d_in[9];
    const float* av        = (const float*)d_in[10];
    const float* Wih       = (const float*)d_in[11];
    const float* Whh       = (const float*)d_in[12];
    const float* bih       = (const float*)d_in[13];
    const float* bhh       = (const float*)d_in[14];
    const float* oW        = (const float*)d_in[15];
    const float* ob        = (const float*)d_in[16];
    float* out = (float*)d_out;

    float *P, *epart, *hidb, *qgh, *gi, *bqh;
    __nv_bfloat16 *A1, *a2b, *hbf, *xt, *encb, *Wp, *Wqh, *W2b, *W3b, *Wihb, *Wob;
    cudaGetSymbolAddress((void**)&P,     g_P);
    cudaGetSymbolAddress((void**)&A1,    g_A1);
    cudaGetSymbolAddress((void**)&a2b,   g_a2);
    cudaGetSymbolAddress((void**)&epart, g_epart);
    cudaGetSymbolAddress((void**)&hidb,  g_hid);
    cudaGetSymbolAddress((void**)&hbf,   g_hbf);
    cudaGetSymbolAddress((void**)&qgh,   g_qgh);
    cudaGetSymbolAddress((void**)&xt,    g_xt);
    cudaGetSymbolAddress((void**)&gi,    g_gi);
    cudaGetSymbolAddress((void**)&bqh,   g_bqh);
    cudaGetSymbolAddress((void**)&encb,  g_encb);
    cudaGetSymbolAddress((void**)&Wp,    g_Wp);
    cudaGetSymbolAddress((void**)&Wqh,   g_Wqh);
    cudaGetSymbolAddress((void**)&W2b,   g_W2);
    cudaGetSymbolAddress((void**)&W3b,   g_W3);
    cudaGetSymbolAddress((void**)&Wihb,  g_Wih);
    cudaGetSymbolAddress((void**)&Wob,   g_Wo);

    // second stream + events for logits/logsoftmax overlap (leaked: tiny host-side
    // cost per call, no device allocation; destroying mid-capture is illegal)
    cudaStream_t s2;
    cudaStreamCreateWithFlags(&s2, cudaStreamNonBlocking);
    static_assert(NSTEP >= 2, "");
    cudaEvent_t evGru[NSTEP], evLog[NSTEP];
    for (int t = 0; t < NSTEP; t++) {
        cudaEventCreateWithFlags(&evGru[t], cudaEventDisableTiming);
        cudaEventCreateWithFlags(&evLog[t], cudaEventDisableTiming);
    }

    init_misc_kernel<<<(BATCH * HDIM + 255) / 256, 256>>>(ench, b1, bhh);
    conv_all_kernel<<<(CB7 + 255) / 256, 256>>>(enc, W1, Whh, W2, W3, Wih, oW);

    // P = enc @ W1[:, :H]^T  (fp32 out, no bias)
    gemm2<0, 1><<<dim3(HDIM / 128, MROWS / 128), 256>>>(
        encb, HDIM, Wp, HDIM, nullptr, P, HDIM, 0, MROWS, HDIM, nullptr);

    for (int t = 0; t < NSTEP; t++) {
        float* hi = hidb + (t & 1) * (BATCH * HDIM);
        float* ho = hidb + ((t + 1) & 1) * (BATCH * HDIM);
        __nv_bfloat16* hbi = hbf + (t & 1) * (BATCH * HDIM);
        __nv_bfloat16* hbo = hbf + ((t + 1) & 1) * (BATCH * HDIM);

        // [q | gh] = hid @ [W1b ; Whh]^T + [b1 | bhh]   (split-K 2)
        gemm2<0, 2><<<dim3(2048 / 128, 1, 2), 256>>>(
            hbi, HDIM, Wqh, HDIM, bqh, qgh, 2048, BATCH * 2048, BATCH, HDIM, nullptr);

        // A1 = tanh(P + q)  (bf16)
        a1prep_kernel<<<MROWS * HDIM / 4 / 256, 256>>>(P, qgh);

        // a2 = tanh(A1 @ W2^T + b2)  (bf16 out)
        gemm2<1, 1><<<dim3(HDIM / 128, MROWS / 128), 256>>>(
            A1, HDIM, W2b, HDIM, b2, a2b, HDIM, 0, MROWS, HDIM, nullptr);

        // e_part = slicewise [ tanh(a2 @ W3^T + b3) . v ]
        gemm2<2, 1><<<dim3(HDIM / 128, MROWS / 128), 256>>>(
            a2b, HDIM, W3b, HDIM, b3, epart, 0, 0, MROWS, HDIM, av);

        softmax_ctx_kernel<<<BATCH, 256>>>(epart, enc, tgt + t, emb);

        // gi = xt @ Wih^T + bih   (split-K 2)
        gemm2<0, 2><<<dim3(1536 / 128, 1, 2), 256>>>(
            xt, 1024, Wihb, 1024, bih, gi, 1536, BATCH * 1536, BATCH, 1024, nullptr);

        // guard: logits(t-2) must be done before we overwrite its hidden buffer
        if (t >= 2) cudaStreamWaitEvent(0, evLog[t - 2], 0);

        gru_kernel<<<BATCH, HDIM>>>(gi, qgh, hi, ho, hbo);
        cudaEventRecord(evGru[t], 0);

        // overlapped branch: logits + log-softmax on s2
        cudaStreamWaitEvent(s2, evGru[t], 0);
        gemm2<0, 1><<<dim3(VOCAB / 128, 1), 256, 0, s2>>>(
            hbo, HDIM, Wob, HDIM, ob, out + (size_t)t * VOCAB, (size_t)NSTEP * VOCAB, 0,
            BATCH, HDIM, nullptr);
        logsoftmax_kernel<<<BATCH, 1024, 0, s2>>>(out, t);
        cudaEventRecord(evLog[t], s2);
    }

    // rejoin: main stream waits for the last overlapped branch
    cudaStreamWaitEvent(0, evLog[NSTEP - 1], 0);
}

// round 11
// speedup vs baseline: 1.9048x; 1.1639x over previous
#include <cuda_runtime.h>
#include <cuda_bf16.h>
#include <math.h>

#define VOCAB 32000
#define HDIM  512
#define BATCH 128
#define ENCL  64
#define NSTEP 31
#define MROWS (BATCH * ENCL)   // 8192
#define STAGES 4

// ---------------- scratch (static device globals; no allocation) ----------------
__device__ float          g_P[MROWS * HDIM];        // enc @ W1a^T (fp32, time-invariant)
__device__ __nv_bfloat16  g_A1[MROWS * HDIM];       // tanh(P + q)
__device__ __nv_bfloat16  g_a2[MROWS * HDIM];
__device__ float          g_epart[8 * MROWS];       // per-slice partial dots (a3 . v)
__device__ float          g_hid[2][BATCH * HDIM];   // fp32 recurrence (ping-pong)
__device__ __nv_bfloat16  g_hbf[2][BATCH * HDIM];   // bf16 hidden (ping-pong, overlap-safe)
__device__ float          g_qgh[2 * BATCH * 2048];  // split-K parts of [q | gh]
__device__ __nv_bfloat16  g_xt[BATCH * 1024];       // [emb[tgt] | ctx]  bf16
__device__ float          g_gi[2 * BATCH * 1536];   // split-K parts of gi
__device__ float          g_bqh[2048];              // [b1 | bhh]

// bf16 operand copies (converted once per replay)
__device__ __nv_bfloat16 g_encb[MROWS * HDIM];
__device__ __nv_bfloat16 g_Wp  [HDIM * HDIM];
__device__ __nv_bfloat16 g_Wqh [2048 * HDIM];
__device__ __nv_bfloat16 g_W2  [HDIM * HDIM];
__device__ __nv_bfloat16 g_W3  [HDIM * HDIM];
__device__ __nv_bfloat16 g_Wih [1536 * 1024];
__device__ __nv_bfloat16 g_Wo  [VOCAB * HDIM];

// ---------------- helpers ----------------
__device__ __forceinline__ unsigned bf2(float lo, float hi) {
    unsigned u;
    asm("cvt.rn.bf16x2.f32 %0, %1, %2;" : "=r"(u) : "f"(hi), "f"(lo));
    return u;
}
__device__ __forceinline__ float tanh_fast(float x) {
    float y;
    asm("tanh.approx.f32 %0, %1;" : "=f"(y) : "f"(x));
    return y;
}
__device__ __forceinline__ void mma_bf16(float c[4], const unsigned a[4], const unsigned b[2]) {
    asm volatile(
        "mma.sync.aligned.m16n8k16.row.col.f32.bf16.bf16.f32 "
        "{%0,%1,%2,%3}, {%4,%5,%6,%7}, {%8,%9}, {%0,%1,%2,%3};\n"
        : "+f"(c[0]), "+f"(c[1]), "+f"(c[2]), "+f"(c[3])
        : "r"(a[0]), "r"(a[1]), "r"(a[2]), "r"(a[3]), "r"(b[0]), "r"(b[1]));
}
__device__ __forceinline__ void ldsm4(unsigned& r0, unsigned& r1, unsigned& r2, unsigned& r3,
                                      unsigned addr) {
    asm volatile("ldmatrix.sync.aligned.m8n8.x4.shared.b16 {%0,%1,%2,%3}, [%4];"
                 : "=r"(r0), "=r"(r1), "=r"(r2), "=r"(r3) : "r"(addr));
}
__device__ __forceinline__ void cpasync16(unsigned dst, const void* src) {
    asm volatile("cp.async.cg.shared.global [%0], [%1], 16;\n" :: "r"(dst), "l"(src));
}
// PDL: wait for the producer kernel's completion before touching its output
__device__ __forceinline__ void gdep_sync() {
#if __CUDA_ARCH__ >= 900
    cudaGridDependencySynchronize();
#endif
}

// ---------------- unified weight/operand conversion (fp32 -> bf16) ----------------
#define N_ENC (MROWS * HDIM / 4)
#define N_SQ  (HDIM * HDIM / 4)
#define N_WQ2 (1536 * HDIM / 4)
#define N_WIH (1536 * 1024 / 4)
#define N_WO  (VOCAB * HDIM / 4)
#define CB0 (N_ENC)
#define CB1 (CB0 + N_SQ)
#define CB2 (CB1 + N_SQ)
#define CB3 (CB2 + N_WQ2)
#define CB4 (CB3 + N_SQ)
#define CB5 (CB4 + N_SQ)
#define CB6 (CB5 + N_WIH)
#define CB7 (CB6 + N_WO)

__device__ __forceinline__ void copy4(__nv_bfloat16* dst, const float* src) {
    float4 v = *(const float4*)src;
    uint2 o;
    o.x = bf2(v.x, v.y);
    o.y = bf2(v.z, v.w);
    *(uint2*)dst = o;
}

__global__ void conv_all_kernel(const float* __restrict__ enc,
                                const float* __restrict__ W1,
                                const float* __restrict__ Whh,
                                const float* __restrict__ W2,
                                const float* __restrict__ W3,
                                const float* __restrict__ Wih,
                                const float* __restrict__ Wo) {
    const int i = blockIdx.x * blockDim.x + threadIdx.x;
    if (i >= CB7) return;
    if (i < CB0) {
        copy4(g_encb + i * 4, enc + i * 4);
    } else if (i < CB1) {
        const int l = i - CB0, r = l >> 7, c = (l & 127) * 4;
        copy4(g_Wp + l * 4, W1 + (size_t)r * 1024 + c);
    } else if (i < CB2) {
        const int l = i - CB1, r = l >> 7, c = (l & 127) * 4;
        copy4(g_Wqh + l * 4, W1 + (size_t)r * 1024 + 512 + c);
    } else if (i < CB3) {
        const int l = i - CB2;
        copy4(g_Wqh + HDIM * HDIM + l * 4, Whh + l * 4);
    } else if (i < CB4) {
        const int l = i - CB3;
        copy4(g_W2 + l * 4, W2 + l * 4);
    } else if (i < CB5) {
        const int l = i - CB4;
        copy4(g_W3 + l * 4, W3 + l * 4);
    } else if (i < CB6) {
        const int l = i - CB5;
        copy4(g_Wih + l * 4, Wih + l * 4);
    } else {
        const int l = i - CB6;
        copy4(g_Wo + l * 4, Wo + l * 4);
    }
}

__global__ void init_misc_kernel(const float* __restrict__ ench,
                                 const float* __restrict__ b1,
                                 const float* __restrict__ bhh) {
    const int i = blockIdx.x * blockDim.x + threadIdx.x;
    if (i < BATCH * HDIM) {
        const float h = ench[i];
        g_hid[0][i] = h;
        g_hbf[0][i] = __float2bfloat16(h);
    }
    if (i < 2048) g_bqh[i] = (i < HDIM) ? b1[i] : bhh[i - HDIM];
}

// ---------------- A1 = tanh(P + q0 + q1)  (bf16; sums split-K q parts) ----------------
__global__ __launch_bounds__(256) void a1prep_kernel(const float* __restrict__ P,
                                                     const float* __restrict__ qgh) {
    const int i4 = (blockIdx.x * blockDim.x + threadIdx.x) * 4;
    const int row = i4 >> 9, k = i4 & 511;
    gdep_sync();
    float4 p = *(const float4*)(P + i4);
    const float* q0 = qgh + ((row >> 6) << 11) + k;
    const float* q1 = q0 + BATCH * 2048;
    uint2 o;
    o.x = bf2(tanh_fast(p.x + q0[0] + q1[0]), tanh_fast(p.y + q0[1] + q1[1]));
    o.y = bf2(tanh_fast(p.z + q0[2] + q1[2]), tanh_fast(p.w + q0[3] + q1[3]));
    *(uint2*)(g_A1 + i4) = o;
}

// ---------------- GEMM: cp.async 4-stage, bf16 in, ldmatrix + mma, optional split-K ------
template <int EPI, int SPLIT>
__global__ __launch_bounds__(256) void gemm2(
    const __nv_bfloat16* __restrict__ A, int lda,
    const __nv_bfloat16* __restrict__ W, int ldw,
    const float* __restrict__ bias,
    void* __restrict__ Cv, size_t ldc, size_t partStride,
    int M, int K,
    const float* __restrict__ v)
{
    __shared__ __align__(16) unsigned char sm[STAGES][2][128 * 48];

    const int tid    = threadIdx.x;
    const int warpid = tid >> 5, lane = tid & 31;
    const int wm = warpid >> 1, wn = warpid & 1;
    const int gid = lane >> 2, tidg = lane & 3;
    const int bm0 = blockIdx.y * 128, bn0 = blockIdx.x * 128;
    const int z   = (SPLIT > 1) ? blockIdx.z : 0;
    const int kbase = z * (K / SPLIT);
    const int frow = tid >> 1;
    const int half = tid & 1;

    const unsigned sbase = (unsigned)__cvta_generic_to_shared(&sm[0][0][0]);
    unsigned aoff[2], boff[4];
    #pragma unroll
    for (int mi = 0; mi < 2; mi++)
        aoff[mi] = (unsigned)((wm * 32 + mi * 16 + (lane & 15)) * 48 + (lane >> 4) * 16);
    #pragma unroll
    for (int p = 0; p < 4; p++)
        boff[p] = (unsigned)(6144 +
            (wn * 64 + p * 16 + ((lane >> 4) << 3) + (lane & 7)) * 48 + ((lane >> 3) & 1) * 16);

    float acc[2][8][4];
    #pragma unroll
    for (int mi = 0; mi < 2; mi++)
        #pragma unroll
        for (int ni = 0; ni < 8; ni++)
            #pragma unroll
            for (int qq = 0; qq < 4; qq++) acc[mi][ni][qq] = 0.f;

    const int nk = (K / SPLIT) >> 4;
    const unsigned dstA = frow * 48 + half * 16;

    auto issue = [&](int kt) {
        const unsigned st = (unsigned)(kt & (STAGES - 1)) * 12288;
        cpasync16(sbase + st + dstA,
                  A + (size_t)(bm0 + frow) * lda + kbase + (kt << 4) + half * 8);
        cpasync16(sbase + st + 6144 + dstA,
                  W + (size_t)(bn0 + frow) * ldw + kbase + (kt << 4) + half * 8);
        asm volatile("cp.async.commit_group;\n");
    };

    gdep_sync();   // producer output must be visible before first cp.async

    #pragma unroll
    for (int s = 0; s < STAGES - 1; s++) issue(s);

    for (int kt = 0; kt < nk; kt++) {
        asm volatile("cp.async.wait_group %0;\n" :: "n"(STAGES - 2));
        __syncthreads();
        if (kt + STAGES - 1 < nk) issue(kt + STAGES - 1);
        else asm volatile("cp.async.commit_group;\n");

        const unsigned sb = sbase + (unsigned)(kt & (STAGES - 1)) * 12288;
        unsigned af[2][4], bfr[8][2];
        #pragma unroll
        for (int mi = 0; mi < 2; mi++)
            ldsm4(af[mi][0], af[mi][1], af[mi][2], af[mi][3], sb + aoff[mi]);
        #pragma unroll
        for (int p = 0; p < 4; p++) {
            unsigned r0, r1, r2, r3;
            ldsm4(r0, r1, r2, r3, sb + boff[p]);
            bfr[2 * p][0] = r0;     bfr[2 * p][1] = r1;
            bfr[2 * p + 1][0] = r2; bfr[2 * p + 1][1] = r3;
        }
        #pragma unroll
        for (int mi = 0; mi < 2; mi++)
            #pragma unroll
            for (int ni = 0; ni < 8; ni++)
                mma_bf16(acc[mi][ni], af[mi], bfr[ni]);
    }

    if (EPI == 2) {
        float* C = (float*)Cv;
        float es[2][2] = {{0.f, 0.f}, {0.f, 0.f}};
        #pragma unroll
        for (int mi = 0; mi < 2; mi++) {
            #pragma unroll
            for (int ni = 0; ni < 8; ni++) {
                const int col = bn0 + wn * 64 + ni * 8 + tidg * 2;
                const float v0 = v[col], v1 = v[col + 1];
                const float b0 = bias[col], b1 = bias[col + 1];
                es[mi][0] += tanh_fast(acc[mi][ni][0] + b0) * v0
                           + tanh_fast(acc[mi][ni][1] + b1) * v1;
                es[mi][1] += tanh_fast(acc[mi][ni][2] + b0) * v0
                           + tanh_fast(acc[mi][ni][3] + b1) * v1;
            }
        }
        const int slice = blockIdx.x * 2 + wn;
        #pragma unroll
        for (int mi = 0; mi < 2; mi++) {
            #pragma unroll
            for (int hh = 0; hh < 2; hh++) {
                float s = es[mi][hh];
                s += __shfl_xor_sync(0xffffffffu, s, 1);
                s += __shfl_xor_sync(0xffffffffu, s, 2);
                if (tidg == 0) {
                    const int row = bm0 + wm * 32 + mi * 16 + gid + hh * 8;
                    C[(size_t)slice * M + row] = s;
                }
            }
        }
        return;
    }

    const bool addBias = (bias != nullptr) && (z == 0);
    #pragma unroll
    for (int mi = 0; mi < 2; mi++) {
        #pragma unroll
        for (int ni = 0; ni < 8; ni++) {
            const int col = bn0 + wn * 64 + ni * 8 + tidg * 2;
            const float b0v = addBias ? bias[col] : 0.f;
            const float b1v = addBias ? bias[col + 1] : 0.f;
            const int row0 = bm0 + wm * 32 + mi * 16 + gid;
            float v0 = acc[mi][ni][0] + b0v, v1 = acc[mi][ni][1] + b1v;
            float v2 = acc[mi][ni][2] + b0v, v3 = acc[mi][ni][3] + b1v;
            if (EPI == 1) {
                __nv_bfloat16* C = (__nv_bfloat16*)Cv;
                *(unsigned*)(C + (size_t)row0 * ldc + col) =
                    bf2(tanh_fast(v0), tanh_fast(v1));
                *(unsigned*)(C + (size_t)(row0 + 8) * ldc + col) =
                    bf2(tanh_fast(v2), tanh_fast(v3));
            } else {
                float* C = (float*)Cv + (size_t)z * partStride;
                C[(size_t)row0 * ldc + col]           = v0;
                C[(size_t)row0 * ldc + col + 1]       = v1;
                C[(size_t)(row0 + 8) * ldc + col]     = v2;
                C[(size_t)(row0 + 8) * ldc + col + 1] = v3;
            }
        }
    }
}

// ---------------- e from partials ; softmax ; ctx (bf16 enc) ; xt = [emb|ctx] bf16 --------
__global__ __launch_bounds__(256) void softmax_ctx_kernel(
    const float* __restrict__ epart,
    const __nv_bfloat16* __restrict__ encb,
    const int* __restrict__ tgt_t,
    const float* __restrict__ emb)
{
    __shared__ float e[ENCL];
    __shared__ float alpha[ENCL];
    const int b = blockIdx.x;
    const int tid = threadIdx.x;
    const int warp = tid >> 5, lane = tid & 31;

    gdep_sync();

    if (tid < ENCL) {
        float s = 0.f;
        #pragma unroll
        for (int sl = 0; sl < 8; sl++) s += epart[sl * MROWS + b * ENCL + tid];
        e[tid] = s;
    }
    {
        int tg = tgt_t[b * 32];
        tg = max(0, min(tg, VOCAB - 1));
        const float* er = emb + (size_t)tg * HDIM;
        for (int j = tid; j < HDIM; j += 256)
            g_xt[b * 1024 + j] = __float2bfloat16(er[j]);
    }
    __syncthreads();
    if (warp == 0) {
        const float e0 = e[lane], e1 = e[lane + 32];
        float m = fmaxf(e0, e1);
        #pragma unroll
        for (int o = 16; o; o >>= 1) m = fmaxf(m, __shfl_xor_sync(0xffffffffu, m, o));
        const float x0 = expf(e0 - m), x1 = expf(e1 - m);
        float s = x0 + x1;
        #pragma unroll
        for (int o = 16; o; o >>= 1) s += __shfl_xor_sync(0xffffffffu, s, o);
        const float inv = 1.f / s;
        alpha[lane]      = x0 * inv;
        alpha[lane + 32] = x1 * inv;
    }
    __syncthreads();
    for (int j = tid * 2; j < HDIM; j += 512) {
        float s0 = 0.f, s1 = 0.f;
        #pragma unroll
        for (int l = 0; l < ENCL; l++) {
            const unsigned pk = *(const unsigned*)(encb + ((size_t)b * ENCL + l) * HDIM + j);
            const float a = alpha[l];
            s0 += a * __bfloat162float(*(const __nv_bfloat16*)&pk);
            s1 += a * __bfloat162float(*((const __nv_bfloat16*)&pk + 1));
        }
        *(unsigned*)(g_xt + b * 1024 + 512 + j) = bf2(s0, s1);
    }
}

// ---------------- GRU gate combine; sums split-K parts; fp32 state + bf16 mirror ----------
__global__ void gru_kernel(const float* __restrict__ gi, const float* __restrict__ qgh,
                           const float* __restrict__ h, float* __restrict__ hn,
                           __nv_bfloat16* __restrict__ hbf_out)
{
    const int b = blockIdx.x, j = threadIdx.x;
    const int o  = b * 1536;
    const int og = b * 2048 + HDIM;
    const int GS = BATCH * 1536, QS = BATCH * 2048;
    gdep_sync();
    const float gir = gi[o + j]              + gi[GS + o + j];
    const float giz = gi[o + HDIM + j]       + gi[GS + o + HDIM + j];
    const float gin = gi[o + 2 * HDIM + j]   + gi[GS + o + 2 * HDIM + j];
    const float ghr = qgh[og + j]            + qgh[QS + og + j];
    const float ghz = qgh[og + HDIM + j]     + qgh[QS + og + HDIM + j];
    const float ghn = qgh[og + 2 * HDIM + j] + qgh[QS + og + 2 * HDIM + j];
    const float r = 1.f / (1.f + expf(-(gir + ghr)));
    const float z = 1.f / (1.f + expf(-(giz + ghz)));
    const float n = tanhf(gin + r * ghn);
    const float hv = h[b * HDIM + j];
    const float out = (1.f - z) * n + z * hv;
    hn[b * HDIM + j] = out;
    hbf_out[b * HDIM + j] = __float2bfloat16(out);
}

// ---------------- in-place log-softmax over one row of 32000 ----------------
__global__ __launch_bounds__(1024) void logsoftmax_kernel(float* __restrict__ out, int t) {
    const int b = blockIdx.x;
    float* row = out + ((size_t)b * NSTEP + t) * VOCAB;
    const int tid = threadIdx.x;
    __shared__ float sm[32];

    gdep_sync();

    float r[32];
    float m = -1e30f;
    #pragma unroll
    for (int i = 0; i < 32; i++) {
        const int idx = tid + (i << 10);
        r[i] = (idx < VOCAB) ? row[idx] : -1e30f;
        m = fmaxf(m, r[i]);
    }
    #pragma unroll
    for (int o = 16; o; o >>= 1) m = fmaxf(m, __shfl_xor_sync(0xffffffffu, m, o));
    if ((tid & 31) == 0) sm[tid >> 5] = m;
    __syncthreads();
    if (tid == 0) {
        float v = sm[0];
        for (int i = 1; i < 32; i++) v = fmaxf(v, sm[i]);
        sm[0] = v;
    }
    __syncthreads();
    m = sm[0];

    float s = 0.f;
    #pragma unroll
    for (int i = 0; i < 32; i++) {
        const int idx = tid + (i << 10);
        if (idx < VOCAB) s += expf(r[i] - m);
    }
    #pragma unroll
    for (int o = 16; o; o >>= 1) s += __shfl_xor_sync(0xffffffffu, s, o);
    __syncthreads();
    if ((tid & 31) == 0) sm[tid >> 5] = s;
    __syncthreads();
    if (tid == 0) {
        float v = 0.f;
        for (int i = 0; i < 32; i++) v += sm[i];
        sm[0] = v;
    }
    __syncthreads();
    const float lse = m + logf(sm[0]);

    #pragma unroll
    for (int i = 0; i < 32; i++) {
        const int idx = tid + (i << 10);
        if (idx < VOCAB) row[idx] = r[i] - lse;
    }
}

// ---------------- PDL launch helper ----------------
template <typename F, typename... Args>
static inline void pdl(F f, dim3 grid, dim3 block, cudaStream_t st, Args... args) {
    cudaLaunchConfig_t cfg = {};
    cfg.gridDim = grid;
    cfg.blockDim = block;
    cfg.stream = st;
    cudaLaunchAttribute attr;
    attr.id = cudaLaunchAttributeProgrammaticStreamSerialization;
    attr.val.programmaticStreamSerializationAllowed = 1;
    cfg.attrs = &attr;
    cfg.numAttrs = 1;
    cudaLaunchKernelEx(&cfg, f, args...);
}

// ---------------- launch ----------------
extern "C" void kernel_launch(void* const* d_in, const int* in_sizes, int n_in,
                              void* d_out, int out_size)
{
    const float* enc       = (const float*)d_in[0];
    const float* ench      = (const float*)d_in[1];
    const int* tgt         = (const int*)d_in[2];
    const float* emb       = (const float*)d_in[3];
    const float* W1        = (const float*)d_in[4];
    const float* b1        = (const float*)d_in[5];
    const float* W2        = (const float*)d_in[6];
    const float* b2        = (const float*)d_in[7];
    const float* W3        = (const float*)d_in[8];
    const float* b3        = (const float*)d_in[9];
    const float* av        = (const float*)d_in[10];
    const float* Wih       = (const float*)d_in[11];
    const float* Whh       = (const float*)d_in[12];
    const float* bih       = (const float*)d_in[13];
    const float* bhh       = (const float*)d_in[14];
    const float* oW        = (const float*)d_in[15];
    const float* ob        = (const float*)d_in[16];
    float* out = (float*)d_out;

    float *P, *epart, *hidb, *qgh, *gi, *bqh;
    __nv_bfloat16 *A1, *a2b, *hbf, *xt, *encb, *Wp, *Wqh, *W2b, *W3b, *Wihb, *Wob;
    cudaGetSymbolAddress((void**)&P,     g_P);
    cudaGetSymbolAddress((void**)&A1,    g_A1);
    cudaGetSymbolAddress((void**)&a2b,   g_a2);
    cudaGetSymbolAddress((void**)&epart, g_epart);
    cudaGetSymbolAddress((void**)&hidb,  g_hid);
    cudaGetSymbolAddress((void**)&hbf,   g_hbf);
    cudaGetSymbolAddress((void**)&qgh,   g_qgh);
    cudaGetSymbolAddress((void**)&xt,    g_xt);
    cudaGetSymbolAddress((void**)&gi,    g_gi);
    cudaGetSymbolAddress((void**)&bqh,   g_bqh);
    cudaGetSymbolAddress((void**)&encb,  g_encb);
    cudaGetSymbolAddress((void**)&Wp,    g_Wp);
    cudaGetSymbolAddress((void**)&Wqh,   g_Wqh);
    cudaGetSymbolAddress((void**)&W2b,   g_W2);
    cudaGetSymbolAddress((void**)&W3b,   g_W3);
    cudaGetSymbolAddress((void**)&Wihb,  g_Wih);
    cudaGetSymbolAddress((void**)&Wob,   g_Wo);

    // second stream + events for logits/logsoftmax overlap (leaked by design:
    // no device allocation; destroying mid-capture is illegal)
    cudaStream_t s2;
    cudaStreamCreateWithFlags(&s2, cudaStreamNonBlocking);
    cudaEvent_t evGru[NSTEP], evLog[NSTEP];
    for (int t = 0; t < NSTEP; t++) {
        cudaEventCreateWithFlags(&evGru[t], cudaEventDisableTiming);
        cudaEventCreateWithFlags(&evLog[t], cudaEventDisableTiming);
    }

    init_misc_kernel<<<(BATCH * HDIM + 255) / 256, 256>>>(ench, b1, bhh);
    conv_all_kernel<<<(CB7 + 255) / 256, 256>>>(enc, W1, Whh, W2, W3, Wih, oW);

    // P = enc @ W1[:, :H]^T  (fp32 out, no bias)
    pdl(&gemm2<0, 1>, dim3(HDIM / 128, MROWS / 128), dim3(256), (cudaStream_t)0,
        (const __nv_bfloat16*)encb, (int)HDIM, (const __nv_bfloat16*)Wp, (int)HDIM,
        (const float*)nullptr, (void*)P, (size_t)HDIM, (size_t)0, (int)MROWS, (int)HDIM,
        (const float*)nullptr);

    for (int t = 0; t < NSTEP; t++) {
        float* hi = hidb + (t & 1) * (BATCH * HDIM);
        float* ho = hidb + ((t + 1) & 1) * (BATCH * HDIM);
        __nv_bfloat16* hbi = hbf + (t & 1) * (BATCH * HDIM);
        __nv_bfloat16* hbo = hbf + ((t + 1) & 1) * (BATCH * HDIM);

        // [q | gh] = hid @ [W1b ; Whh]^T + [b1 | bhh]   (split-K 2)
        pdl(&gemm2<0, 2>, dim3(2048 / 128, 1, 2), dim3(256), (cudaStream_t)0,
            (const __nv_bfloat16*)hbi, (int)HDIM, (const __nv_bfloat16*)Wqh, (int)HDIM,
            (const float*)bqh, (void*)qgh, (size_t)2048, (size_t)(BATCH * 2048),
            (int)BATCH, (int)HDIM, (const float*)nullptr);

        // A1 = tanh(P + q)  (bf16)
        pdl(&a1prep_kernel, dim3(MROWS * HDIM / 4 / 256), dim3(256), (cudaStream_t)0,
            (const float*)P, (const float*)qgh);

        // a2 = tanh(A1 @ W2^T + b2)  (bf16 out)
        pdl(&gemm2<1, 1>, dim3(HDIM / 128, MROWS / 128), dim3(256), (cudaStream_t)0,
            (const __nv_bfloat16*)A1, (int)HDIM, (const __nv_bfloat16*)W2b, (int)HDIM,
            (const float*)b2, (void*)a2b, (size_t)HDIM, (size_t)0,
            (int)MROWS, (int)HDIM, (const float*)nullptr);

        // e_part = slicewise [ tanh(a2 @ W3^T + b3) . v ]
        pdl(&gemm2<2, 1>, dim3(HDIM / 128, MROWS / 128), dim3(256), (cudaStream_t)0,
            (const __nv_bfloat16*)a2b, (int)HDIM, (const __nv_bfloat16*)W3b, (int)HDIM,
            (const float*)b3, (void*)epart, (size_t)0, (size_t)0,
            (int)MROWS, (int)HDIM, (const float*)av);

        pdl(&softmax_ctx_kernel, dim3(BATCH), dim3(256), (cudaStream_t)0,
            (const float*)epart, (const __nv_bfloat16*)encb,
            (const int*)(tgt + t), (const float*)emb);

        // gi = xt @ Wih^T + bih   (split-K 2)
        pdl(&gemm2<0, 2>, dim3(1536 / 128, 1, 2), dim3(256), (cudaStream_t)0,
            (const __nv_bfloat16*)xt, (int)1024, (const __nv_bfloat16*)Wihb, (int)1024,
            (const float*)bih, (void*)gi, (size_t)1536, (size_t)(BATCH * 1536),
            (int)BATCH, (int)1024, (const float*)nullptr);

        // guard: logits(t-2) must be done before we overwrite its hidden buffer
        if (t >= 2) cudaStreamWaitEvent(0, evLog[t - 2], 0);

        pdl(&gru_kernel, dim3(BATCH), dim3(HDIM), (cudaStream_t)0,
            (const float*)gi, (const float*)qgh, (const float*)hi, (float*)ho,
            (__nv_bfloat16*)hbo);
        cudaEventRecord(evGru[t], 0);

        // overlapped branch: logits + log-softmax on s2
        cudaStreamWaitEvent(s2, evGru[t], 0);
        pdl(&gemm2<0, 1>, dim3(VOCAB / 128, 1), dim3(256), s2,
            (const __nv_bfloat16*)hbo, (int)HDIM, (const __nv_bfloat16*)Wob, (int)HDIM,
            (const float*)ob, (void*)(out + (size_t)t * VOCAB),
            (size_t)((size_t)NSTEP * VOCAB), (size_t)0,
            (int)BATCH, (int)HDIM, (const float*)nullptr);
        pdl(&logsoftmax_kernel, dim3(BATCH), dim3(1024), s2, (float*)out, (int)t);
        cudaEventRecord(evLog[t], s2);
    }

    // rejoin: main stream waits for the last overlapped branch
    cudaStreamWaitEvent(0, evLog[NSTEP - 1], 0);
}

// round 14
// speedup vs baseline: 1.9190x; 1.0074x over previous
#include <cuda_runtime.h>
#include <cuda_bf16.h>
#include <math.h>

#define VOCAB 32000
#define HDIM  512
#define BATCH 128
#define ENCL  64
#define NSTEP 31
#define MROWS (BATCH * ENCL)   // 8192
#define STAGES 4
#define W8SCALE 32.0f
#define W8INV   0.03125f

// ---------------- scratch (static device globals; no allocation) ----------------
__device__ float          g_P[MROWS * HDIM];        // enc @ W1a^T (fp32, time-invariant)
__device__ unsigned char  g_A1f[MROWS * HDIM];      // tanh(P + q)  (e4m3)
__device__ unsigned char  g_a2f[MROWS * HDIM];      // tanh(a1 @ W2^T + b2)  (e4m3)
__device__ float          g_epart[8 * MROWS];       // per-slice partial dots (a3 . v)
__device__ float          g_hid[2][BATCH * HDIM];   // fp32 recurrence (ping-pong)
__device__ __nv_bfloat16  g_hbf[2][BATCH * HDIM];   // bf16 hidden (ping-pong)
__device__ float          g_qgh[2 * BATCH * 2048];  // split-K parts of [q | gh]
__device__ __nv_bfloat16  g_xt[BATCH * 1024];       // [emb[tgt] | ctx]  bf16
__device__ float          g_gi[2 * BATCH * 1536];   // split-K parts of gi
__device__ float          g_bqh[2048];              // [b1 | bhh]

// weight copies (converted once per replay)
__device__ __nv_bfloat16 g_encb[MROWS * HDIM];
__device__ __nv_bfloat16 g_Wp  [HDIM * HDIM];
__device__ __nv_bfloat16 g_Wqh [2048 * HDIM];
__device__ unsigned char g_W2f [HDIM * HDIM];       // e4m3, pre-scaled x32
__device__ unsigned char g_W3f [HDIM * HDIM];       // e4m3, pre-scaled x32
__device__ __nv_bfloat16 g_Wih [1536 * 1024];
__device__ __nv_bfloat16 g_Wo  [VOCAB * HDIM];

// ---------------- helpers ----------------
__device__ __forceinline__ unsigned bf2(float lo, float hi) {
    unsigned u;
    asm("cvt.rn.bf16x2.f32 %0, %1, %2;" : "=r"(u) : "f"(hi), "f"(lo));
    return u;
}
__device__ __forceinline__ unsigned short f8x2(float lo, float hi) {
    unsigned short u;
    asm("cvt.rn.satfinite.e4m3x2.f32 %0, %1, %2;" : "=h"(u) : "f"(hi), "f"(lo));
    return u;
}
__device__ __forceinline__ float tanh_fast(float x) {
    float y;
    asm("tanh.approx.f32 %0, %1;" : "=f"(y) : "f"(x));
    return y;
}
__device__ __forceinline__ void mma_bf16(float c[4], const unsigned a[4], const unsigned b[2]) {
    asm volatile(
        "mma.sync.aligned.m16n8k16.row.col.f32.bf16.bf16.f32 "
        "{%0,%1,%2,%3}, {%4,%5,%6,%7}, {%8,%9}, {%0,%1,%2,%3};\n"
        : "+f"(c[0]), "+f"(c[1]), "+f"(c[2]), "+f"(c[3])
        : "r"(a[0]), "r"(a[1]), "r"(a[2]), "r"(a[3]), "r"(b[0]), "r"(b[1]));
}
__device__ __forceinline__ void mma_fp8(float c[4], const unsigned a[4], const unsigned b[2]) {
    asm volatile(
        "mma.sync.aligned.m16n8k32.row.col.f32.e4m3.e4m3.f32 "
        "{%0,%1,%2,%3}, {%4,%5,%6,%7}, {%8,%9}, {%0,%1,%2,%3};\n"
        : "+f"(c[0]), "+f"(c[1]), "+f"(c[2]), "+f"(c[3])
        : "r"(a[0]), "r"(a[1]), "r"(a[2]), "r"(a[3]), "r"(b[0]), "r"(b[1]));
}
__device__ __forceinline__ void ldsm4(unsigned& r0, unsigned& r1, unsigned& r2, unsigned& r3,
                                      unsigned addr) {
    asm volatile("ldmatrix.sync.aligned.m8n8.x4.shared.b16 {%0,%1,%2,%3}, [%4];"
                 : "=r"(r0), "=r"(r1), "=r"(r2), "=r"(r3) : "r"(addr));
}
__device__ __forceinline__ void cpasync16(unsigned dst, const void* src) {
    asm volatile("cp.async.cg.shared.global [%0], [%1], 16;\n" :: "r"(dst), "l"(src));
}
__device__ __forceinline__ void gdep_sync() {
#if __CUDA_ARCH__ >= 900
    cudaGridDependencySynchronize();
#endif
}

// ---------------- unified weight/operand conversion ----------------
#define N_ENC (MROWS * HDIM / 4)
#define N_SQ  (HDIM * HDIM / 4)
#define N_WQ2 (1536 * HDIM / 4)
#define N_WIH (1536 * 1024 / 4)
#define N_WO  (VOCAB * HDIM / 4)
#define CB0 (N_ENC)
#define CB1 (CB0 + N_SQ)
#define CB2 (CB1 + N_SQ)
#define CB3 (CB2 + N_WQ2)
#define CB4 (CB3 + N_SQ)
#define CB5 (CB4 + N_SQ)
#define CB6 (CB5 + N_WIH)
#define CB7 (CB6 + N_WO)

__device__ __forceinline__ void copy4(__nv_bfloat16* dst, const float* src) {
    float4 v = *(const float4*)src;
    uint2 o;
    o.x = bf2(v.x, v.y);
    o.y = bf2(v.z, v.w);
    *(uint2*)dst = o;
}
__device__ __forceinline__ void copy4_f8(unsigned char* dst, const float* src) {
    float4 v = *(const float4*)src;
    const unsigned lo = f8x2(v.x * W8SCALE, v.y * W8SCALE);
    const unsigned hi = f8x2(v.z * W8SCALE, v.w * W8SCALE);
    *(unsigned*)dst = lo | (hi << 16);
}

__global__ void conv_all_kernel(const float* __restrict__ enc,
                                const float* __restrict__ W1,
                                const float* __restrict__ Whh,
                                const float* __restrict__ W2,
                                const float* __restrict__ W3,
                                const float* __restrict__ Wih,
                                const float* __restrict__ Wo) {
    const int i = blockIdx.x * blockDim.x + threadIdx.x;
    if (i >= CB7) return;
    if (i < CB0) {
        copy4(g_encb + i * 4, enc + i * 4);
    } else if (i < CB1) {
        const int l = i - CB0, r = l >> 7, c = (l & 127) * 4;
        copy4(g_Wp + l * 4, W1 + (size_t)r * 1024 + c);
    } else if (i < CB2) {
        const int l = i - CB1, r = l >> 7, c = (l & 127) * 4;
        copy4(g_Wqh + l * 4, W1 + (size_t)r * 1024 + 512 + c);
    } else if (i < CB3) {
        const int l = i - CB2;
        copy4(g_Wqh + HDIM * HDIM + l * 4, Whh + l * 4);
    } else if (i < CB4) {
        const int l = i - CB3;
        copy4_f8(g_W2f + l * 4, W2 + l * 4);
    } else if (i < CB5) {
        const int l = i - CB4;
        copy4_f8(g_W3f + l * 4, W3 + l * 4);
    } else if (i < CB6) {
        const int l = i - CB5;
        copy4(g_Wih + l * 4, Wih + l * 4);
    } else {
        const int l = i - CB6;
        copy4(g_Wo + l * 4, Wo + l * 4);
    }
}

__global__ void init_misc_kernel(const float* __restrict__ ench,
                                 const float* __restrict__ b1,
                                 const float* __restrict__ bhh) {
    const int i = blockIdx.x * blockDim.x + threadIdx.x;
    if (i < BATCH * HDIM) {
        const float h = ench[i];
        g_hid[0][i] = h;
        g_hbf[0][i] = __float2bfloat16(h);
    }
    if (i < 2048) g_bqh[i] = (i < HDIM) ? b1[i] : bhh[i - HDIM];
}

// ---------------- A1 = tanh(P + q0 + q1)  (e4m3; sums split-K q parts) ----------------
__global__ __launch_bounds__(256) void a1prep_kernel(const float* __restrict__ P,
                                                     const float* __restrict__ qgh) {
    const int i4 = (blockIdx.x * blockDim.x + threadIdx.x) * 4;
    const int row = i4 >> 9, k = i4 & 511;
    gdep_sync();
    float4 p = *(const float4*)(P + i4);
    const float* q0 = qgh + ((row >> 6) << 11) + k;
    const float* q1 = q0 + BATCH * 2048;
    const unsigned lo = f8x2(tanh_fast(p.x + q0[0] + q1[0]), tanh_fast(p.y + q0[1] + q1[1]));
    const unsigned hi = f8x2(tanh_fast(p.z + q0[2] + q1[2]), tanh_fast(p.w + q0[3] + q1[3]));
    *(unsigned*)(g_A1f + i4) = lo | (hi << 16);
}

// ---------------- bf16 GEMM (cp.async 4-stage, ldmatrix + mma, optional split-K) -------
// EPI 0: C fp32 = acc (+bias if z==0), written at C + z*partStride
template <int EPI, int SPLIT>
__global__ __launch_bounds__(256) void gemm2(
    const __nv_bfloat16* __restrict__ A, int lda,
    const __nv_bfloat16* __restrict__ W, int ldw,
    const float* __restrict__ bias,
    void* __restrict__ Cv, size_t ldc, size_t partStride,
    int M, int K,
    const float* __restrict__ v)
{
    __shared__ __align__(16) unsigned char sm[STAGES][2][128 * 48];

    const int tid    = threadIdx.x;
    const int warpid = tid >> 5, lane = tid & 31;
    const int wm = warpid >> 1, wn = warpid & 1;
    const int gid = lane >> 2, tidg = lane & 3;
    const int bm0 = blockIdx.y * 128, bn0 = blockIdx.x * 128;
    const int z   = (SPLIT > 1) ? blockIdx.z : 0;
    const int kbase = z * (K / SPLIT);
    const int frow = tid >> 1;
    const int half = tid & 1;

    const unsigned sbase = (unsigned)__cvta_generic_to_shared(&sm[0][0][0]);
    unsigned aoff[2], boff[4];
    #pragma unroll
    for (int mi = 0; mi < 2; mi++)
        aoff[mi] = (unsigned)((wm * 32 + mi * 16 + (lane & 15)) * 48 + (lane >> 4) * 16);
    #pragma unroll
    for (int p = 0; p < 4; p++)
        boff[p] = (unsigned)(6144 +
            (wn * 64 + p * 16 + ((lane >> 4) << 3) + (lane & 7)) * 48 + ((lane >> 3) & 1) * 16);

    float acc[2][8][4];
    #pragma unroll
    for (int mi = 0; mi < 2; mi++)
        #pragma unroll
        for (int ni = 0; ni < 8; ni++)
            #pragma unroll
            for (int qq = 0; qq < 4; qq++) acc[mi][ni][qq] = 0.f;

    const int nk = (K / SPLIT) >> 4;
    const unsigned dstA = frow * 48 + half * 16;

    auto issue = [&](int kt) {
        const unsigned st = (unsigned)(kt & (STAGES - 1)) * 12288;
        cpasync16(sbase + st + dstA,
                  A + (size_t)(bm0 + frow) * lda + kbase + (kt << 4) + half * 8);
        cpasync16(sbase + st + 6144 + dstA,
                  W + (size_t)(bn0 + frow) * ldw + kbase + (kt << 4) + half * 8);
        asm volatile("cp.async.commit_group;\n");
    };

    gdep_sync();

    #pragma unroll
    for (int s = 0; s < STAGES - 1; s++) issue(s);

    for (int kt = 0; kt < nk; kt++) {
        asm volatile("cp.async.wait_group %0;\n" :: "n"(STAGES - 2));
        __syncthreads();
        if (kt + STAGES - 1 < nk) issue(kt + STAGES - 1);
        else asm volatile("cp.async.commit_group;\n");

        const unsigned sb = sbase + (unsigned)(kt & (STAGES - 1)) * 12288;
        unsigned af[2][4], bfr[8][2];
        #pragma unroll
        for (int mi = 0; mi < 2; mi++)
            ldsm4(af[mi][0], af[mi][1], af[mi][2], af[mi][3], sb + aoff[mi]);
        #pragma unroll
        for (int p = 0; p < 4; p++) {
            unsigned r0, r1, r2, r3;
            ldsm4(r0, r1, r2, r3, sb + boff[p]);
            bfr[2 * p][0] = r0;     bfr[2 * p][1] = r1;
            bfr[2 * p + 1][0] = r2; bfr[2 * p + 1][1] = r3;
        }
        #pragma unroll
        for (int mi = 0; mi < 2; mi++)
            #pragma unroll
            for (int ni = 0; ni < 8; ni++)
                mma_bf16(acc[mi][ni], af[mi], bfr[ni]);
    }

    const bool addBias = (bias != nullptr) && (z == 0);
    #pragma unroll
    for (int mi = 0; mi < 2; mi++) {
        #pragma unroll
        for (int ni = 0; ni < 8; ni++) {
            const int col = bn0 + wn * 64 + ni * 8 + tidg * 2;
            const float b0v = addBias ? bias[col] : 0.f;
            const float b1v = addBias ? bias[col + 1] : 0.f;
            const int row0 = bm0 + wm * 32 + mi * 16 + gid;
            float* C = (float*)Cv + (size_t)z * partStride;
            C[(size_t)row0 * ldc + col]           = acc[mi][ni][0] + b0v;
            C[(size_t)row0 * ldc + col + 1]       = acc[mi][ni][1] + b1v;
            C[(size_t)(row0 + 8) * ldc + col]     = acc[mi][ni][2] + b0v;
            C[(size_t)(row0 + 8) * ldc + col + 1] = acc[mi][ni][3] + b1v;
        }
    }
}

// ---------------- fp8 GEMM (e4m3, k-tile 32; W pre-scaled x32, epilogue x1/32) ----------
// Same smem layout + ldmatrix as gemm2 (fp8 pairs are layout-identical to b16 units).
// EPI 1: C e4m3 = tanh(acc/32 + bias)
// EPI 2: e-dot: C[slice][row] = sum_col tanh(acc/32 + bias[col]) * v[col]
template <int EPI>
__global__ __launch_bounds__(256) void gemm8(
    const unsigned char* __restrict__ A, int lda,
    const unsigned char* __restrict__ W, int ldw,
    const float* __restrict__ bias,
    void* __restrict__ Cv, size_t ldc,
    int M, int K,
    const float* __restrict__ v)
{
    __shared__ __align__(16) unsigned char sm[STAGES][2][128 * 48];

    const int tid    = threadIdx.x;
    const int warpid = tid >> 5, lane = tid & 31;
    const int wm = warpid >> 1, wn = warpid & 1;
    const int gid = lane >> 2, tidg = lane & 3;
    const int bm0 = blockIdx.y * 128, bn0 = blockIdx.x * 128;
    const int frow = tid >> 1;
    const int half = tid & 1;

    const unsigned sbase = (unsigned)__cvta_generic_to_shared(&sm[0][0][0]);
    unsigned aoff[2], boff[4];
    #pragma unroll
    for (int mi = 0; mi < 2; mi++)
        aoff[mi] = (unsigned)((wm * 32 + mi * 16 + (lane & 15)) * 48 + (lane >> 4) * 16);
    #pragma unroll
    for (int p = 0; p < 4; p++)
        boff[p] = (unsigned)(6144 +
            (wn * 64 + p * 16 + ((lane >> 4) << 3) + (lane & 7)) * 48 + ((lane >> 3) & 1) * 16);

    float acc[2][8][4];
    #pragma unroll
    for (int mi = 0; mi < 2; mi++)
        #pragma unroll
        for (int ni = 0; ni < 8; ni++)
            #pragma unroll
            for (int qq = 0; qq < 4; qq++) acc[mi][ni][qq] = 0.f;

    const int nk = K >> 5;                 // k-tile = 32 fp8 = 32 bytes/row
    const unsigned dstA = frow * 48 + half * 16;

    auto issue = [&](int kt) {
        const unsigned st = (unsigned)(kt & (STAGES - 1)) * 12288;
        cpasync16(sbase + st + dstA,
                  A + (size_t)(bm0 + frow) * lda + (kt << 5) + half * 16);
        cpasync16(sbase + st + 6144 + dstA,
                  W + (size_t)(bn0 + frow) * ldw + (kt << 5) + half * 16);
        asm volatile("cp.async.commit_group;\n");
    };

    gdep_sync();

    #pragma unroll
    for (int s = 0; s < STAGES - 1; s++) issue(s);

    for (int kt = 0; kt < nk; kt++) {
        asm volatile("cp.async.wait_group %0;\n" :: "n"(STAGES - 2));
        __syncthreads();
        if (kt + STAGES - 1 < nk) issue(kt + STAGES - 1);
        else asm volatile("cp.async.commit_group;\n");

        const unsigned sb = sbase + (unsigned)(kt & (STAGES - 1)) * 12288;
        unsigned af[2][4], bfr[8][2];
        #pragma unroll
        for (int mi = 0; mi < 2; mi++)
            ldsm4(af[mi][0], af[mi][1], af[mi][2], af[mi][3], sb + aoff[mi]);
        #pragma unroll
        for (int p = 0; p < 4; p++) {
            unsigned r0, r1, r2, r3;
            ldsm4(r0, r1, r2, r3, sb + boff[p]);
            bfr[2 * p][0] = r0;     bfr[2 * p][1] = r1;
            bfr[2 * p + 1][0] = r2; bfr[2 * p + 1][1] = r3;
        }
        #pragma unroll
        for (int mi = 0; mi < 2; mi++)
            #pragma unroll
            for (int ni = 0; ni < 8; ni++)
                mma_fp8(acc[mi][ni], af[mi], bfr[ni]);
    }

    if (EPI == 2) {
        float* C = (float*)Cv;
        float es[2][2] = {{0.f, 0.f}, {0.f, 0.f}};
        #pragma unroll
        for (int mi = 0; mi < 2; mi++) {
            #pragma unroll
            for (int ni = 0; ni < 8; ni++) {
                const int col = bn0 + wn * 64 + ni * 8 + tidg * 2;
                const float v0 = v[col], v1 = v[col + 1];
                const float b0 = bias[col], b1 = bias[col + 1];
                es[mi][0] += tanh_fast(acc[mi][ni][0] * W8INV + b0) * v0
                           + tanh_fast(acc[mi][ni][1] * W8INV + b1) * v1;
                es[mi][1] += tanh_fast(acc[mi][ni][2] * W8INV + b0) * v0
                           + tanh_fast(acc[mi][ni][3] * W8INV + b1) * v1;
            }
        }
        const int slice = blockIdx.x * 2 + wn;   // 0..7
        #pragma unroll
        for (int mi = 0; mi < 2; mi++) {
            #pragma unroll
            for (int hh = 0; hh < 2; hh++) {
                float s = es[mi][hh];
                s += __shfl_xor_sync(0xffffffffu, s, 1);
                s += __shfl_xor_sync(0xffffffffu, s, 2);
                if (tidg == 0) {
                    const int row = bm0 + wm * 32 + mi * 16 + gid + hh * 8;
                    C[(size_t)slice * M + row] = s;
                }
            }
        }
        return;
    }

    // EPI 1: e4m3 out = tanh(acc/32 + bias)
    unsigned char* C = (unsigned char*)Cv;
    #pragma unroll
    for (int mi = 0; mi < 2; mi++) {
        #pragma unroll
        for (int ni = 0; ni < 8; ni++) {
            const int col = bn0 + wn * 64 + ni * 8 + tidg * 2;
            const float b0v = bias ? bias[col] : 0.f;
            const float b1v = bias ? bias[col + 1] : 0.f;
            const int row0 = bm0 + wm * 32 + mi * 16 + gid;
            *(unsigned short*)(C + (size_t)row0 * ldc + col) =
                f8x2(tanh_fast(acc[mi][ni][0] * W8INV + b0v),
                     tanh_fast(acc[mi][ni][1] * W8INV + b1v));
            *(unsigned short*)(C + (size_t)(row0 + 8) * ldc + col) =
                f8x2(tanh_fast(acc[mi][ni][2] * W8INV + b0v),
                     tanh_fast(acc[mi][ni][3] * W8INV + b1v));
        }
    }
}

// ---------------- e from partials ; softmax ; ctx (bf16 enc) ; xt = [emb|ctx] bf16 --------
__global__ __launch_bounds__(256) void softmax_ctx_kernel(
    const float* __restrict__ epart,
    const __nv_bfloat16* __restrict__ encb,
    const int* __restrict__ tgt_t,
    const float* __restrict__ emb)
{
    __shared__ float e[ENCL];
    __shared__ float alpha[ENCL];
    const int b = blockIdx.x;
    const int tid = threadIdx.x;
    const int warp = tid >> 5, lane = tid & 31;

    gdep_sync();

    if (tid < ENCL) {
        float s = 0.f;
        #pragma unroll
        for (int sl = 0; sl < 8; sl++) s += epart[sl * MROWS + b * ENCL + tid];
        e[tid] = s;
    }
    {
        int tg = tgt_t[b * 32];
        tg = max(0, min(tg, VOCAB - 1));
        const float* er = emb + (size_t)tg * HDIM;
        for (int j = tid; j < HDIM; j += 256)
            g_xt[b * 1024 + j] = __float2bfloat16(er[j]);
    }
    __syncthreads();
    if (warp == 0) {
        const float e0 = e[lane], e1 = e[lane + 32];
        float m = fmaxf(e0, e1);
        #pragma unroll
        for (int o = 16; o; o >>= 1) m = fmaxf(m, __shfl_xor_sync(0xffffffffu, m, o));
        const float x0 = expf(e0 - m), x1 = expf(e1 - m);
        float s = x0 + x1;
        #pragma unroll
        for (int o = 16; o; o >>= 1) s += __shfl_xor_sync(0xffffffffu, s, o);
        const float inv = 1.f / s;
        alpha[lane]      = x0 * inv;
        alpha[lane + 32] = x1 * inv;
    }
    __syncthreads();
    for (int j = tid * 2; j < HDIM; j += 512) {
        float s0 = 0.f, s1 = 0.f;
        #pragma unroll
        for (int l = 0; l < ENCL; l++) {
            const unsigned pk = *(const unsigned*)(encb + ((size_t)b * ENCL + l) * HDIM + j);
            const float a = alpha[l];
            s0 += a * __bfloat162float(*(const __nv_bfloat16*)&pk);
            s1 += a * __bfloat162float(*((const __nv_bfloat16*)&pk + 1));
        }
        *(unsigned*)(g_xt + b * 1024 + 512 + j) = bf2(s0, s1);
    }
}

// ---------------- GRU gate combine; sums split-K parts; fp32 state + bf16 mirror ----------
__global__ void gru_kernel(const float* __restrict__ gi, const float* __restrict__ qgh,
                           const float* __restrict__ h, float* __restrict__ hn,
                           __nv_bfloat16* __restrict__ hbf_out)
{
    const int b = blockIdx.x, j = threadIdx.x;
    const int o  = b * 1536;
    const int og = b * 2048 + HDIM;
    const int GS = BATCH * 1536, QS = BATCH * 2048;
    gdep_sync();
    const float gir = gi[o + j]              + gi[GS + o + j];
    const float giz = gi[o + HDIM + j]       + gi[GS + o + HDIM + j];
    const float gin = gi[o + 2 * HDIM + j]   + gi[GS + o + 2 * HDIM + j];
    const float ghr = qgh[og + j]            + qgh[QS + og + j];
    const float ghz = qgh[og + HDIM + j]     + qgh[QS + og + HDIM + j];
    const float ghn = qgh[og + 2 * HDIM + j] + qgh[QS + og + 2 * HDIM + j];
    const float r = 1.f / (1.f + expf(-(gir + ghr)));
    const float z = 1.f / (1.f + expf(-(giz + ghz)));
    const float n = tanhf(gin + r * ghn);
    const float hv = h[b * HDIM + j];
    const float out = (1.f - z) * n + z * hv;
    hn[b * HDIM + j] = out;
    hbf_out[b * HDIM + j] = __float2bfloat16(out);
}

// ---------------- in-place log-softmax over one row of 32000 ----------------
__global__ __launch_bounds__(1024) void logsoftmax_kernel(float* __restrict__ out, int t) {
    const int b = blockIdx.x;
    float* row = out + ((size_t)b * NSTEP + t) * VOCAB;
    const int tid = threadIdx.x;
    __shared__ float sm[32];

    gdep_sync();

    float r[32];
    float m = -1e30f;
    #pragma unroll
    for (int i = 0; i < 32; i++) {
        const int idx = tid + (i << 10);
        r[i] = (idx < VOCAB) ? row[idx] : -1e30f;
        m = fmaxf(m, r[i]);
    }
    #pragma unroll
    for (int o = 16; o; o >>= 1) m = fmaxf(m, __shfl_xor_sync(0xffffffffu, m, o));
    if ((tid & 31) == 0) sm[tid >> 5] = m;
    __syncthreads();
    if (tid == 0) {
        float v = sm[0];
        for (int i = 1; i < 32; i++) v = fmaxf(v, sm[i]);
        sm[0] = v;
    }
    __syncthreads();
    m = sm[0];

    float s = 0.f;
    #pragma unroll
    for (int i = 0; i < 32; i++) {
        const int idx = tid + (i << 10);
        if (idx < VOCAB) s += expf(r[i] - m);
    }
    #pragma unroll
    for (int o = 16; o; o >>= 1) s += __shfl_xor_sync(0xffffffffu, s, o);
    __syncthreads();
    if ((tid & 31) == 0) sm[tid >> 5] = s;
    __syncthreads();
    if (tid == 0) {
        float v = 0.f;
        for (int i = 0; i < 32; i++) v += sm[i];
        sm[0] = v;
    }
    __syncthreads();
    const float lse = m + logf(sm[0]);

    #pragma unroll
    for (int i = 0; i < 32; i++) {
        const int idx = tid + (i << 10);
        if (idx < VOCAB) row[idx] = r[i] - lse;
    }
}

// ---------------- PDL launch helper ----------------
template <typename F, typename... Args>
static inline void pdl(F f, dim3 grid, dim3 block, cudaStream_t st, Args... args) {
    cudaLaunchConfig_t cfg = {};
    cfg.gridDim = grid;
    cfg.blockDim = block;
    cfg.stream = st;
    cudaLaunchAttribute attr;
    attr.id = cudaLaunchAttributeProgrammaticStreamSerialization;
    attr.val.programmaticStreamSerializationAllowed = 1;
    cfg.attrs = &attr;
    cfg.numAttrs = 1;
    cudaLaunchKernelEx(&cfg, f, args...);
}

// ---------------- launch ----------------
extern "C" void kernel_launch(void* const* d_in, const int* in_sizes, int n_in,
                              void* d_out, int out_size)
{
    const float* enc       = (const float*)d_in[0];
    const float* ench      = (const float*)d_in[1];
    const int* tgt         = (const int*)d_in[2];
    const float* emb       = (const float*)d_in[3];
    const float* W1        = (const float*)d_in[4];
    const float* b1        = (const float*)d_in[5];
    const float* W2        = (const float*)d_in[6];
    const float* b2        = (const float*)d_in[7];
    const float* W3        = (const float*)d_in[8];
    const float* b3        = (const float*)d_in[9];
    const float* av        = (const float*)d_in[10];
    const float* Wih       = (const float*)d_in[11];
    const float* Whh       = (const float*)d_in[12];
    const float* bih       = (const float*)d_in[13];
    const float* bhh       = (const float*)d_in[14];
    const float* oW        = (const float*)d_in[15];
    const float* ob        = (const float*)d_in[16];
    float* out = (float*)d_out;

    float *P, *epart, *hidb, *qgh, *gi, *bqh;
    unsigned char *A1f, *a2f, *W2f, *W3f;
    __nv_bfloat16 *hbf, *xt, *encb, *Wp, *Wqh, *Wihb, *Wob;
    cudaGetSymbolAddress((void**)&P,     g_P);
    cudaGetSymbolAddress((void**)&A1f,   g_A1f);
    cudaGetSymbolAddress((void**)&a2f,   g_a2f);
    cudaGetSymbolAddress((void**)&epart, g_epart);
    cudaGetSymbolAddress((void**)&hidb,  g_hid);
    cudaGetSymbolAddress((void**)&hbf,   g_hbf);
    cudaGetSymbolAddress((void**)&qgh,   g_qgh);
    cudaGetSymbolAddress((void**)&xt,    g_xt);
    cudaGetSymbolAddress((void**)&gi,    g_gi);
    cudaGetSymbolAddress((void**)&bqh,   g_bqh);
    cudaGetSymbolAddress((void**)&encb,  g_encb);
    cudaGetSymbolAddress((void**)&Wp,    g_Wp);
    cudaGetSymbolAddress((void**)&Wqh,   g_Wqh);
    cudaGetSymbolAddress((void**)&W2f,   g_W2f);
    cudaGetSymbolAddress((void**)&W3f,   g_W3f);
    cudaGetSymbolAddress((void**)&Wihb,  g_Wih);
    cudaGetSymbolAddress((void**)&Wob,   g_Wo);

    // second stream + events for logits/logsoftmax overlap (leaked by design:
    // no device allocation; destroying mid-capture is illegal)
    cudaStream_t s2;
    cudaStreamCreateWithFlags(&s2, cudaStreamNonBlocking);
    cudaEvent_t evGru[NSTEP], evLog[NSTEP];
    for (int t = 0; t < NSTEP; t++) {
        cudaEventCreateWithFlags(&evGru[t], cudaEventDisableTiming);
        cudaEventCreateWithFlags(&evLog[t], cudaEventDisableTiming);
    }

    init_misc_kernel<<<(BATCH * HDIM + 255) / 256, 256>>>(ench, b1, bhh);
    conv_all_kernel<<<(CB7 + 255) / 256, 256>>>(enc, W1, Whh, W2, W3, Wih, oW);

    // P = enc @ W1[:, :H]^T  (fp32 out, no bias)
    pdl(&gemm2<0, 1>, dim3(HDIM / 128, MROWS / 128), dim3(256), (cudaStream_t)0,
        (const __nv_bfloat16*)encb, (int)HDIM, (const __nv_bfloat16*)Wp, (int)HDIM,
        (const float*)nullptr, (void*)P, (size_t)HDIM, (size_t)0, (int)MROWS, (int)HDIM,
        (const float*)nullptr);

    for (int t = 0; t < NSTEP; t++) {
        float* hi = hidb + (t & 1) * (BATCH * HDIM);
        float* ho = hidb + ((t + 1) & 1) * (BATCH * HDIM);
        __nv_bfloat16* hbi = hbf + (t & 1) * (BATCH * HDIM);
        __nv_bfloat16* hbo = hbf + ((t + 1) & 1) * (BATCH * HDIM);

        // [q | gh] = hid @ [W1b ; Whh]^T + [b1 | bhh]   (split-K 2, bf16)
        pdl(&gemm2<0, 2>, dim3(2048 / 128, 1, 2), dim3(256), (cudaStream_t)0,
            (const __nv_bfloat16*)hbi, (int)HDIM, (const __nv_bfloat16*)Wqh, (int)HDIM,
            (const float*)bqh, (void*)qgh, (size_t)2048, (size_t)(BATCH * 2048),
            (int)BATCH, (int)HDIM, (const float*)nullptr);

        // A1 = tanh(P + q)  (e4m3)
        pdl(&a1prep_kernel, dim3(MROWS * HDIM / 4 / 256), dim3(256), (cudaStream_t)0,
            (const float*)P, (const float*)qgh);

        // a2 = tanh(A1 @ W2^T + b2)  (fp8 GEMM, e4m3 out)
        pdl(&gemm8<1>, dim3(HDIM / 128, MROWS / 128), dim3(256), (cudaStream_t)0,
            (const unsigned char*)A1f, (int)HDIM, (const unsigned char*)W2f, (int)HDIM,
            (const float*)b2, (void*)a2f, (size_t)HDIM,
            (int)MROWS, (int)HDIM, (const float*)nullptr);

        // e_part[8][MROWS] = slicewise [ tanh(a2 @ W3^T + b3) . v ]  (fp8 GEMM)
        pdl(&gemm8<2>, dim3(HDIM / 128, MROWS / 128), dim3(256), (cudaStream_t)0,
            (const unsigned char*)a2f, (int)HDIM, (const unsigned char*)W3f, (int)HDIM,
            (const float*)b3, (void*)epart, (size_t)0,
            (int)MROWS, (int)HDIM, (const float*)av);

        pdl(&softmax_ctx_kernel, dim3(BATCH), dim3(256), (cudaStream_t)0,
            (const float*)epart, (const __nv_bfloat16*)encb,
            (const int*)(tgt + t), (const float*)emb);

        // gi = xt @ Wih^T + bih   (split-K 2, bf16)
        pdl(&gemm2<0, 2>, dim3(1536 / 128, 1, 2), dim3(256), (cudaStream_t)0,
            (const __nv_bfloat16*)xt, (int)1024, (const __nv_bfloat16*)Wihb, (int)1024,
            (const float*)bih, (void*)gi, (size_t)1536, (size_t)(BATCH * 1536),
            (int)BATCH, (int)1024, (const float*)nullptr);

        // guard: logits(t-2) must be done before we overwrite its hidden buffer
        if (t >= 2) cudaStreamWaitEvent(0, evLog[t - 2], 0);

        pdl(&gru_kernel, dim3(BATCH), dim3(HDIM), (cudaStream_t)0,
            (const float*)gi, (const float*)qgh, (const float*)hi, (float*)ho,
            (__nv_bfloat16*)hbo);
        cudaEventRecord(evGru[t], 0);

        // overlapped branch: logits + log-softmax on s2 (bf16)
        cudaStreamWaitEvent(s2, evGru[t], 0);
        pdl(&gemm2<0, 1>, dim3(VOCAB / 128, 1), dim3(256), s2,
            (const __nv_bfloat16*)hbo, (int)HDIM, (const __nv_bfloat16*)Wob, (int)HDIM,
            (const float*)ob, (void*)(out + (size_t)t * VOCAB),
            (size_t)((size_t)NSTEP * VOCAB), (size_t)0,
            (int)BATCH, (int)HDIM, (const float*)nullptr);
        pdl(&logsoftmax_kernel, dim3(BATCH), dim3(1024), s2, (float*)out, (int)t);
        cudaEventRecord(evLog[t], s2);
    }

    // rejoin: main stream waits for the last overlapped branch
    cudaStreamWaitEvent(0, evLog[NSTEP - 1], 0);
}

// round 15
// speedup vs baseline: 1.9985x; 1.0414x over previous
#include <cuda_runtime.h>
#include <cuda_bf16.h>
#include <math.h>

#define VOCAB 32000
#define HDIM  512
#define BATCH 128
#define ENCL  64
#define NSTEP 31
#define MROWS (BATCH * ENCL)   // 8192
#define STAGES 4
#define W8SCALE 32.0f
#define W8INV   0.03125f
#define KSPL    4               // split-K for small-M GEMMs

// ---------------- scratch (static device globals; no allocation) ----------------
__device__ __nv_bfloat16  g_Pb[MROWS * HDIM];       // enc @ W1a^T (bf16, time-invariant)
__device__ unsigned char  g_A1f[MROWS * HDIM];      // tanh(P + q)  (e4m3)
__device__ unsigned char  g_a2f[MROWS * HDIM];      // tanh(a1 @ W2^T + b2)  (e4m3)
__device__ float          g_epart[8 * MROWS];       // per-slice partial dots (a3 . v)
__device__ float          g_hid[2][BATCH * HDIM];   // fp32 recurrence (ping-pong)
__device__ __nv_bfloat16  g_hbf[2][BATCH * HDIM];   // bf16 hidden (ping-pong)
__device__ unsigned char  g_hf8[2][BATCH * HDIM];   // e4m3 hidden (ping-pong, logits)
__device__ float          g_qgh[KSPL * BATCH * 2048]; // split-K parts of [q | gh]
__device__ __nv_bfloat16  g_xt[BATCH * 1024];       // [emb[tgt] | ctx]  bf16
__device__ float          g_gi[KSPL * BATCH * 1536];  // split-K parts of gi
__device__ float          g_bqh[2048];              // [b1 | bhh]

// weight copies (converted once per replay)
__device__ __nv_bfloat16 g_encb[MROWS * HDIM];
__device__ __nv_bfloat16 g_Wp  [HDIM * HDIM];
__device__ __nv_bfloat16 g_Wqh [2048 * HDIM];
__device__ unsigned char g_W2f [HDIM * HDIM];       // e4m3, pre-scaled x32
__device__ unsigned char g_W3f [HDIM * HDIM];       // e4m3, pre-scaled x32
__device__ __nv_bfloat16 g_Wih [1536 * 1024];
__device__ unsigned char g_Wof [VOCAB * HDIM];      // e4m3, pre-scaled x32

// ---------------- helpers ----------------
__device__ __forceinline__ unsigned bf2(float lo, float hi) {
    unsigned u;
    asm("cvt.rn.bf16x2.f32 %0, %1, %2;" : "=r"(u) : "f"(hi), "f"(lo));
    return u;
}
__device__ __forceinline__ unsigned short f8x2(float lo, float hi) {
    unsigned short u;
    asm("cvt.rn.satfinite.e4m3x2.f32 %0, %1, %2;" : "=h"(u) : "f"(hi), "f"(lo));
    return u;
}
__device__ __forceinline__ float tanh_fast(float x) {
    float y;
    asm("tanh.approx.f32 %0, %1;" : "=f"(y) : "f"(x));
    return y;
}
__device__ __forceinline__ void mma_bf16(float c[4], const unsigned a[4], const unsigned b[2]) {
    asm volatile(
        "mma.sync.aligned.m16n8k16.row.col.f32.bf16.bf16.f32 "
        "{%0,%1,%2,%3}, {%4,%5,%6,%7}, {%8,%9}, {%0,%1,%2,%3};\n"
        : "+f"(c[0]), "+f"(c[1]), "+f"(c[2]), "+f"(c[3])
        : "r"(a[0]), "r"(a[1]), "r"(a[2]), "r"(a[3]), "r"(b[0]), "r"(b[1]));
}
__device__ __forceinline__ void mma_fp8(float c[4], const unsigned a[4], const unsigned b[2]) {
    asm volatile(
        "mma.sync.aligned.m16n8k32.row.col.f32.e4m3.e4m3.f32 "
        "{%0,%1,%2,%3}, {%4,%5,%6,%7}, {%8,%9}, {%0,%1,%2,%3};\n"
        : "+f"(c[0]), "+f"(c[1]), "+f"(c[2]), "+f"(c[3])
        : "r"(a[0]), "r"(a[1]), "r"(a[2]), "r"(a[3]), "r"(b[0]), "r"(b[1]));
}
__device__ __forceinline__ void ldsm4(unsigned& r0, unsigned& r1, unsigned& r2, unsigned& r3,
                                      unsigned addr) {
    asm volatile("ldmatrix.sync.aligned.m8n8.x4.shared.b16 {%0,%1,%2,%3}, [%4];"
                 : "=r"(r0), "=r"(r1), "=r"(r2), "=r"(r3) : "r"(addr));
}
__device__ __forceinline__ void cpasync16(unsigned dst, const void* src) {
    asm volatile("cp.async.cg.shared.global [%0], [%1], 16;\n" :: "r"(dst), "l"(src));
}
__device__ __forceinline__ void gdep_sync() {
#if __CUDA_ARCH__ >= 900
    cudaGridDependencySynchronize();
#endif
}

// ---------------- unified weight/operand conversion ----------------
#define N_ENC (MROWS * HDIM / 4)
#define N_SQ  (HDIM * HDIM / 4)
#define N_WQ2 (1536 * HDIM / 4)
#define N_WIH (1536 * 1024 / 4)
#define N_WO  (VOCAB * HDIM / 4)
#define CB0 (N_ENC)
#define CB1 (CB0 + N_SQ)
#define CB2 (CB1 + N_SQ)
#define CB3 (CB2 + N_WQ2)
#define CB4 (CB3 + N_SQ)
#define CB5 (CB4 + N_SQ)
#define CB6 (CB5 + N_WIH)
#define CB7 (CB6 + N_WO)

__device__ __forceinline__ void copy4(__nv_bfloat16* dst, const float* src) {
    float4 v = *(const float4*)src;
    uint2 o;
    o.x = bf2(v.x, v.y);
    o.y = bf2(v.z, v.w);
    *(uint2*)dst = o;
}
__device__ __forceinline__ void copy4_f8(unsigned char* dst, const float* src) {
    float4 v = *(const float4*)src;
    const unsigned lo = f8x2(v.x * W8SCALE, v.y * W8SCALE);
    const unsigned hi = f8x2(v.z * W8SCALE, v.w * W8SCALE);
    *(unsigned*)dst = lo | (hi << 16);
}

__global__ void conv_all_kernel(const float* __restrict__ enc,
                                const float* __restrict__ W1,
                                const float* __restrict__ Whh,
                                const float* __restrict__ W2,
                                const float* __restrict__ W3,
                                const float* __restrict__ Wih,
                                const float* __restrict__ Wo) {
    const int i = blockIdx.x * blockDim.x + threadIdx.x;
    if (i >= CB7) return;
    if (i < CB0) {
        copy4(g_encb + i * 4, enc + i * 4);
    } else if (i < CB1) {
        const int l = i - CB0, r = l >> 7, c = (l & 127) * 4;
        copy4(g_Wp + l * 4, W1 + (size_t)r * 1024 + c);
    } else if (i < CB2) {
        const int l = i - CB1, r = l >> 7, c = (l & 127) * 4;
        copy4(g_Wqh + l * 4, W1 + (size_t)r * 1024 + 512 + c);
    } else if (i < CB3) {
        const int l = i - CB2;
        copy4(g_Wqh + HDIM * HDIM + l * 4, Whh + l * 4);
    } else if (i < CB4) {
        const int l = i - CB3;
        copy4_f8(g_W2f + l * 4, W2 + l * 4);
    } else if (i < CB5) {
        const int l = i - CB4;
        copy4_f8(g_W3f + l * 4, W3 + l * 4);
    } else if (i < CB6) {
        const int l = i - CB5;
        copy4(g_Wih + l * 4, Wih + l * 4);
    } else {
        const int l = i - CB6;
        copy4_f8(g_Wof + l * 4, Wo + l * 4);
    }
}

__global__ void init_misc_kernel(const float* __restrict__ ench,
                                 const float* __restrict__ b1,
                                 const float* __restrict__ bhh) {
    const int i = blockIdx.x * blockDim.x + threadIdx.x;
    if (i < BATCH * HDIM) {
        const float h = ench[i];
        g_hid[0][i] = h;
        g_hbf[0][i] = __float2bfloat16(h);
        unsigned short u = f8x2(h, 0.f);
        g_hf8[0][i] = (unsigned char)(u & 0xFF);
    }
    if (i < 2048) g_bqh[i] = (i < HDIM) ? b1[i] : bhh[i - HDIM];
}

// ---------------- A1 = tanh(P + sum_p q_p)  (e4m3; P bf16, KSPL q parts) --------------
__global__ __launch_bounds__(256) void a1prep_kernel(const __nv_bfloat16* __restrict__ Pb,
                                                     const float* __restrict__ qgh) {
    const int i4 = (blockIdx.x * blockDim.x + threadIdx.x) * 4;
    const int row = i4 >> 9, k = i4 & 511;
    gdep_sync();
    const uint2 pk = *(const uint2*)(Pb + i4);
    float p0 = __bfloat162float(*(const __nv_bfloat16*)&pk.x);
    float p1 = __bfloat162float(*((const __nv_bfloat16*)&pk.x + 1));
    float p2 = __bfloat162float(*(const __nv_bfloat16*)&pk.y);
    float p3 = __bfloat162float(*((const __nv_bfloat16*)&pk.y + 1));
    const float* qb = qgh + ((row >> 6) << 11) + k;
    #pragma unroll
    for (int p = 0; p < KSPL; p++) {
        const float* q = qb + p * (BATCH * 2048);
        p0 += q[0]; p1 += q[1]; p2 += q[2]; p3 += q[3];
    }
    const unsigned lo = f8x2(tanh_fast(p0), tanh_fast(p1));
    const unsigned hi = f8x2(tanh_fast(p2), tanh_fast(p3));
    *(unsigned*)(g_A1f + i4) = lo | (hi << 16);
}

// ---------------- bf16 GEMM (cp.async 4-stage, ldmatrix + mma, optional split-K) -------
// EPI 0: C fp32 = acc (+bias if z==0), written at C + z*partStride
// EPI 3: C bf16 = acc (raw, no bias)
template <int EPI, int SPLIT>
__global__ __launch_bounds__(256) void gemm2(
    const __nv_bfloat16* __restrict__ A, int lda,
    const __nv_bfloat16* __restrict__ W, int ldw,
    const float* __restrict__ bias,
    void* __restrict__ Cv, size_t ldc, size_t partStride,
    int M, int K,
    const float* __restrict__ v)
{
    __shared__ __align__(16) unsigned char sm[STAGES][2][128 * 48];

    const int tid    = threadIdx.x;
    const int warpid = tid >> 5, lane = tid & 31;
    const int wm = warpid >> 1, wn = warpid & 1;
    const int gid = lane >> 2, tidg = lane & 3;
    const int bm0 = blockIdx.y * 128, bn0 = blockIdx.x * 128;
    const int z   = (SPLIT > 1) ? blockIdx.z : 0;
    const int kbase = z * (K / SPLIT);
    const int frow = tid >> 1;
    const int half = tid & 1;

    const unsigned sbase = (unsigned)__cvta_generic_to_shared(&sm[0][0][0]);
    unsigned aoff[2], boff[4];
    #pragma unroll
    for (int mi = 0; mi < 2; mi++)
        aoff[mi] = (unsigned)((wm * 32 + mi * 16 + (lane & 15)) * 48 + (lane >> 4) * 16);
    #pragma unroll
    for (int p = 0; p < 4; p++)
        boff[p] = (unsigned)(6144 +
            (wn * 64 + p * 16 + ((lane >> 4) << 3) + (lane & 7)) * 48 + ((lane >> 3) & 1) * 16);

    float acc[2][8][4];
    #pragma unroll
    for (int mi = 0; mi < 2; mi++)
        #pragma unroll
        for (int ni = 0; ni < 8; ni++)
            #pragma unroll
            for (int qq = 0; qq < 4; qq++) acc[mi][ni][qq] = 0.f;

    const int nk = (K / SPLIT) >> 4;
    const unsigned dstA = frow * 48 + half * 16;

    auto issue = [&](int kt) {
        const unsigned st = (unsigned)(kt & (STAGES - 1)) * 12288;
        cpasync16(sbase + st + dstA,
                  A + (size_t)(bm0 + frow) * lda + kbase + (kt << 4) + half * 8);
        cpasync16(sbase + st + 6144 + dstA,
                  W + (size_t)(bn0 + frow) * ldw + kbase + (kt << 4) + half * 8);
        asm volatile("cp.async.commit_group;\n");
    };

    gdep_sync();

    #pragma unroll
    for (int s = 0; s < STAGES - 1; s++) issue(s);

    for (int kt = 0; kt < nk; kt++) {
        asm volatile("cp.async.wait_group %0;\n" :: "n"(STAGES - 2));
        __syncthreads();
        if (kt + STAGES - 1 < nk) issue(kt + STAGES - 1);
        else asm volatile("cp.async.commit_group;\n");

        const unsigned sb = sbase + (unsigned)(kt & (STAGES - 1)) * 12288;
        unsigned af[2][4], bfr[8][2];
        #pragma unroll
        for (int mi = 0; mi < 2; mi++)
            ldsm4(af[mi][0], af[mi][1], af[mi][2], af[mi][3], sb + aoff[mi]);
        #pragma unroll
        for (int p = 0; p < 4; p++) {
            unsigned r0, r1, r2, r3;
            ldsm4(r0, r1, r2, r3, sb + boff[p]);
            bfr[2 * p][0] = r0;     bfr[2 * p][1] = r1;
            bfr[2 * p + 1][0] = r2; bfr[2 * p + 1][1] = r3;
        }
        #pragma unroll
        for (int mi = 0; mi < 2; mi++)
            #pragma unroll
            for (int ni = 0; ni < 8; ni++)
                mma_bf16(acc[mi][ni], af[mi], bfr[ni]);
    }

    if (EPI == 3) {
        __nv_bfloat16* C = (__nv_bfloat16*)Cv;
        #pragma unroll
        for (int mi = 0; mi < 2; mi++) {
            #pragma unroll
            for (int ni = 0; ni < 8; ni++) {
                const int col = bn0 + wn * 64 + ni * 8 + tidg * 2;
                const int row0 = bm0 + wm * 32 + mi * 16 + gid;
                *(unsigned*)(C + (size_t)row0 * ldc + col) =
                    bf2(acc[mi][ni][0], acc[mi][ni][1]);
                *(unsigned*)(C + (size_t)(row0 + 8) * ldc + col) =
                    bf2(acc[mi][ni][2], acc[mi][ni][3]);
            }
        }
        return;
    }

    const bool addBias = (bias != nullptr) && (z == 0);
    #pragma unroll
    for (int mi = 0; mi < 2; mi++) {
        #pragma unroll
        for (int ni = 0; ni < 8; ni++) {
            const int col = bn0 + wn * 64 + ni * 8 + tidg * 2;
            const float b0v = addBias ? bias[col] : 0.f;
            const float b1v = addBias ? bias[col + 1] : 0.f;
            const int row0 = bm0 + wm * 32 + mi * 16 + gid;
            float* C = (float*)Cv + (size_t)z * partStride;
            C[(size_t)row0 * ldc + col]           = acc[mi][ni][0] + b0v;
            C[(size_t)row0 * ldc + col + 1]       = acc[mi][ni][1] + b1v;
            C[(size_t)(row0 + 8) * ldc + col]     = acc[mi][ni][2] + b0v;
            C[(size_t)(row0 + 8) * ldc + col + 1] = acc[mi][ni][3] + b1v;
        }
    }
}

// ---------------- fp8 GEMM (e4m3, k-tile 32; W pre-scaled x32, epilogue x1/32) ----------
// EPI 0: C fp32 = acc/32 + bias  (logits)
// EPI 1: C e4m3 = tanh(acc/32 + bias)
// EPI 2: e-dot: C[slice][row] = sum_col tanh(acc/32 + bias[col]) * v[col]
template <int EPI>
__global__ __launch_bounds__(256) void gemm8(
    const unsigned char* __restrict__ A, int lda,
    const unsigned char* __restrict__ W, int ldw,
    const float* __restrict__ bias,
    void* __restrict__ Cv, size_t ldc,
    int M, int K,
    const float* __restrict__ v)
{
    __shared__ __align__(16) unsigned char sm[STAGES][2][128 * 48];

    const int tid    = threadIdx.x;
    const int warpid = tid >> 5, lane = tid & 31;
    const int wm = warpid >> 1, wn = warpid & 1;
    const int gid = lane >> 2, tidg = lane & 3;
    const int bm0 = blockIdx.y * 128, bn0 = blockIdx.x * 128;
    const int frow = tid >> 1;
    const int half = tid & 1;

    const unsigned sbase = (unsigned)__cvta_generic_to_shared(&sm[0][0][0]);
    unsigned aoff[2], boff[4];
    #pragma unroll
    for (int mi = 0; mi < 2; mi++)
        aoff[mi] = (unsigned)((wm * 32 + mi * 16 + (lane & 15)) * 48 + (lane >> 4) * 16);
    #pragma unroll
    for (int p = 0; p < 4; p++)
        boff[p] = (unsigned)(6144 +
            (wn * 64 + p * 16 + ((lane >> 4) << 3) + (lane & 7)) * 48 + ((lane >> 3) & 1) * 16);

    float acc[2][8][4];
    #pragma unroll
    for (int mi = 0; mi < 2; mi++)
        #pragma unroll
        for (int ni = 0; ni < 8; ni++)
            #pragma unroll
            for (int qq = 0; qq < 4; qq++) acc[mi][ni][qq] = 0.f;

    const int nk = K >> 5;
    const unsigned dstA = frow * 48 + half * 16;

    auto issue = [&](int kt) {
        const unsigned st = (unsigned)(kt & (STAGES - 1)) * 12288;
        cpasync16(sbase + st + dstA,
                  A + (size_t)(bm0 + frow) * lda + (kt << 5) + half * 16);
        cpasync16(sbase + st + 6144 + dstA,
                  W + (size_t)(bn0 + frow) * ldw + (kt << 5) + half * 16);
        asm volatile("cp.async.commit_group;\n");
    };

    gdep_sync();

    #pragma unroll
    for (int s = 0; s < STAGES - 1; s++) issue(s);

    for (int kt = 0; kt < nk; kt++) {
        asm volatile("cp.async.wait_group %0;\n" :: "n"(STAGES - 2));
        __syncthreads();
        if (kt + STAGES - 1 < nk) issue(kt + STAGES - 1);
        else asm volatile("cp.async.commit_group;\n");

        const unsigned sb = sbase + (unsigned)(kt & (STAGES - 1)) * 12288;
        unsigned af[2][4], bfr[8][2];
        #pragma unroll
        for (int mi = 0; mi < 2; mi++)
            ldsm4(af[mi][0], af[mi][1], af[mi][2], af[mi][3], sb + aoff[mi]);
        #pragma unroll
        for (int p = 0; p < 4; p++) {
            unsigned r0, r1, r2, r3;
            ldsm4(r0, r1, r2, r3, sb + boff[p]);
            bfr[2 * p][0] = r0;     bfr[2 * p][1] = r1;
            bfr[2 * p + 1][0] = r2; bfr[2 * p + 1][1] = r3;
        }
        #pragma unroll
        for (int mi = 0; mi < 2; mi++)
            #pragma unroll
            for (int ni = 0; ni < 8; ni++)
                mma_fp8(acc[mi][ni], af[mi], bfr[ni]);
    }

    if (EPI == 2) {
        float* C = (float*)Cv;
        float es[2][2] = {{0.f, 0.f}, {0.f, 0.f}};
        #pragma unroll
        for (int mi = 0; mi < 2; mi++) {
            #pragma unroll
            for (int ni = 0; ni < 8; ni++) {
                const int col = bn0 + wn * 64 + ni * 8 + tidg * 2;
                const float v0 = v[col], v1 = v[col + 1];
                const float b0 = bias[col], b1 = bias[col + 1];
                es[mi][0] += tanh_fast(acc[mi][ni][0] * W8INV + b0) * v0
                           + tanh_fast(acc[mi][ni][1] * W8INV + b1) * v1;
                es[mi][1] += tanh_fast(acc[mi][ni][2] * W8INV + b0) * v0
                           + tanh_fast(acc[mi][ni][3] * W8INV + b1) * v1;
            }
        }
        const int slice = blockIdx.x * 2 + wn;
        #pragma unroll
        for (int mi = 0; mi < 2; mi++) {
            #pragma unroll
            for (int hh = 0; hh < 2; hh++) {
                float s = es[mi][hh];
                s += __shfl_xor_sync(0xffffffffu, s, 1);
                s += __shfl_xor_sync(0xffffffffu, s, 2);
                if (tidg == 0) {
                    const int row = bm0 + wm * 32 + mi * 16 + gid + hh * 8;
                    C[(size_t)slice * M + row] = s;
                }
            }
        }
        return;
    }

    if (EPI == 0) {
        float* C = (float*)Cv;
        #pragma unroll
        for (int mi = 0; mi < 2; mi++) {
            #pragma unroll
            for (int ni = 0; ni < 8; ni++) {
                const int col = bn0 + wn * 64 + ni * 8 + tidg * 2;
                const float b0v = bias ? bias[col] : 0.f;
                const float b1v = bias ? bias[col + 1] : 0.f;
                const int row0 = bm0 + wm * 32 + mi * 16 + gid;
                C[(size_t)row0 * ldc + col]           = acc[mi][ni][0] * W8INV + b0v;
                C[(size_t)row0 * ldc + col + 1]       = acc[mi][ni][1] * W8INV + b1v;
                C[(size_t)(row0 + 8) * ldc + col]     = acc[mi][ni][2] * W8INV + b0v;
                C[(size_t)(row0 + 8) * ldc + col + 1] = acc[mi][ni][3] * W8INV + b1v;
            }
        }
        return;
    }

    // EPI 1: e4m3 out = tanh(acc/32 + bias)
    unsigned char* C = (unsigned char*)Cv;
    #pragma unroll
    for (int mi = 0; mi < 2; mi++) {
        #pragma unroll
        for (int ni = 0; ni < 8; ni++) {
            const int col = bn0 + wn * 64 + ni * 8 + tidg * 2;
            const float b0v = bias ? bias[col] : 0.f;
            const float b1v = bias ? bias[col + 1] : 0.f;
            const int row0 = bm0 + wm * 32 + mi * 16 + gid;
            *(unsigned short*)(C + (size_t)row0 * ldc + col) =
                f8x2(tanh_fast(acc[mi][ni][0] * W8INV + b0v),
                     tanh_fast(acc[mi][ni][1] * W8INV + b1v));
            *(unsigned short*)(C + (size_t)(row0 + 8) * ldc + col) =
                f8x2(tanh_fast(acc[mi][ni][2] * W8INV + b0v),
                     tanh_fast(acc[mi][ni][3] * W8INV + b1v));
        }
    }
}

// ---------------- e from partials ; softmax ; ctx (bf16 enc) ; xt = [emb|ctx] bf16 --------
__global__ __launch_bounds__(256) void softmax_ctx_kernel(
    const float* __restrict__ epart,
    const __nv_bfloat16* __restrict__ encb,
    const int* __restrict__ tgt_t,
    const float* __restrict__ emb)
{
    __shared__ float e[ENCL];
    __shared__ float alpha[ENCL];
    const int b = blockIdx.x;
    const int tid = threadIdx.x;
    const int warp = tid >> 5, lane = tid & 31;

    gdep_sync();

    if (tid < ENCL) {
        float s = 0.f;
        #pragma unroll
        for (int sl = 0; sl < 8; sl++) s += epart[sl * MROWS + b * ENCL + tid];
        e[tid] = s;
    }
    {
        int tg = tgt_t[b * 32];
        tg = max(0, min(tg, VOCAB - 1));
        const float* er = emb + (size_t)tg * HDIM;
        for (int j = tid; j < HDIM; j += 256)
            g_xt[b * 1024 + j] = __float2bfloat16(er[j]);
    }
    __syncthreads();
    if (warp == 0) {
        const float e0 = e[lane], e1 = e[lane + 32];
        float m = fmaxf(e0, e1);
        #pragma unroll
        for (int o = 16; o; o >>= 1) m = fmaxf(m, __shfl_xor_sync(0xffffffffu, m, o));
        const float x0 = expf(e0 - m), x1 = expf(e1 - m);
        float s = x0 + x1;
        #pragma unroll
        for (int o = 16; o; o >>= 1) s += __shfl_xor_sync(0xffffffffu, s, o);
        const float inv = 1.f / s;
        alpha[lane]      = x0 * inv;
        alpha[lane + 32] = x1 * inv;
    }
    __syncthreads();
    for (int j = tid * 2; j < HDIM; j += 512) {
        float s0 = 0.f, s1 = 0.f;
        #pragma unroll
        for (int l = 0; l < ENCL; l++) {
            const unsigned pk = *(const unsigned*)(encb + ((size_t)b * ENCL + l) * HDIM + j);
            const float a = alpha[l];
            s0 += a * __bfloat162float(*(const __nv_bfloat16*)&pk);
            s1 += a * __bfloat162float(*((const __nv_bfloat16*)&pk + 1));
        }
        *(unsigned*)(g_xt + b * 1024 + 512 + j) = bf2(s0, s1);
    }
}

// ---------------- GRU gate combine; sums KSPL parts; fp32 + bf16 + fp8 mirrors ----------
__global__ void gru_kernel(const float* __restrict__ gi, const float* __restrict__ qgh,
                           const float* __restrict__ h, float* __restrict__ hn,
                           __nv_bfloat16* __restrict__ hbf_out,
                           unsigned char* __restrict__ hf8_out)
{
    const int b = blockIdx.x, j = threadIdx.x;
    const int o  = b * 1536;
    const int og = b * 2048 + HDIM;
    const int GS = BATCH * 1536, QS = BATCH * 2048;
    gdep_sync();
    float gir = 0.f, giz = 0.f, gin = 0.f, ghr = 0.f, ghz = 0.f, ghn = 0.f;
    #pragma unroll
    for (int p = 0; p < KSPL; p++) {
        gir += gi[p * GS + o + j];
        giz += gi[p * GS + o + HDIM + j];
        gin += gi[p * GS + o + 2 * HDIM + j];
        ghr += qgh[p * QS + og + j];
        ghz += qgh[p * QS + og + HDIM + j];
        ghn += qgh[p * QS + og + 2 * HDIM + j];
    }
    const float r = 1.f / (1.f + expf(-(gir + ghr)));
    const float z = 1.f / (1.f + expf(-(giz + ghz)));
    const float n = tanhf(gin + r * ghn);
    const float hv = h[b * HDIM + j];
    const float out = (1.f - z) * n + z * hv;
    hn[b * HDIM + j] = out;
    hbf_out[b * HDIM + j] = __float2bfloat16(out);
    unsigned short u = f8x2(out, 0.f);
    hf8_out[b * HDIM + j] = (unsigned char)(u & 0xFF);
}

// ---------------- in-place log-softmax over one row of 32000 ----------------
__global__ __launch_bounds__(1024) void logsoftmax_kernel(float* __restrict__ out, int t) {
    const int b = blockIdx.x;
    float* row = out + ((size_t)b * NSTEP + t) * VOCAB;
    const int tid = threadIdx.x;
    __shared__ float sm[32];

    gdep_sync();

    float r[32];
    float m = -1e30f;
    #pragma unroll
    for (int i = 0; i < 32; i++) {
        const int idx = tid + (i << 10);
        r[i] = (idx < VOCAB) ? row[idx] : -1e30f;
        m = fmaxf(m, r[i]);
    }
    #pragma unroll
    for (int o = 16; o; o >>= 1) m = fmaxf(m, __shfl_xor_sync(0xffffffffu, m, o));
    if ((tid & 31) == 0) sm[tid >> 5] = m;
    __syncthreads();
    if (tid == 0) {
        float v = sm[0];
        for (int i = 1; i < 32; i++) v = fmaxf(v, sm[i]);
        sm[0] = v;
    }
    __syncthreads();
    m = sm[0];

    float s = 0.f;
    #pragma unroll
    for (int i = 0; i < 32; i++) {
        const int idx = tid + (i << 10);
        if (idx < VOCAB) s += expf(r[i] - m);
    }
    #pragma unroll
    for (int o = 16; o; o >>= 1) s += __shfl_xor_sync(0xffffffffu, s, o);
    __syncthreads();
    if ((tid & 31) == 0) sm[tid >> 5] = s;
    __syncthreads();
    if (tid == 0) {
        float v = 0.f;
        for (int i = 0; i < 32; i++) v += sm[i];
        sm[0] = v;
    }
    __syncthreads();
    const float lse = m + logf(sm[0]);

    #pragma unroll
    for (int i = 0; i < 32; i++) {
        const int idx = tid + (i << 10);
        if (idx < VOCAB) row[idx] = r[i] - lse;
    }
}

// ---------------- PDL launch helper ----------------
template <typename F, typename... Args>
static inline void pdl(F f, dim3 grid, dim3 block, cudaStream_t st, Args... args) {
    cudaLaunchConfig_t cfg = {};
    cfg.gridDim = grid;
    cfg.blockDim = block;
    cfg.stream = st;
    cudaLaunchAttribute attr;
    attr.id = cudaLaunchAttributeProgrammaticStreamSerialization;
    attr.val.programmaticStreamSerializationAllowed = 1;
    cfg.attrs = &attr;
    cfg.numAttrs = 1;
    cudaLaunchKernelEx(&cfg, f, args...);
}

// ---------------- launch ----------------
extern "C" void kernel_launch(void* const* d_in, const int* in_sizes, int n_in,
                              void* d_out, int out_size)
{
    const float* enc       = (const float*)d_in[0];
    const float* ench      = (const float*)d_in[1];
    const int* tgt         = (const int*)d_in[2];
    const float* emb       = (const float*)d_in[3];
    const float* W1        = (const float*)d_in[4];
    const float* b1        = (const float*)d_in[5];
    const float* W2        = (const float*)d_in[6];
    const float* b2        = (const float*)d_in[7];
    const float* W3        = (const float*)d_in[8];
    const float* b3        = (const float*)d_in[9];
    const float* av        = (const float*)d_in[10];
    const float* Wih       = (const float*)d_in[11];
    const float* Whh       = (const float*)d_in[12];
    const float* bih       = (const float*)d_in[13];
    const float* bhh       = (const float*)d_in[14];
    const float* oW        = (const float*)d_in[15];
    const float* ob        = (const float*)d_in[16];
    float* out = (float*)d_out;

    float *epart, *hidb, *qgh, *gi, *bqh;
    unsigned char *A1f, *a2f, *W2f, *W3f, *Wof, *hf8;
    __nv_bfloat16 *Pb, *hbf, *xt, *encb, *Wp, *Wqh, *Wihb;
    cudaGetSymbolAddress((void**)&Pb,    g_Pb);
    cudaGetSymbolAddress((void**)&A1f,   g_A1f);
    cudaGetSymbolAddress((void**)&a2f,   g_a2f);
    cudaGetSymbolAddress((void**)&epart, g_epart);
    cudaGetSymbolAddress((void**)&hidb,  g_hid);
    cudaGetSymbolAddress((void**)&hbf,   g_hbf);
    cudaGetSymbolAddress((void**)&hf8,   g_hf8);
    cudaGetSymbolAddress((void**)&qgh,   g_qgh);
    cudaGetSymbolAddress((void**)&xt,    g_xt);
    cudaGetSymbolAddress((void**)&gi,    g_gi);
    cudaGetSymbolAddress((void**)&bqh,   g_bqh);
    cudaGetSymbolAddress((void**)&encb,  g_encb);
    cudaGetSymbolAddress((void**)&Wp,    g_Wp);
    cudaGetSymbolAddress((void**)&Wqh,   g_Wqh);
    cudaGetSymbolAddress((void**)&W2f,   g_W2f);
    cudaGetSymbolAddress((void**)&W3f,   g_W3f);
    cudaGetSymbolAddress((void**)&Wihb,  g_Wih);
    cudaGetSymbolAddress((void**)&Wof,   g_Wof);

    // second stream + events for logits/logsoftmax overlap (leaked by design:
    // no device allocation; destroying mid-capture is illegal)
    cudaStream_t s2;
    cudaStreamCreateWithFlags(&s2, cudaStreamNonBlocking);
    cudaEvent_t evGru[NSTEP], evLog[NSTEP];
    for (int t = 0; t < NSTEP; t++) {
        cudaEventCreateWithFlags(&evGru[t], cudaEventDisableTiming);
        cudaEventCreateWithFlags(&evLog[t], cudaEventDisableTiming);
    }

    init_misc_kernel<<<(BATCH * HDIM + 255) / 256, 256>>>(ench, b1, bhh);
    conv_all_kernel<<<(CB7 + 255) / 256, 256>>>(enc, W1, Whh, W2, W3, Wih, oW);

    // P = enc @ W1[:, :H]^T  (bf16 out, no bias)
    pdl(&gemm2<3, 1>, dim3(HDIM / 128, MROWS / 128), dim3(256), (cudaStream_t)0,
        (const __nv_bfloat16*)encb, (int)HDIM, (const __nv_bfloat16*)Wp, (int)HDIM,
        (const float*)nullptr, (void*)Pb, (size_t)HDIM, (size_t)0, (int)MROWS, (int)HDIM,
        (const float*)nullptr);

    for (int t = 0; t < NSTEP; t++) {
        float* hi = hidb + (t & 1) * (BATCH * HDIM);
        float* ho = hidb + ((t + 1) & 1) * (BATCH * HDIM);
        __nv_bfloat16* hbi = hbf + (t & 1) * (BATCH * HDIM);
        __nv_bfloat16* hbo = hbf + ((t + 1) & 1) * (BATCH * HDIM);
        unsigned char* hfo = hf8 + ((t + 1) & 1) * (BATCH * HDIM);

        // [q | gh] = hid @ [W1b ; Whh]^T + [b1 | bhh]   (split-K 4, bf16)
        pdl(&gemm2<0, KSPL>, dim3(2048 / 128, 1, KSPL), dim3(256), (cudaStream_t)0,
            (const __nv_bfloat16*)hbi, (int)HDIM, (const __nv_bfloat16*)Wqh, (int)HDIM,
            (const float*)bqh, (void*)qgh, (size_t)2048, (size_t)(BATCH * 2048),
            (int)BATCH, (int)HDIM, (const float*)nullptr);

        // A1 = tanh(P + q)  (e4m3)
        pdl(&a1prep_kernel, dim3(MROWS * HDIM / 4 / 256), dim3(256), (cudaStream_t)0,
            (const __nv_bfloat16*)Pb, (const float*)qgh);

        // a2 = tanh(A1 @ W2^T + b2)  (fp8 GEMM, e4m3 out)
        pdl(&gemm8<1>, dim3(HDIM / 128, MROWS / 128), dim3(256), (cudaStream_t)0,
            (const unsigned char*)A1f, (int)HDIM, (const unsigned char*)W2f, (int)HDIM,
            (const float*)b2, (void*)a2f, (size_t)HDIM,
            (int)MROWS, (int)HDIM, (const float*)nullptr);

        // e_part[8][MROWS] = slicewise [ tanh(a2 @ W3^T + b3) . v ]  (fp8 GEMM)
        pdl(&gemm8<2>, dim3(HDIM / 128, MROWS / 128), dim3(256), (cudaStream_t)0,
            (const unsigned char*)a2f, (int)HDIM, (const unsigned char*)W3f, (int)HDIM,
            (const float*)b3, (void*)epart, (size_t)0,
            (int)MROWS, (int)HDIM, (const float*)av);

        pdl(&softmax_ctx_kernel, dim3(BATCH), dim3(256), (cudaStream_t)0,
            (const float*)epart, (const __nv_bfloat16*)encb,
            (const int*)(tgt + t), (const float*)emb);

        // gi = xt @ Wih^T + bih   (split-K 4, bf16)
        pdl(&gemm2<0, KSPL>, dim3(1536 / 128, 1, KSPL), dim3(256), (cudaStream_t)0,
            (const __nv_bfloat16*)xt, (int)1024, (const __nv_bfloat16*)Wihb, (int)1024,
            (const float*)bih, (void*)gi, (size_t)1536, (size_t)(BATCH * 1536),
            (int)BATCH, (int)1024, (const float*)nullptr);

        // guard: logits(t-2) must be done before we overwrite its hidden buffer
        if (t >= 2) cudaStreamWaitEvent(0, evLog[t - 2], 0);

        pdl(&gru_kernel, dim3(BATCH), dim3(HDIM), (cudaStream_t)0,
            (const float*)gi, (const float*)qgh, (const float*)hi, (float*)ho,
            (__nv_bfloat16*)hbo, (unsigned char*)hfo);
        cudaEventRecord(evGru[t], 0);

        // overlapped branch: fp8 logits + log-softmax on s2
        cudaStreamWaitEvent(s2, evGru[t], 0);
        pdl(&gemm8<0>, dim3(VOCAB / 128, 1), dim3(256), s2,
            (const unsigned char*)hfo, (int)HDIM, (const unsigned char*)Wof, (int)HDIM,
            (const float*)ob, (void*)(out + (size_t)t * VOCAB),
            (size_t)((size_t)NSTEP * VOCAB),
            (int)BATCH, (int)HDIM, (const float*)nullptr);
        pdl(&logsoftmax_kernel, dim3(BATCH), dim3(1024), s2, (float*)out, (int)t);
        cudaEventRecord(evLog[t], s2);
    }

    // rejoin: main stream waits for the last overlapped branch
    cudaStreamWaitEvent(0, evLog[NSTEP - 1], 0);
}

// round 16
// speedup vs baseline: 2.1834x; 1.0925x over previous
#include <cuda_runtime.h>
#include <cuda_bf16.h>
#include <math.h>

#define VOCAB 32000
#define HDIM  512
#define BATCH 128
#define ENCL  64
#define NSTEP 31
#define MROWS (BATCH * ENCL)   // 8192
#define STAGES 4
#define W8SCALE 32.0f
#define W8INV   0.03125f
#define KSPL    4               // split-K for small-M GEMMs
#define A1_NST  3               // stages in fused a2 kernel

// ---------------- scratch (static device globals; no allocation) ----------------
__device__ __nv_bfloat16  g_Pb[MROWS * HDIM];       // enc @ W1a^T (bf16, time-invariant)
__device__ unsigned char  g_a2f[MROWS * HDIM];      // tanh(a1 @ W2^T + b2)  (e4m3)
__device__ float          g_epart[8 * MROWS];       // per-slice partial dots (a3 . v)
__device__ float          g_hid[2][BATCH * HDIM];   // fp32 recurrence (ping-pong)
__device__ __nv_bfloat16  g_hbf[2][BATCH * HDIM];   // bf16 hidden (ping-pong)
__device__ unsigned char  g_hf8[2][BATCH * HDIM];   // e4m3 hidden (ping-pong, logits)
__device__ float          g_qgh[KSPL * BATCH * 2048]; // split-K parts of [q | gh]
__device__ __nv_bfloat16  g_xt[BATCH * HDIM];       // ctx  bf16
__device__ float          g_gi[KSPL * BATCH * 1536];  // split-K parts of gi_ctx
__device__ float          g_bqh[2048];              // [b1 | bhh]
__device__ __nv_bfloat16  g_xe[NSTEP * BATCH * HDIM];   // gathered embeddings (bf16)
__device__ float          g_giemb[NSTEP * BATCH * 1536]; // emb-half of gi (+bih), all steps

// weight copies (converted once per replay)
__device__ __nv_bfloat16 g_encb[MROWS * HDIM];
__device__ __nv_bfloat16 g_Wp  [HDIM * HDIM];
__device__ __nv_bfloat16 g_Wqh [2048 * HDIM];
__device__ unsigned char g_W2f [HDIM * HDIM];       // e4m3, pre-scaled x32
__device__ unsigned char g_W3f [HDIM * HDIM];       // e4m3, pre-scaled x32
__device__ __nv_bfloat16 g_Wih [1536 * 1024];
__device__ unsigned char g_Wof [VOCAB * HDIM];      // e4m3, pre-scaled x32

// ---------------- helpers ----------------
__device__ __forceinline__ unsigned bf2(float lo, float hi) {
    unsigned u;
    asm("cvt.rn.bf16x2.f32 %0, %1, %2;" : "=r"(u) : "f"(hi), "f"(lo));
    return u;
}
__device__ __forceinline__ unsigned short f8x2(float lo, float hi) {
    unsigned short u;
    asm("cvt.rn.satfinite.e4m3x2.f32 %0, %1, %2;" : "=h"(u) : "f"(hi), "f"(lo));
    return u;
}
__device__ __forceinline__ float tanh_fast(float x) {
    float y;
    asm("tanh.approx.f32 %0, %1;" : "=f"(y) : "f"(x));
    return y;
}
__device__ __forceinline__ float blo(unsigned u) {
    return __bfloat162float(*(const __nv_bfloat16*)&u);
}
__device__ __forceinline__ float bhi(unsigned u) {
    return __bfloat162float(*((const __nv_bfloat16*)&u + 1));
}
__device__ __forceinline__ void mma_bf16(float c[4], const unsigned a[4], const unsigned b[2]) {
    asm volatile(
        "mma.sync.aligned.m16n8k16.row.col.f32.bf16.bf16.f32 "
        "{%0,%1,%2,%3}, {%4,%5,%6,%7}, {%8,%9}, {%0,%1,%2,%3};\n"
        : "+f"(c[0]), "+f"(c[1]), "+f"(c[2]), "+f"(c[3])
        : "r"(a[0]), "r"(a[1]), "r"(a[2]), "r"(a[3]), "r"(b[0]), "r"(b[1]));
}
__device__ __forceinline__ void mma_fp8(float c[4], const unsigned a[4], const unsigned b[2]) {
    asm volatile(
        "mma.sync.aligned.m16n8k32.row.col.f32.e4m3.e4m3.f32 "
        "{%0,%1,%2,%3}, {%4,%5,%6,%7}, {%8,%9}, {%0,%1,%2,%3};\n"
        : "+f"(c[0]), "+f"(c[1]), "+f"(c[2]), "+f"(c[3])
        : "r"(a[0]), "r"(a[1]), "r"(a[2]), "r"(a[3]), "r"(b[0]), "r"(b[1]));
}
__device__ __forceinline__ void ldsm4(unsigned& r0, unsigned& r1, unsigned& r2, unsigned& r3,
                                      unsigned addr) {
    asm volatile("ldmatrix.sync.aligned.m8n8.x4.shared.b16 {%0,%1,%2,%3}, [%4];"
                 : "=r"(r0), "=r"(r1), "=r"(r2), "=r"(r3) : "r"(addr));
}
__device__ __forceinline__ void cpasync16(unsigned dst, const void* src) {
    asm volatile("cp.async.cg.shared.global [%0], [%1], 16;\n" :: "r"(dst), "l"(src));
}
__device__ __forceinline__ void gdep_sync() {
#if __CUDA_ARCH__ >= 900
    cudaGridDependencySynchronize();
#endif
}

// ---------------- unified weight/operand conversion ----------------
#define N_ENC (MROWS * HDIM / 4)
#define N_SQ  (HDIM * HDIM / 4)
#define N_WQ2 (1536 * HDIM / 4)
#define N_WIH (1536 * 1024 / 4)
#define N_WO  (VOCAB * HDIM / 4)
#define CB0 (N_ENC)
#define CB1 (CB0 + N_SQ)
#define CB2 (CB1 + N_SQ)
#define CB3 (CB2 + N_WQ2)
#define CB4 (CB3 + N_SQ)
#define CB5 (CB4 + N_SQ)
#define CB6 (CB5 + N_WIH)
#define CB7 (CB6 + N_WO)

__device__ __forceinline__ void copy4(__nv_bfloat16* dst, const float* src) {
    float4 v = *(const float4*)src;
    uint2 o;
    o.x = bf2(v.x, v.y);
    o.y = bf2(v.z, v.w);
    *(uint2*)dst = o;
}
__device__ __forceinline__ void copy4_f8(unsigned char* dst, const float* src) {
    float4 v = *(const float4*)src;
    const unsigned lo = f8x2(v.x * W8SCALE, v.y * W8SCALE);
    const unsigned hi = f8x2(v.z * W8SCALE, v.w * W8SCALE);
    *(unsigned*)dst = lo | (hi << 16);
}

__global__ void conv_all_kernel(const float* __restrict__ enc,
                                const float* __restrict__ W1,
                                const float* __restrict__ Whh,
                                const float* __restrict__ W2,
                                const float* __restrict__ W3,
                                const float* __restrict__ Wih,
                                const float* __restrict__ Wo) {
    const int i = blockIdx.x * blockDim.x + threadIdx.x;
    if (i >= CB7) return;
    if (i < CB0) {
        copy4(g_encb + i * 4, enc + i * 4);
    } else if (i < CB1) {
        const int l = i - CB0, r = l >> 7, c = (l & 127) * 4;
        copy4(g_Wp + l * 4, W1 + (size_t)r * 1024 + c);
    } else if (i < CB2) {
        const int l = i - CB1, r = l >> 7, c = (l & 127) * 4;
        copy4(g_Wqh + l * 4, W1 + (size_t)r * 1024 + 512 + c);
    } else if (i < CB3) {
        const int l = i - CB2;
        copy4(g_Wqh + HDIM * HDIM + l * 4, Whh + l * 4);
    } else if (i < CB4) {
        const int l = i - CB3;
        copy4_f8(g_W2f + l * 4, W2 + l * 4);
    } else if (i < CB5) {
        const int l = i - CB4;
        copy4_f8(g_W3f + l * 4, W3 + l * 4);
    } else if (i < CB6) {
        const int l = i - CB5;
        copy4(g_Wih + l * 4, Wih + l * 4);
    } else {
        const int l = i - CB6;
        copy4_f8(g_Wof + l * 4, Wo + l * 4);
    }
}

__global__ void init_misc_kernel(const float* __restrict__ ench,
                                 const float* __restrict__ b1,
                                 const float* __restrict__ bhh) {
    const int i = blockIdx.x * blockDim.x + threadIdx.x;
    if (i < BATCH * HDIM) {
        const float h = ench[i];
        g_hid[0][i] = h;
        g_hbf[0][i] = __float2bfloat16(h);
        unsigned short u = f8x2(h, 0.f);
        g_hf8[0][i] = (unsigned char)(u & 0xFF);
    }
    if (i < 2048) g_bqh[i] = (i < HDIM) ? b1[i] : bhh[i - HDIM];
}

// ---------------- gather all step embeddings to bf16 (xe[t*128+b][:]) ----------------
__global__ __launch_bounds__(256) void gather_xe_kernel(const float* __restrict__ emb,
                                                        const int* __restrict__ tgt) {
    const int i4 = (blockIdx.x * blockDim.x + threadIdx.x) * 4;
    if (i4 >= NSTEP * BATCH * HDIM) return;
    const int row = i4 >> 9, col = i4 & 511;
    const int t = row >> 7, b = row & 127;
    int tk = tgt[b * 32 + t];
    tk = max(0, min(tk, VOCAB - 1));
    copy4(g_xe + i4, emb + (size_t)tk * HDIM + col);
}

// ---------------- bf16 GEMM (cp.async 4-stage, ldmatrix + mma, optional split-K) -------
// EPI 0: C fp32 = acc (+bias if z==0), written at C + z*partStride
// EPI 3: C bf16 = acc (raw, no bias)
template <int EPI, int SPLIT>
__global__ __launch_bounds__(256) void gemm2(
    const __nv_bfloat16* __restrict__ A, int lda,
    const __nv_bfloat16* __restrict__ W, int ldw,
    const float* __restrict__ bias,
    void* __restrict__ Cv, size_t ldc, size_t partStride,
    int M, int K,
    const float* __restrict__ v)
{
    __shared__ __align__(16) unsigned char sm[STAGES][2][128 * 48];

    const int tid    = threadIdx.x;
    const int warpid = tid >> 5, lane = tid & 31;
    const int wm = warpid >> 1, wn = warpid & 1;
    const int gid = lane >> 2, tidg = lane & 3;
    const int bm0 = blockIdx.y * 128, bn0 = blockIdx.x * 128;
    const int z   = (SPLIT > 1) ? blockIdx.z : 0;
    const int kbase = z * (K / SPLIT);
    const int frow = tid >> 1;
    const int half = tid & 1;

    const unsigned sbase = (unsigned)__cvta_generic_to_shared(&sm[0][0][0]);
    unsigned aoff[2], boff[4];
    #pragma unroll
    for (int mi = 0; mi < 2; mi++)
        aoff[mi] = (unsigned)((wm * 32 + mi * 16 + (lane & 15)) * 48 + (lane >> 4) * 16);
    #pragma unroll
    for (int p = 0; p < 4; p++)
        boff[p] = (unsigned)(6144 +
            (wn * 64 + p * 16 + ((lane >> 4) << 3) + (lane & 7)) * 48 + ((lane >> 3) & 1) * 16);

    float acc[2][8][4];
    #pragma unroll
    for (int mi = 0; mi < 2; mi++)
        #pragma unroll
        for (int ni = 0; ni < 8; ni++)
            #pragma unroll
            for (int qq = 0; qq < 4; qq++) acc[mi][ni][qq] = 0.f;

    const int nk = (K / SPLIT) >> 4;
    const unsigned dstA = frow * 48 + half * 16;

    auto issue = [&](int kt) {
        const unsigned st = (unsigned)(kt & (STAGES - 1)) * 12288;
        cpasync16(sbase + st + dstA,
                  A + (size_t)(bm0 + frow) * lda + kbase + (kt << 4) + half * 8);
        cpasync16(sbase + st + 6144 + dstA,
                  W + (size_t)(bn0 + frow) * ldw + kbase + (kt << 4) + half * 8);
        asm volatile("cp.async.commit_group;\n");
    };

    gdep_sync();

    #pragma unroll
    for (int s = 0; s < STAGES - 1; s++) issue(s);

    for (int kt = 0; kt < nk; kt++) {
        asm volatile("cp.async.wait_group %0;\n" :: "n"(STAGES - 2));
        __syncthreads();
        if (kt + STAGES - 1 < nk) issue(kt + STAGES - 1);
        else asm volatile("cp.async.commit_group;\n");

        const unsigned sb = sbase + (unsigned)(kt & (STAGES - 1)) * 12288;
        unsigned af[2][4], bfr[8][2];
        #pragma unroll
        for (int mi = 0; mi < 2; mi++)
            ldsm4(af[mi][0], af[mi][1], af[mi][2], af[mi][3], sb + aoff[mi]);
        #pragma unroll
        for (int p = 0; p < 4; p++) {
            unsigned r0, r1, r2, r3;
            ldsm4(r0, r1, r2, r3, sb + boff[p]);
            bfr[2 * p][0] = r0;     bfr[2 * p][1] = r1;
            bfr[2 * p + 1][0] = r2; bfr[2 * p + 1][1] = r3;
        }
        #pragma unroll
        for (int mi = 0; mi < 2; mi++)
            #pragma unroll
            for (int ni = 0; ni < 8; ni++)
                mma_bf16(acc[mi][ni], af[mi], bfr[ni]);
    }

    if (EPI == 3) {
        __nv_bfloat16* C = (__nv_bfloat16*)Cv;
        #pragma unroll
        for (int mi = 0; mi < 2; mi++) {
            #pragma unroll
            for (int ni = 0; ni < 8; ni++) {
                const int col = bn0 + wn * 64 + ni * 8 + tidg * 2;
                const int row0 = bm0 + wm * 32 + mi * 16 + gid;
                *(unsigned*)(C + (size_t)row0 * ldc + col) =
                    bf2(acc[mi][ni][0], acc[mi][ni][1]);
                *(unsigned*)(C + (size_t)(row0 + 8) * ldc + col) =
                    bf2(acc[mi][ni][2], acc[mi][ni][3]);
            }
        }
        return;
    }

    const bool addBias = (bias != nullptr) && (z == 0);
    #pragma unroll
    for (int mi = 0; mi < 2; mi++) {
        #pragma unroll
        for (int ni = 0; ni < 8; ni++) {
            const int col = bn0 + wn * 64 + ni * 8 + tidg * 2;
            const float b0v = addBias ? bias[col] : 0.f;
            const float b1v = addBias ? bias[col + 1] : 0.f;
            const int row0 = bm0 + wm * 32 + mi * 16 + gid;
            float* C = (float*)Cv + (size_t)z * partStride;
            C[(size_t)row0 * ldc + col]           = acc[mi][ni][0] + b0v;
            C[(size_t)row0 * ldc + col + 1]       = acc[mi][ni][1] + b1v;
            C[(size_t)(row0 + 8) * ldc + col]     = acc[mi][ni][2] + b0v;
            C[(size_t)(row0 + 8) * ldc + col + 1] = acc[mi][ni][3] + b1v;
        }
    }
}

// ---------------- fp8 GEMM (e4m3, k-tile 32; W pre-scaled x32, epilogue x1/32) ----------
// EPI 0: C fp32 = acc/32 + bias  (logits)
// EPI 2: e-dot: C[slice][row] = sum_col tanh(acc/32 + bias[col]) * v[col]
template <int EPI>
__global__ __launch_bounds__(256) void gemm8(
    const unsigned char* __restrict__ A, int lda,
    const unsigned char* __restrict__ W, int ldw,
    const float* __restrict__ bias,
    void* __restrict__ Cv, size_t ldc,
    int M, int K,
    const float* __restrict__ v)
{
    __shared__ __align__(16) unsigned char sm[STAGES][2][128 * 48];

    const int tid    = threadIdx.x;
    const int warpid = tid >> 5, lane = tid & 31;
    const int wm = warpid >> 1, wn = warpid & 1;
    const int gid = lane >> 2, tidg = lane & 3;
    const int bm0 = blockIdx.y * 128, bn0 = blockIdx.x * 128;
    const int frow = tid >> 1;
    const int half = tid & 1;

    const unsigned sbase = (unsigned)__cvta_generic_to_shared(&sm[0][0][0]);
    unsigned aoff[2], boff[4];
    #pragma unroll
    for (int mi = 0; mi < 2; mi++)
        aoff[mi] = (unsigned)((wm * 32 + mi * 16 + (lane & 15)) * 48 + (lane >> 4) * 16);
    #pragma unroll
    for (int p = 0; p < 4; p++)
        boff[p] = (unsigned)(6144 +
            (wn * 64 + p * 16 + ((lane >> 4) << 3) + (lane & 7)) * 48 + ((lane >> 3) & 1) * 16);

    float acc[2][8][4];
    #pragma unroll
    for (int mi = 0; mi < 2; mi++)
        #pragma unroll
        for (int ni = 0; ni < 8; ni++)
            #pragma unroll
            for (int qq = 0; qq < 4; qq++) acc[mi][ni][qq] = 0.f;

    const int nk = K >> 5;
    const unsigned dstA = frow * 48 + half * 16;

    auto issue = [&](int kt) {
        const unsigned st = (unsigned)(kt & (STAGES - 1)) * 12288;
        cpasync16(sbase + st + dstA,
                  A + (size_t)(bm0 + frow) * lda + (kt << 5) + half * 16);
        cpasync16(sbase + st + 6144 + dstA,
                  W + (size_t)(bn0 + frow) * ldw + (kt << 5) + half * 16);
        asm volatile("cp.async.commit_group;\n");
    };

    gdep_sync();

    #pragma unroll
    for (int s = 0; s < STAGES - 1; s++) issue(s);

    for (int kt = 0; kt < nk; kt++) {
        asm volatile("cp.async.wait_group %0;\n" :: "n"(STAGES - 2));
        __syncthreads();
        if (kt + STAGES - 1 < nk) issue(kt + STAGES - 1);
        else asm volatile("cp.async.commit_group;\n");

        const unsigned sb = sbase + (unsigned)(kt & (STAGES - 1)) * 12288;
        unsigned af[2][4], bfr[8][2];
        #pragma unroll
        for (int mi = 0; mi < 2; mi++)
            ldsm4(af[mi][0], af[mi][1], af[mi][2], af[mi][3], sb + aoff[mi]);
        #pragma unroll
        for (int p = 0; p < 4; p++) {
            unsigned r0, r1, r2, r3;
            ldsm4(r0, r1, r2, r3, sb + boff[p]);
            bfr[2 * p][0] = r0;     bfr[2 * p][1] = r1;
            bfr[2 * p + 1][0] = r2; bfr[2 * p + 1][1] = r3;
        }
        #pragma unroll
        for (int mi = 0; mi < 2; mi++)
            #pragma unroll
            for (int ni = 0; ni < 8; ni++)
                mma_fp8(acc[mi][ni], af[mi], bfr[ni]);
    }

    if (EPI == 2) {
        float* C = (float*)Cv;
        float es[2][2] = {{0.f, 0.f}, {0.f, 0.f}};
        #pragma unroll
        for (int mi = 0; mi < 2; mi++) {
            #pragma unroll
            for (int ni = 0; ni < 8; ni++) {
                const int col = bn0 + wn * 64 + ni * 8 + tidg * 2;
                const float v0 = v[col], v1 = v[col + 1];
                const float b0 = bias[col], b1 = bias[col + 1];
                es[mi][0] += tanh_fast(acc[mi][ni][0] * W8INV + b0) * v0
                           + tanh_fast(acc[mi][ni][1] * W8INV + b1) * v1;
                es[mi][1] += tanh_fast(acc[mi][ni][2] * W8INV + b0) * v0
                           + tanh_fast(acc[mi][ni][3] * W8INV + b1) * v1;
            }
        }
        const int slice = blockIdx.x * 2 + wn;
        #pragma unroll
        for (int mi = 0; mi < 2; mi++) {
            #pragma unroll
            for (int hh = 0; hh < 2; hh++) {
                float s = es[mi][hh];
                s += __shfl_xor_sync(0xffffffffu, s, 1);
                s += __shfl_xor_sync(0xffffffffu, s, 2);
                if (tidg == 0) {
                    const int row = bm0 + wm * 32 + mi * 16 + gid + hh * 8;
                    C[(size_t)slice * M + row] = s;
                }
            }
        }
        return;
    }

    // EPI 0: fp32 logits
    float* C = (float*)Cv;
    #pragma unroll
    for (int mi = 0; mi < 2; mi++) {
        #pragma unroll
        for (int ni = 0; ni < 8; ni++) {
            const int col = bn0 + wn * 64 + ni * 8 + tidg * 2;
            const float b0v = bias ? bias[col] : 0.f;
            const float b1v = bias ? bias[col + 1] : 0.f;
            const int row0 = bm0 + wm * 32 + mi * 16 + gid;
            C[(size_t)row0 * ldc + col]           = acc[mi][ni][0] * W8INV + b0v;
            C[(size_t)row0 * ldc + col + 1]       = acc[mi][ni][1] * W8INV + b1v;
            C[(size_t)(row0 + 8) * ldc + col]     = acc[mi][ni][2] * W8INV + b0v;
            C[(size_t)(row0 + 8) * ldc + col + 1] = acc[mi][ni][3] * W8INV + b1v;
        }
    }
}

// ---------------- fused a2 GEMM: a2 = tanh( tanh(P + Σq) @ W2^T + b2 )  (e4m3 out) ------
// A-operand built on the fly: cp.async P (bf16) tiles; per k-tile, threads convert
// tanh(P+q) -> fp8 into Aconv smem; ldsm/mma consume. Removes a1prep kernel + A1 buffer.
// smem: sQ 4KB | Pst 3x8KB | Wst 3x6KB | Aconv 6KB = 52KB (dynamic)
#define A1_SMEM (4096 + A1_NST * 8192 + A1_NST * 6144 + 6144)
__global__ __launch_bounds__(256) void gemm8a1(
    const __nv_bfloat16* __restrict__ Pb,
    const float* __restrict__ qgh,
    const unsigned char* __restrict__ W,
    const float* __restrict__ bias,
    unsigned char* __restrict__ C)
{
    extern __shared__ __align__(16) unsigned char dsm[];
    float* sQ = (float*)dsm;                                   // [2][512]
    const unsigned sb0   = (unsigned)__cvta_generic_to_shared(dsm);
    const unsigned Pbase = sb0 + 4096;
    const unsigned Wbase = Pbase + A1_NST * 8192;
    const unsigned Abase = Wbase + A1_NST * 6144;
    unsigned char* PstG  = dsm + 4096;

    const int tid  = threadIdx.x;
    const int warpid = tid >> 5, lane = tid & 31;
    const int wm = warpid >> 1, wn = warpid & 1;
    const int gid = lane >> 2, tidg = lane & 3;
    const int bn0 = blockIdx.x * 128, bm0 = blockIdx.y * 128;
    const int row = tid >> 1, pr = tid & 1;

    unsigned aoff[2], boff[4];
    #pragma unroll
    for (int mi = 0; mi < 2; mi++)
        aoff[mi] = Abase + (unsigned)((wm * 32 + mi * 16 + (lane & 15)) * 48 + (lane >> 4) * 16);
    #pragma unroll
    for (int p = 0; p < 4; p++)
        boff[p] = (unsigned)((wn * 64 + p * 16 + ((lane >> 4) << 3) + (lane & 7)) * 48 +
                             ((lane >> 3) & 1) * 16);

    float acc[2][8][4];
    #pragma unroll
    for (int mi = 0; mi < 2; mi++)
        #pragma unroll
        for (int ni = 0; ni < 8; ni++)
            #pragma unroll
            for (int qq = 0; qq < 4; qq++) acc[mi][ni][qq] = 0.f;

    const int nk = HDIM / 32;   // 16

    auto issue = [&](int kt) {
        const int st = kt % A1_NST;
        const unsigned pd = Pbase + (unsigned)st * 8192 + row * 64 + pr * 32;
        const __nv_bfloat16* ps = Pb + (size_t)(bm0 + row) * HDIM + kt * 32 + pr * 16;
        cpasync16(pd,      ps);
        cpasync16(pd + 16, ps + 8);
        const unsigned wd = Wbase + (unsigned)st * 6144 + row * 48 + pr * 16;
        cpasync16(wd, W + (size_t)(bn0 + row) * HDIM + kt * 32 + pr * 16);
        asm volatile("cp.async.commit_group;\n");
    };

    gdep_sync();   // qgh must be complete

    // q sums for the 2 batches covered by this row block
    for (int i = tid; i < 1024; i += 256) {
        const int bi = i >> 9, c = i & 511;
        const float* q = qgh + (size_t)((bm0 >> 6) + bi) * 2048 + c;
        float s = 0.f;
        #pragma unroll
        for (int p = 0; p < KSPL; p++) s += q[(size_t)p * (BATCH * 2048)];
        sQ[i] = s;
    }
    issue(0);
    issue(1);

    for (int kt = 0; kt < nk; kt++) {
        if (kt == nk - 1) asm volatile("cp.async.wait_group 0;\n" ::: "memory");
        else              asm volatile("cp.async.wait_group 1;\n" ::: "memory");
        __syncthreads();   // stage ready; sQ ready (kt=0); prior ldsm of Aconv complete

        // convert 16 P values -> fp8 A tile (row, pr*16 .. +16)
        {
            const int st = kt % A1_NST;
            const uint4 p0 = *(const uint4*)(PstG + st * 8192 + row * 64 + pr * 32);
            const uint4 p1 = *(const uint4*)(PstG + st * 8192 + row * 64 + pr * 32 + 16);
            const float* q = sQ + (row >> 6) * 512 + kt * 32 + pr * 16;
            uint4 o;
            o.x = (unsigned)f8x2(tanh_fast(blo(p0.x) + q[0]),  tanh_fast(bhi(p0.x) + q[1]))
                | ((unsigned)f8x2(tanh_fast(blo(p0.y) + q[2]),  tanh_fast(bhi(p0.y) + q[3])) << 16);
            o.y = (unsigned)f8x2(tanh_fast(blo(p0.z) + q[4]),  tanh_fast(bhi(p0.z) + q[5]))
                | ((unsigned)f8x2(tanh_fast(blo(p0.w) + q[6]),  tanh_fast(bhi(p0.w) + q[7])) << 16);
            o.z = (unsigned)f8x2(tanh_fast(blo(p1.x) + q[8]),  tanh_fast(bhi(p1.x) + q[9]))
                | ((unsigned)f8x2(tanh_fast(blo(p1.y) + q[10]), tanh_fast(bhi(p1.y) + q[11])) << 16);
            o.w = (unsigned)f8x2(tanh_fast(blo(p1.z) + q[12]), tanh_fast(bhi(p1.z) + q[13]))
                | ((unsigned)f8x2(tanh_fast(blo(p1.w) + q[14]), tanh_fast(bhi(p1.w) + q[15])) << 16);
            *(uint4*)(dsm + (Abase - sb0) + row * 48 + pr * 16) = o;
        }
        __syncthreads();   // Aconv ready

        if (kt + 2 < nk) issue(kt + 2);

        const unsigned wsb = Wbase + (unsigned)(kt % A1_NST) * 6144;
        unsigned af[2][4], bfr[8][2];
        #pragma unroll
        for (int mi = 0; mi < 2; mi++)
            ldsm4(af[mi][0], af[mi][1], af[mi][2], af[mi][3], aoff[mi]);
        #pragma unroll
        for (int p = 0; p < 4; p++) {
            unsigned r0, r1, r2, r3;
            ldsm4(r0, r1, r2, r3, wsb + boff[p]);
            bfr[2 * p][0] = r0;     bfr[2 * p][1] = r1;
            bfr[2 * p + 1][0] = r2; bfr[2 * p + 1][1] = r3;
        }
        #pragma unroll
        for (int mi = 0; mi < 2; mi++)
            #pragma unroll
            for (int ni = 0; ni < 8; ni++)
                mma_fp8(acc[mi][ni], af[mi], bfr[ni]);
    }

    // epilogue: e4m3 out = tanh(acc/32 + bias)
    #pragma unroll
    for (int mi = 0; mi < 2; mi++) {
        #pragma unroll
        for (int ni = 0; ni < 8; ni++) {
            const int col = bn0 + wn * 64 + ni * 8 + tidg * 2;
            const float b0v = bias[col];
            const float b1v = bias[col + 1];
            const int row0 = bm0 + wm * 32 + mi * 16 + gid;
            *(unsigned short*)(C + (size_t)row0 * HDIM + col) =
                f8x2(tanh_fast(acc[mi][ni][0] * W8INV + b0v),
                     tanh_fast(acc[mi][ni][1] * W8INV + b1v));
            *(unsigned short*)(C + (size_t)(row0 + 8) * HDIM + col) =
                f8x2(tanh_fast(acc[mi][ni][2] * W8INV + b0v),
                     tanh_fast(acc[mi][ni][3] * W8INV + b1v));
        }
    }
}

// ---------------- e from partials ; softmax ; ctx (bf16 enc) -> g_xt bf16 ----------------
__global__ __launch_bounds__(256) void softmax_ctx_kernel(
    const float* __restrict__ epart,
    const __nv_bfloat16* __restrict__ encb)
{
    __shared__ float e[ENCL];
    __shared__ float alpha[ENCL];
    const int b = blockIdx.x;
    const int tid = threadIdx.x;
    const int warp = tid >> 5, lane = tid & 31;

    gdep_sync();

    if (tid < ENCL) {
        float s = 0.f;
        #pragma unroll
        for (int sl = 0; sl < 8; sl++) s += epart[sl * MROWS + b * ENCL + tid];
        e[tid] = s;
    }
    __syncthreads();
    if (warp == 0) {
        const float e0 = e[lane], e1 = e[lane + 32];
        float m = fmaxf(e0, e1);
        #pragma unroll
        for (int o = 16; o; o >>= 1) m = fmaxf(m, __shfl_xor_sync(0xffffffffu, m, o));
        const float x0 = expf(e0 - m), x1 = expf(e1 - m);
        float s = x0 + x1;
        #pragma unroll
        for (int o = 16; o; o >>= 1) s += __shfl_xor_sync(0xffffffffu, s, o);
        const float inv = 1.f / s;
        alpha[lane]      = x0 * inv;
        alpha[lane + 32] = x1 * inv;
    }
    __syncthreads();
    for (int j = tid * 2; j < HDIM; j += 512) {
        float s0 = 0.f, s1 = 0.f;
        #pragma unroll
        for (int l = 0; l < ENCL; l++) {
            const unsigned pk = *(const unsigned*)(encb + ((size_t)b * ENCL + l) * HDIM + j);
            const float a = alpha[l];
            s0 += a * blo(pk);
            s1 += a * bhi(pk);
        }
        *(unsigned*)(g_xt + b * HDIM + j) = bf2(s0, s1);
    }
}

// ---------------- GRU gate combine; gi = giemb[t] + Σ gi_ctx parts ----------------
__global__ void gru_kernel(const float* __restrict__ gi, const float* __restrict__ giemb,
                           const float* __restrict__ qgh,
                           const float* __restrict__ h, float* __restrict__ hn,
                           __nv_bfloat16* __restrict__ hbf_out,
                           unsigned char* __restrict__ hf8_out)
{
    const int b = blockIdx.x, j = threadIdx.x;
    const int o  = b * 1536;
    const int og = b * 2048 + HDIM;
    const int GS = BATCH * 1536, QS = BATCH * 2048;
    gdep_sync();
    float gir = giemb[o + j];
    float giz = giemb[o + HDIM + j];
    float gin = giemb[o + 2 * HDIM + j];
    float ghr = 0.f, ghz = 0.f, ghn = 0.f;
    #pragma unroll
    for (int p = 0; p < KSPL; p++) {
        gir += gi[p * GS + o + j];
        giz += gi[p * GS + o + HDIM + j];
        gin += gi[p * GS + o + 2 * HDIM + j];
        ghr += qgh[p * QS + og + j];
        ghz += qgh[p * QS + og + HDIM + j];
        ghn += qgh[p * QS + og + 2 * HDIM + j];
    }
    const float r = 1.f / (1.f + expf(-(gir + ghr)));
    const float z = 1.f / (1.f + expf(-(giz + ghz)));
    const float n = tanhf(gin + r * ghn);
    const float hv = h[b * HDIM + j];
    const float out = (1.f - z) * n + z * hv;
    hn[b * HDIM + j] = out;
    hbf_out[b * HDIM + j] = __float2bfloat16(out);
    unsigned short u = f8x2(out, 0.f);
    hf8_out[b * HDIM + j] = (unsigned char)(u & 0xFF);
}

// ---------------- in-place log-softmax over one row of 32000 ----------------
__global__ __launch_bounds__(1024) void logsoftmax_kernel(float* __restrict__ out, int t) {
    const int b = blockIdx.x;
    float* row = out + ((size_t)b * NSTEP + t) * VOCAB;
    const int tid = threadIdx.x;
    __shared__ float sm[32];

    gdep_sync();

    float r[32];
    float m = -1e30f;
    #pragma unroll
    for (int i = 0; i < 32; i++) {
        const int idx = tid + (i << 10);
        r[i] = (idx < VOCAB) ? row[idx] : -1e30f;
        m = fmaxf(m, r[i]);
    }
    #pragma unroll
    for (int o = 16; o; o >>= 1) m = fmaxf(m, __shfl_xor_sync(0xffffffffu, m, o));
    if ((tid & 31) == 0) sm[tid >> 5] = m;
    __syncthreads();
    if (tid == 0) {
        float v = sm[0];
        for (int i = 1; i < 32; i++) v = fmaxf(v, sm[i]);
        sm[0] = v;
    }
    __syncthreads();
    m = sm[0];

    float s = 0.f;
    #pragma unroll
    for (int i = 0; i < 32; i++) {
        const int idx = tid + (i << 10);
        if (idx < VOCAB) s += expf(r[i] - m);
    }
    #pragma unroll
    for (int o = 16; o; o >>= 1) s += __shfl_xor_sync(0xffffffffu, s, o);
    __syncthreads();
    if ((tid & 31) == 0) sm[tid >> 5] = s;
    __syncthreads();
    if (tid == 0) {
        float v = 0.f;
        for (int i = 0; i < 32; i++) v += sm[i];
        sm[0] = v;
    }
    __syncthreads();
    const float lse = m + logf(sm[0]);

    #pragma unroll
    for (int i = 0; i < 32; i++) {
        const int idx = tid + (i << 10);
        if (idx < VOCAB) row[idx] = r[i] - lse;
    }
}

// ---------------- PDL launch helpers ----------------
template <typename F, typename... Args>
static inline void pdl(F f, dim3 grid, dim3 block, cudaStream_t st, Args... args) {
    cudaLaunchConfig_t cfg = {};
    cfg.gridDim = grid;
    cfg.blockDim = block;
    cfg.stream = st;
    cudaLaunchAttribute attr;
    attr.id = cudaLaunchAttributeProgrammaticStreamSerialization;
    attr.val.programmaticStreamSerializationAllowed = 1;
    cfg.attrs = &attr;
    cfg.numAttrs = 1;
    cudaLaunchKernelEx(&cfg, f, args...);
}
template <typename F, typename... Args>
static inline void pdls(F f, dim3 grid, dim3 block, size_t smem, cudaStream_t st, Args... args) {
    cudaLaunchConfig_t cfg = {};
    cfg.gridDim = grid;
    cfg.blockDim = block;
    cfg.stream = st;
    cfg.dynamicSmemBytes = smem;
    cudaLaunchAttribute attr;
    attr.id = cudaLaunchAttributeProgrammaticStreamSerialization;
    attr.val.programmaticStreamSerializationAllowed = 1;
    cfg.attrs = &attr;
    cfg.numAttrs = 1;
    cudaLaunchKernelEx(&cfg, f, args...);
}

// ---------------- launch ----------------
extern "C" void kernel_launch(void* const* d_in, const int* in_sizes, int n_in,
                              void* d_out, int out_size)
{
    const float* enc       = (const float*)d_in[0];
    const float* ench      = (const float*)d_in[1];
    const int* tgt         = (const int*)d_in[2];
    const float* emb       = (const float*)d_in[3];
    const float* W1        = (const float*)d_in[4];
    const float* b1        = (const float*)d_in[5];
    const float* W2        = (const float*)d_in[6];
    const float* b2        = (const float*)d_in[7];
    const float* W3        = (const float*)d_in[8];
    const float* b3        = (const float*)d_in[9];
    const float* av        = (const float*)d_in[10];
    const float* Wih       = (const float*)d_in[11];
    const float* Whh       = (const float*)d_in[12];
    const float* bih       = (const float*)d_in[13];
    const float* bhh       = (const float*)d_in[14];
    const float* oW        = (const float*)d_in[15];
    const float* ob        = (const float*)d_in[16];
    float* out = (float*)d_out;

    float *epart, *hidb, *qgh, *gi, *bqh, *giemb;
    unsigned char *a2f, *W2f, *W3f, *Wof, *hf8;
    __nv_bfloat16 *Pb, *hbf, *xt, *encb, *Wp, *Wqh, *Wihb, *xe;
    cudaGetSymbolAddress((void**)&Pb,    g_Pb);
    cudaGetSymbolAddress((void**)&a2f,   g_a2f);
    cudaGetSymbolAddress((void**)&epart, g_epart);
    cudaGetSymbolAddress((void**)&hidb,  g_hid);
    cudaGetSymbolAddress((void**)&hbf,   g_hbf);
    cudaGetSymbolAddress((void**)&hf8,   g_hf8);
    cudaGetSymbolAddress((void**)&qgh,   g_qgh);
    cudaGetSymbolAddress((void**)&xt,    g_xt);
    cudaGetSymbolAddress((void**)&gi,    g_gi);
    cudaGetSymbolAddress((void**)&bqh,   g_bqh);
    cudaGetSymbolAddress((void**)&giemb, g_giemb);
    cudaGetSymbolAddress((void**)&xe,    g_xe);
    cudaGetSymbolAddress((void**)&encb,  g_encb);
    cudaGetSymbolAddress((void**)&Wp,    g_Wp);
    cudaGetSymbolAddress((void**)&Wqh,   g_Wqh);
    cudaGetSymbolAddress((void**)&W2f,   g_W2f);
    cudaGetSymbolAddress((void**)&W3f,   g_W3f);
    cudaGetSymbolAddress((void**)&Wihb,  g_Wih);
    cudaGetSymbolAddress((void**)&Wof,   g_Wof);

    cudaFuncSetAttribute(gemm8a1, cudaFuncAttributeMaxDynamicSharedMemorySize, A1_SMEM);

    // second stream + events for logits/logsoftmax overlap (leaked by design:
    // no device allocation; destroying mid-capture is illegal)
    cudaStream_t s2;
    cudaStreamCreateWithFlags(&s2, cudaStreamNonBlocking);
    cudaEvent_t evGru[NSTEP], evLog[NSTEP];
    for (int t = 0; t < NSTEP; t++) {
        cudaEventCreateWithFlags(&evGru[t], cudaEventDisableTiming);
        cudaEventCreateWithFlags(&evLog[t], cudaEventDisableTiming);
    }

    init_misc_kernel<<<(BATCH * HDIM + 255) / 256, 256>>>(ench, b1, bhh);
    conv_all_kernel<<<(CB7 + 255) / 256, 256>>>(enc, W1, Whh, W2, W3, Wih, oW);
    gather_xe_kernel<<<(NSTEP * BATCH * HDIM / 4 + 255) / 256, 256>>>(emb, tgt);

    // P = enc @ W1[:, :H]^T  (bf16 out, no bias)
    pdl(&gemm2<3, 1>, dim3(HDIM / 128, MROWS / 128), dim3(256), (cudaStream_t)0,
        (const __nv_bfloat16*)encb, (int)HDIM, (const __nv_bfloat16*)Wp, (int)HDIM,
        (const float*)nullptr, (void*)Pb, (size_t)HDIM, (size_t)0, (int)MROWS, (int)HDIM,
        (const float*)nullptr);

    // giemb = xe @ Wih[:, :512]^T + bih   (all steps, one GEMM)
    pdl(&gemm2<0, 1>, dim3(1536 / 128, NSTEP * BATCH / 128), dim3(256), (cudaStream_t)0,
        (const __nv_bfloat16*)xe, (int)HDIM, (const __nv_bfloat16*)Wihb, (int)1024,
        (const float*)bih, (void*)giemb, (size_t)1536, (size_t)0,
        (int)(NSTEP * BATCH), (int)HDIM, (const float*)nullptr);

    for (int t = 0; t < NSTEP; t++) {
        float* hi = hidb + (t & 1) * (BATCH * HDIM);
        float* ho = hidb + ((t + 1) & 1) * (BATCH * HDIM);
        __nv_bfloat16* hbi = hbf + (t & 1) * (BATCH * HDIM);
        __nv_bfloat16* hbo = hbf + ((t + 1) & 1) * (BATCH * HDIM);
        unsigned char* hfo = hf8 + ((t + 1) & 1) * (BATCH * HDIM);

        // [q | gh] = hid @ [W1b ; Whh]^T + [b1 | bhh]   (split-K 4, bf16)
        pdl(&gemm2<0, KSPL>, dim3(2048 / 128, 1, KSPL), dim3(256), (cudaStream_t)0,
            (const __nv_bfloat16*)hbi, (int)HDIM, (const __nv_bfloat16*)Wqh, (int)HDIM,
            (const float*)bqh, (void*)qgh, (size_t)2048, (size_t)(BATCH * 2048),
            (int)BATCH, (int)HDIM, (const float*)nullptr);

        // a2 = tanh( tanh(P + q) @ W2^T + b2 )  (fused fp8 GEMM, e4m3 out)
        pdls(&gemm8a1, dim3(HDIM / 128, MROWS / 128), dim3(256), (size_t)A1_SMEM,
             (cudaStream_t)0,
             (const __nv_bfloat16*)Pb, (const float*)qgh,
             (const unsigned char*)W2f, (const float*)b2, (unsigned char*)a2f);

        // e_part[8][MROWS] = slicewise [ tanh(a2 @ W3^T + b3) . v ]  (fp8 GEMM)
        pdl(&gemm8<2>, dim3(HDIM / 128, MROWS / 128), dim3(256), (cudaStream_t)0,
            (const unsigned char*)a2f, (int)HDIM, (const unsigned char*)W3f, (int)HDIM,
            (const float*)b3, (void*)epart, (size_t)0,
            (int)MROWS, (int)HDIM, (const float*)av);

        pdl(&softmax_ctx_kernel, dim3(BATCH), dim3(256), (cudaStream_t)0,
            (const float*)epart, (const __nv_bfloat16*)encb);

        // gi_ctx = ctx @ Wih[:, 512:]^T   (split-K 4, bf16, no bias)
        pdl(&gemm2<0, KSPL>, dim3(1536 / 128, 1, KSPL), dim3(256), (cudaStream_t)0,
            (const __nv_bfloat16*)xt, (int)HDIM, (const __nv_bfloat16*)(Wihb + 512), (int)1024,
            (const float*)nullptr, (void*)gi, (size_t)1536, (size_t)(BATCH * 1536),
            (int)BATCH, (int)HDIM, (const float*)nullptr);

        // guard: logits(t-2) must be done before we overwrite its hidden buffer
        if (t >= 2) cudaStreamWaitEvent(0, evLog[t - 2], 0);

        pdl(&gru_kernel, dim3(BATCH), dim3(HDIM), (cudaStream_t)0,
            (const float*)gi, (const float*)(giemb + (size_t)t * BATCH * 1536),
            (const float*)qgh, (const float*)hi, (float*)ho,
            (__nv_bfloat16*)hbo, (unsigned char*)hfo);
        cudaEventRecord(evGru[t], 0);

        // overlapped branch: fp8 logits + log-softmax on s2
        cudaStreamWaitEvent(s2, evGru[t], 0);
        pdl(&gemm8<0>, dim3(VOCAB / 128, 1), dim3(256), s2,
            (const unsigned char*)hfo, (int)HDIM, (const unsigned char*)Wof, (int)HDIM,
            (const float*)ob, (void*)(out + (size_t)t * VOCAB),
            (size_t)((size_t)NSTEP * VOCAB),
            (int)BATCH, (int)HDIM, (const float*)nullptr);
        pdl(&logsoftmax_kernel, dim3(BATCH), dim3(1024), s2, (float*)out, (int)t);
        cudaEventRecord(evLog[t], s2);
    }

    // rejoin: main stream waits for the last overlapped branch
    cudaStreamWaitEvent(0, evLog[NSTEP - 1], 0);
}